// round 1
// baseline (speedup 1.0000x reference)
#include <cuda_runtime.h>
#include <math.h>
#include <stdint.h>

// Problem constants
#define BB 2
#define SS 2048
#define DD 1024
#define HH 16
#define KVH 4
#define HDIM 64
#define NREP (HH / KVH)   // 4

// Scratch (allocation-free: __device__ globals)
__device__ float g_qraw[BB * SS * HH * HDIM];    // (b,s,h,d)   16 MB
__device__ float g_kraw[BB * SS * KVH * HDIM];   // (b,s,kv,d)   4 MB
__device__ float g_vraw[BB * SS * KVH * HDIM];   //              4 MB
__device__ float g_qt[BB * HH * SS * HDIM];      // (b,h,s,d)   16 MB
__device__ float g_kt[BB * KVH * SS * HDIM];     //              4 MB
__device__ float g_vt[BB * KVH * SS * HDIM];     //              4 MB
__device__ float g_attn[BB * SS * HH * HDIM];    // (b,s,h*d)   16 MB

// ---------------------------------------------------------------------------
// Tiled fp32 GEMM: C[M,N] = A[M,K] @ B[K,N], all row-major.
// BM=BN=64, BK=16, 256 threads, 4x4 per thread. Dims assumed divisible.
// ---------------------------------------------------------------------------
#define GBM 64
#define GBN 64
#define GBK 16

__global__ __launch_bounds__(256)
void gemm_kernel(const float* __restrict__ A, const float* __restrict__ B,
                 float* __restrict__ C, int M, int N, int K)
{
    __shared__ float As[GBK][GBM];
    __shared__ float Bs[GBK][GBN];

    const int tid = threadIdx.x;
    const int bm = blockIdx.y * GBM;
    const int bn = blockIdx.x * GBN;
    const int tx = tid & 15;        // 0..15 (cols)
    const int ty = tid >> 4;        // 0..15 (rows)

    float acc[4][4];
#pragma unroll
    for (int i = 0; i < 4; i++)
#pragma unroll
        for (int j = 0; j < 4; j++) acc[i][j] = 0.f;

    for (int k0 = 0; k0 < K; k0 += GBK) {
        // Load A tile 64x16 -> As[c][r]
#pragma unroll
        for (int i = 0; i < 4; i++) {
            int e = tid + i * 256;
            int r = e / GBK;
            int c = e % GBK;
            As[c][r] = A[(size_t)(bm + r) * K + k0 + c];
        }
        // Load B tile 16x64 -> Bs[c][r]  (coalesced)
#pragma unroll
        for (int i = 0; i < 4; i++) {
            int e = tid + i * 256;
            int c = e / GBN;
            int r = e % GBN;
            Bs[c][r] = B[(size_t)(k0 + c) * N + bn + r];
        }
        __syncthreads();

#pragma unroll
        for (int k = 0; k < GBK; k++) {
            float a[4], b[4];
#pragma unroll
            for (int i = 0; i < 4; i++) a[i] = As[k][ty * 4 + i];
#pragma unroll
            for (int j = 0; j < 4; j++) b[j] = Bs[k][tx * 4 + j];
#pragma unroll
            for (int i = 0; i < 4; i++)
#pragma unroll
                for (int j = 0; j < 4; j++)
                    acc[i][j] = fmaf(a[i], b[j], acc[i][j]);
        }
        __syncthreads();
    }

#pragma unroll
    for (int i = 0; i < 4; i++) {
        int row = bm + ty * 4 + i;
#pragma unroll
        for (int j = 0; j < 4; j++) {
            int col = bn + tx * 4 + j;
            C[(size_t)row * N + col] = acc[i][j];
        }
    }
}

// ---------------------------------------------------------------------------
// RoPE + transpose kernels
// qraw: (b, s, h, d) -> qt: (b, h, s, d), rope applied
// ---------------------------------------------------------------------------
__global__ void rope_q_kernel(const float* __restrict__ qraw,
                              const float* __restrict__ cosT,
                              const float* __restrict__ sinT,
                              float* __restrict__ qt)
{
    int idx = blockIdx.x * blockDim.x + threadIdx.x;
    if (idx >= BB * SS * HH * HDIM) return;
    int d = idx & 63;
    int h = (idx >> 6) & (HH - 1);
    int s = (idx >> 10) & (SS - 1);
    int b = idx >> 21;
    float v = qraw[idx];
    float rot = (d < 32) ? -qraw[idx + 32] : qraw[idx - 32];
    float o = v * cosT[s * HDIM + d] + rot * sinT[s * HDIM + d];
    qt[(((size_t)(b * HH + h) * SS) + s) * HDIM + d] = o;
}

__global__ void rope_k_kernel(const float* __restrict__ kraw,
                              const float* __restrict__ cosT,
                              const float* __restrict__ sinT,
                              float* __restrict__ kt)
{
    int idx = blockIdx.x * blockDim.x + threadIdx.x;
    if (idx >= BB * SS * KVH * HDIM) return;
    int d = idx & 63;
    int h = (idx >> 6) & (KVH - 1);
    int s = (idx >> 8) & (SS - 1);
    int b = idx >> 19;
    float v = kraw[idx];
    float rot = (d < 32) ? -kraw[idx + 32] : kraw[idx - 32];
    float o = v * cosT[s * HDIM + d] + rot * sinT[s * HDIM + d];
    kt[(((size_t)(b * KVH + h) * SS) + s) * HDIM + d] = o;
}

__global__ void trans_v_kernel(const float* __restrict__ vraw,
                               float* __restrict__ vt)
{
    int idx = blockIdx.x * blockDim.x + threadIdx.x;
    if (idx >= BB * SS * KVH * HDIM) return;
    int d = idx & 63;
    int h = (idx >> 6) & (KVH - 1);
    int s = (idx >> 8) & (SS - 1);
    int b = idx >> 19;
    vt[(((size_t)(b * KVH + h) * SS) + s) * HDIM + d] = vraw[idx];
}

// ---------------------------------------------------------------------------
// Flash-style causal attention with GQA.
// Grid: (S/64, B*H). Block: 64 threads, one query row per thread.
// Q row + accumulator live in registers; K/V tiles in smem (broadcast reads).
// Output written to g_attn as (b, s, h*64+d).
// ---------------------------------------------------------------------------
__global__ __launch_bounds__(64)
void flash_kernel(const float* __restrict__ Qt, const float* __restrict__ Kt,
                  const float* __restrict__ Vt, float* __restrict__ attn)
{
    __shared__ float Ks[64][64];
    __shared__ float Vs[64][64];

    const int t = threadIdx.x;
    const int bh = blockIdx.y;
    const int b = bh / HH;
    const int h = bh % HH;
    const int kvh = h / NREP;
    const int row = blockIdx.x * 64 + t;

    const float* qp = Qt + ((size_t)(b * HH + h) * SS + row) * HDIM;
    float qreg[64];
#pragma unroll
    for (int d = 0; d < 64; d += 4) {
        float4 v4 = *(const float4*)(qp + d);
        qreg[d + 0] = v4.x; qreg[d + 1] = v4.y;
        qreg[d + 2] = v4.z; qreg[d + 3] = v4.w;
    }

    float acc[64];
#pragma unroll
    for (int d = 0; d < 64; d++) acc[d] = 0.f;
    float m = -INFINITY;
    float l = 0.f;

    const float* kbase = Kt + (size_t)(b * KVH + kvh) * SS * HDIM;
    const float* vbase = Vt + (size_t)(b * KVH + kvh) * SS * HDIM;

    const int ntiles = blockIdx.x + 1;
    for (int jt = 0; jt < ntiles; jt++) {
        __syncthreads();
        // cooperative coalesced load of K,V tiles (64 keys x 64 dims)
#pragma unroll 8
        for (int i = 0; i < 64; i++) {
            size_t off = (size_t)(jt * 64 + i) * HDIM + t;
            Ks[i][t] = kbase[off];
            Vs[i][t] = vbase[off];
        }
        __syncthreads();

        const int kmax = (jt == blockIdx.x) ? (t + 1) : 64;
        for (int kk = 0; kk < kmax; kk++) {
            float s = 0.f;
#pragma unroll
            for (int d = 0; d < 64; d++) s = fmaf(qreg[d], Ks[kk][d], s);
            s *= 0.125f;   // 1/sqrt(64)

            if (s > m) {
                float scale = __expf(m - s);
                m = s;
                l *= scale;
#pragma unroll
                for (int d = 0; d < 64; d++) acc[d] *= scale;
            }
            float p = __expf(s - m);
            l += p;
#pragma unroll
            for (int d = 0; d < 64; d++) acc[d] = fmaf(p, Vs[kk][d], acc[d]);
        }
    }

    const float inv_l = 1.f / l;
    float* op = attn + ((size_t)b * SS + row) * (HH * HDIM) + h * HDIM;
#pragma unroll
    for (int d = 0; d < 64; d++) op[d] = acc[d] * inv_l;
}

// ---------------------------------------------------------------------------
// Launch
// ---------------------------------------------------------------------------
extern "C" void kernel_launch(void* const* d_in, const int* in_sizes, int n_in,
                              void* d_out, int out_size)
{
    (void)in_sizes; (void)n_in; (void)out_size;
    const float* x    = (const float*)d_in[0];   // (B,S,D)
    const float* cosT = (const float*)d_in[1];   // (S,HD)
    const float* sinT = (const float*)d_in[2];   // (S,HD)
    const float* Wq   = (const float*)d_in[3];   // (D, H*HD)
    const float* Wk   = (const float*)d_in[4];   // (D, KV*HD)
    const float* Wv   = (const float*)d_in[5];   // (D, KV*HD)
    const float* Wo   = (const float*)d_in[6];   // (H*HD, D)
    float* out = (float*)d_out;                  // (B,S,D)

    float *qraw, *kraw, *vraw, *qt, *kt, *vt, *attn;
    cudaGetSymbolAddress((void**)&qraw, g_qraw);
    cudaGetSymbolAddress((void**)&kraw, g_kraw);
    cudaGetSymbolAddress((void**)&vraw, g_vraw);
    cudaGetSymbolAddress((void**)&qt,   g_qt);
    cudaGetSymbolAddress((void**)&kt,   g_kt);
    cudaGetSymbolAddress((void**)&vt,   g_vt);
    cudaGetSymbolAddress((void**)&attn, g_attn);

    const int M = BB * SS;           // 4096
    const int NQ = HH * HDIM;        // 1024
    const int NKV = KVH * HDIM;      // 256

    // 1) Projections
    gemm_kernel<<<dim3(NQ / GBN,  M / GBM), 256>>>(x, Wq, qraw, M, NQ,  DD);
    gemm_kernel<<<dim3(NKV / GBN, M / GBM), 256>>>(x, Wk, kraw, M, NKV, DD);
    gemm_kernel<<<dim3(NKV / GBN, M / GBM), 256>>>(x, Wv, vraw, M, NKV, DD);

    // 2) RoPE + transpose
    {
        int nq = BB * SS * HH * HDIM;
        rope_q_kernel<<<(nq + 255) / 256, 256>>>(qraw, cosT, sinT, qt);
        int nk = BB * SS * KVH * HDIM;
        rope_k_kernel<<<(nk + 255) / 256, 256>>>(kraw, cosT, sinT, kt);
        trans_v_kernel<<<(nk + 255) / 256, 256>>>(vraw, vt);
    }

    // 3) Causal GQA attention
    flash_kernel<<<dim3(SS / 64, BB * HH), 64>>>(qt, kt, vt, attn);

    // 4) Output projection
    gemm_kernel<<<dim3(DD / GBN, M / GBM), 256>>>(attn, Wo, out, M, DD, DD);
}

// round 2
// speedup vs baseline: 1.5838x; 1.5838x over previous
#include <cuda_runtime.h>
#include <math.h>
#include <stdint.h>

// Problem constants
#define BB 2
#define SS 2048
#define DD 1024
#define HH 16
#define KVH 4
#define HDIM 64
#define NREP (HH / KVH)   // 4

// Scratch (allocation-free: __device__ globals)
__device__ float g_qraw[BB * SS * HH * HDIM];    // (b,s,h,d)   16 MB
__device__ float g_kraw[BB * SS * KVH * HDIM];   // (b,s,kv,d)   4 MB
__device__ float g_vraw[BB * SS * KVH * HDIM];   //              4 MB
__device__ float g_qt[BB * HH * SS * HDIM];      // (b,h,s,d)   16 MB
__device__ float g_kt[BB * KVH * SS * HDIM];     //              4 MB
__device__ float g_vt[BB * KVH * SS * HDIM];     //              4 MB
__device__ float g_attn[BB * SS * HH * HDIM];    // (b,s,h*d)   16 MB

// ---------------------------------------------------------------------------
// TF32 tensor-core GEMM: C[M,N] = A[M,K] @ B[K,N], all row-major fp32.
// BM=128, BN=128, BK=32, 256 threads (8 warps, 2x4), warp tile 64x32,
// mma.sync.aligned.m16n8k8.tf32. M,N,K assumed multiples of 128/128/32.
// ---------------------------------------------------------------------------
#define TBM 128
#define TBN 128
#define TBK 32
#define AS_STRIDE 36     // [m][k] padded: bank = 4q + r (conflict-free)
#define BS_STRIDE 136    // [k][n] padded: bank = 8q + r (conflict-free)

__device__ __forceinline__ uint32_t f2tf32(float f) {
    uint32_t u;
    asm("cvt.rna.tf32.f32 %0, %1;" : "=r"(u) : "f"(f));
    return u;
}

__device__ __forceinline__ void mma_tf32(float d[4], const uint32_t a[4],
                                         const uint32_t b[2], const float c[4]) {
    asm volatile(
        "mma.sync.aligned.m16n8k8.row.col.f32.tf32.tf32.f32 "
        "{%0,%1,%2,%3}, {%4,%5,%6,%7}, {%8,%9}, {%10,%11,%12,%13};"
        : "=f"(d[0]), "=f"(d[1]), "=f"(d[2]), "=f"(d[3])
        : "r"(a[0]), "r"(a[1]), "r"(a[2]), "r"(a[3]),
          "r"(b[0]), "r"(b[1]),
          "f"(c[0]), "f"(c[1]), "f"(c[2]), "f"(c[3]));
}

__global__ __launch_bounds__(256)
void gemm_tf32_kernel(const float* __restrict__ A, const float* __restrict__ B,
                      float* __restrict__ C, int M, int N, int K)
{
    __shared__ uint32_t As[TBM * AS_STRIDE];   // [m][k], tf32 bits
    __shared__ uint32_t Bs[TBK * BS_STRIDE];   // [k][n], tf32 bits

    const int tid = threadIdx.x;
    const int lane = tid & 31;
    const int warp = tid >> 5;
    const int q = lane >> 2;       // 0..7
    const int r = lane & 3;        // 0..3

    const int bm = blockIdx.y * TBM;
    const int bn = blockIdx.x * TBN;
    const int warpM = (warp & 1) * 64;   // 0 or 64
    const int warpN = (warp >> 1) * 32;  // 0,32,64,96

    float acc[4][4][4];
#pragma unroll
    for (int mi = 0; mi < 4; mi++)
#pragma unroll
        for (int ni = 0; ni < 4; ni++)
#pragma unroll
            for (int e = 0; e < 4; e++) acc[mi][ni][e] = 0.f;

    // Global-load index precompute
    const int a_row = tid >> 3;          // 0..31 (+32*i)
    const int a_col4 = (tid & 7) * 4;    // 0..28
    const int b_row = tid >> 5;          // 0..7 (+8*i)
    const int b_col4 = (tid & 31) * 4;   // 0..124

    for (int k0 = 0; k0 < K; k0 += TBK) {
        // A tile: 128 x 32, row-major global -> As[m][k] (tf32)
#pragma unroll
        for (int i = 0; i < 4; i++) {
            int row = a_row + i * 32;
            float4 v = *(const float4*)(A + (size_t)(bm + row) * K + k0 + a_col4);
            uint32_t* dst = &As[row * AS_STRIDE + a_col4];
            dst[0] = f2tf32(v.x); dst[1] = f2tf32(v.y);
            dst[2] = f2tf32(v.z); dst[3] = f2tf32(v.w);
        }
        // B tile: 32 x 128, row-major global -> Bs[k][n] (tf32)
#pragma unroll
        for (int i = 0; i < 4; i++) {
            int row = b_row + i * 8;
            float4 v = *(const float4*)(B + (size_t)(k0 + row) * N + bn + b_col4);
            uint32_t* dst = &Bs[row * BS_STRIDE + b_col4];
            dst[0] = f2tf32(v.x); dst[1] = f2tf32(v.y);
            dst[2] = f2tf32(v.z); dst[3] = f2tf32(v.w);
        }
        __syncthreads();

#pragma unroll
        for (int ki = 0; ki < 4; ki++) {
            uint32_t afr[4][4];
            uint32_t bfr[4][2];
#pragma unroll
            for (int mi = 0; mi < 4; mi++) {
                const uint32_t* ap = &As[(warpM + mi * 16 + q) * AS_STRIDE + ki * 8 + r];
                afr[mi][0] = ap[0];
                afr[mi][1] = ap[8 * AS_STRIDE];
                afr[mi][2] = ap[4];
                afr[mi][3] = ap[8 * AS_STRIDE + 4];
            }
#pragma unroll
            for (int ni = 0; ni < 4; ni++) {
                const uint32_t* bp = &Bs[(ki * 8 + r) * BS_STRIDE + warpN + ni * 8 + q];
                bfr[ni][0] = bp[0];
                bfr[ni][1] = bp[4 * BS_STRIDE];
            }
#pragma unroll
            for (int mi = 0; mi < 4; mi++)
#pragma unroll
                for (int ni = 0; ni < 4; ni++)
                    mma_tf32(acc[mi][ni], afr[mi], bfr[ni], acc[mi][ni]);
        }
        __syncthreads();
    }

    // Epilogue: c0,c1 at (row0, col..col+1), c2,c3 at (row0+8, col..col+1)
#pragma unroll
    for (int mi = 0; mi < 4; mi++) {
        int row0 = bm + warpM + mi * 16 + q;
#pragma unroll
        for (int ni = 0; ni < 4; ni++) {
            int col = bn + warpN + ni * 8 + 2 * r;
            float2 v01 = make_float2(acc[mi][ni][0], acc[mi][ni][1]);
            float2 v23 = make_float2(acc[mi][ni][2], acc[mi][ni][3]);
            *(float2*)(C + (size_t)row0 * N + col) = v01;
            *(float2*)(C + (size_t)(row0 + 8) * N + col) = v23;
        }
    }
}

// ---------------------------------------------------------------------------
// RoPE + transpose kernels
// ---------------------------------------------------------------------------
__global__ void rope_q_kernel(const float* __restrict__ qraw,
                              const float* __restrict__ cosT,
                              const float* __restrict__ sinT,
                              float* __restrict__ qt)
{
    int idx = blockIdx.x * blockDim.x + threadIdx.x;
    if (idx >= BB * SS * HH * HDIM) return;
    int d = idx & 63;
    int h = (idx >> 6) & (HH - 1);
    int s = (idx >> 10) & (SS - 1);
    int b = idx >> 21;
    float v = qraw[idx];
    float rot = (d < 32) ? -qraw[idx + 32] : qraw[idx - 32];
    float o = v * cosT[s * HDIM + d] + rot * sinT[s * HDIM + d];
    qt[(((size_t)(b * HH + h) * SS) + s) * HDIM + d] = o;
}

__global__ void rope_k_kernel(const float* __restrict__ kraw,
                              const float* __restrict__ cosT,
                              const float* __restrict__ sinT,
                              float* __restrict__ kt)
{
    int idx = blockIdx.x * blockDim.x + threadIdx.x;
    if (idx >= BB * SS * KVH * HDIM) return;
    int d = idx & 63;
    int h = (idx >> 6) & (KVH - 1);
    int s = (idx >> 8) & (SS - 1);
    int b = idx >> 19;
    float v = kraw[idx];
    float rot = (d < 32) ? -kraw[idx + 32] : kraw[idx - 32];
    float o = v * cosT[s * HDIM + d] + rot * sinT[s * HDIM + d];
    kt[(((size_t)(b * KVH + h) * SS) + s) * HDIM + d] = o;
}

__global__ void trans_v_kernel(const float* __restrict__ vraw,
                               float* __restrict__ vt)
{
    int idx = blockIdx.x * blockDim.x + threadIdx.x;
    if (idx >= BB * SS * KVH * HDIM) return;
    int d = idx & 63;
    int h = (idx >> 6) & (KVH - 1);
    int s = (idx >> 8) & (SS - 1);
    int b = idx >> 19;
    vt[(((size_t)(b * KVH + h) * SS) + s) * HDIM + d] = vraw[idx];
}

// ---------------------------------------------------------------------------
// Flash-style causal attention with GQA (SIMT).
// Grid: (S/64, B*H). Block: 64 threads, one query row per thread.
// ---------------------------------------------------------------------------
__global__ __launch_bounds__(64)
void flash_kernel(const float* __restrict__ Qt, const float* __restrict__ Kt,
                  const float* __restrict__ Vt, float* __restrict__ attn)
{
    __shared__ float Ks[64][64];
    __shared__ float Vs[64][64];

    const int t = threadIdx.x;
    const int bh = blockIdx.y;
    const int b = bh / HH;
    const int h = bh % HH;
    const int kvh = h / NREP;
    const int row = blockIdx.x * 64 + t;

    const float* qp = Qt + ((size_t)(b * HH + h) * SS + row) * HDIM;
    float qreg[64];
#pragma unroll
    for (int d = 0; d < 64; d += 4) {
        float4 v4 = *(const float4*)(qp + d);
        qreg[d + 0] = v4.x; qreg[d + 1] = v4.y;
        qreg[d + 2] = v4.z; qreg[d + 3] = v4.w;
    }

    float acc[64];
#pragma unroll
    for (int d = 0; d < 64; d++) acc[d] = 0.f;
    float m = -INFINITY;
    float l = 0.f;

    const float* kbase = Kt + (size_t)(b * KVH + kvh) * SS * HDIM;
    const float* vbase = Vt + (size_t)(b * KVH + kvh) * SS * HDIM;

    const int ntiles = blockIdx.x + 1;
    for (int jt = 0; jt < ntiles; jt++) {
        __syncthreads();
#pragma unroll 8
        for (int i = 0; i < 64; i++) {
            size_t off = (size_t)(jt * 64 + i) * HDIM + t;
            Ks[i][t] = kbase[off];
            Vs[i][t] = vbase[off];
        }
        __syncthreads();

        const int kmax = (jt == blockIdx.x) ? (t + 1) : 64;
        for (int kk = 0; kk < kmax; kk++) {
            // 4-way partial sums to shorten the dependent FMA chain
            float s0 = 0.f, s1 = 0.f, s2 = 0.f, s3 = 0.f;
#pragma unroll
            for (int d = 0; d < 64; d += 4) {
                s0 = fmaf(qreg[d + 0], Ks[kk][d + 0], s0);
                s1 = fmaf(qreg[d + 1], Ks[kk][d + 1], s1);
                s2 = fmaf(qreg[d + 2], Ks[kk][d + 2], s2);
                s3 = fmaf(qreg[d + 3], Ks[kk][d + 3], s3);
            }
            float s = ((s0 + s1) + (s2 + s3)) * 0.125f;   // 1/sqrt(64)

            if (s > m) {
                float scale = __expf(m - s);
                m = s;
                l *= scale;
#pragma unroll
                for (int d = 0; d < 64; d++) acc[d] *= scale;
            }
            float p = __expf(s - m);
            l += p;
#pragma unroll
            for (int d = 0; d < 64; d++) acc[d] = fmaf(p, Vs[kk][d], acc[d]);
        }
    }

    const float inv_l = 1.f / l;
    float* op = attn + ((size_t)b * SS + row) * (HH * HDIM) + h * HDIM;
#pragma unroll
    for (int d = 0; d < 64; d++) op[d] = acc[d] * inv_l;
}

// ---------------------------------------------------------------------------
// Launch
// ---------------------------------------------------------------------------
extern "C" void kernel_launch(void* const* d_in, const int* in_sizes, int n_in,
                              void* d_out, int out_size)
{
    (void)in_sizes; (void)n_in; (void)out_size;
    const float* x    = (const float*)d_in[0];   // (B,S,D)
    const float* cosT = (const float*)d_in[1];   // (S,HD)
    const float* sinT = (const float*)d_in[2];   // (S,HD)
    const float* Wq   = (const float*)d_in[3];   // (D, H*HD)
    const float* Wk   = (const float*)d_in[4];   // (D, KV*HD)
    const float* Wv   = (const float*)d_in[5];   // (D, KV*HD)
    const float* Wo   = (const float*)d_in[6];   // (H*HD, D)
    float* out = (float*)d_out;                  // (B,S,D)

    float *qraw, *kraw, *vraw, *qt, *kt, *vt, *attn;
    cudaGetSymbolAddress((void**)&qraw, g_qraw);
    cudaGetSymbolAddress((void**)&kraw, g_kraw);
    cudaGetSymbolAddress((void**)&vraw, g_vraw);
    cudaGetSymbolAddress((void**)&qt,   g_qt);
    cudaGetSymbolAddress((void**)&kt,   g_kt);
    cudaGetSymbolAddress((void**)&vt,   g_vt);
    cudaGetSymbolAddress((void**)&attn, g_attn);

    const int M = BB * SS;           // 4096
    const int NQ = HH * HDIM;        // 1024
    const int NKV = KVH * HDIM;      // 256

    // 1) Projections (TF32 tensor cores)
    gemm_tf32_kernel<<<dim3(NQ / TBN,  M / TBM), 256>>>(x, Wq, qraw, M, NQ,  DD);
    gemm_tf32_kernel<<<dim3(NKV / TBN, M / TBM), 256>>>(x, Wk, kraw, M, NKV, DD);
    gemm_tf32_kernel<<<dim3(NKV / TBN, M / TBM), 256>>>(x, Wv, vraw, M, NKV, DD);

    // 2) RoPE + transpose
    {
        int nq = BB * SS * HH * HDIM;
        rope_q_kernel<<<(nq + 255) / 256, 256>>>(qraw, cosT, sinT, qt);
        int nk = BB * SS * KVH * HDIM;
        rope_k_kernel<<<(nk + 255) / 256, 256>>>(kraw, cosT, sinT, kt);
        trans_v_kernel<<<(nk + 255) / 256, 256>>>(vraw, vt);
    }

    // 3) Causal GQA attention
    flash_kernel<<<dim3(SS / 64, BB * HH), 64>>>(qt, kt, vt, attn);

    // 4) Output projection (TF32 tensor cores)
    gemm_tf32_kernel<<<dim3(DD / TBN, M / TBM), 256>>>(attn, Wo, out, M, DD, DD);
}

// round 4
// speedup vs baseline: 4.1651x; 2.6298x over previous
#include <cuda_runtime.h>
#include <math.h>
#include <stdint.h>

// Problem constants
#define BB 2
#define SS 2048
#define DD 1024
#define HH 16
#define KVH 4
#define HDIM 64
#define NREP (HH / KVH)   // 4

// Scratch (allocation-free: __device__ globals)
__device__ float g_qraw[BB * SS * HH * HDIM];
__device__ float g_kraw[BB * SS * KVH * HDIM];
__device__ float g_vraw[BB * SS * KVH * HDIM];
__device__ float g_qt[BB * HH * SS * HDIM];
__device__ float g_kt[BB * KVH * SS * HDIM];
__device__ float g_vt[BB * KVH * SS * HDIM];
__device__ float g_attn[BB * SS * HH * HDIM];

__device__ __forceinline__ uint32_t f2tf32(float f) {
    uint32_t u;
    asm("cvt.rna.tf32.f32 %0, %1;" : "=r"(u) : "f"(f));
    return u;
}

__device__ __forceinline__ float ex2(float x) {
    float y;
    asm("ex2.approx.ftz.f32 %0, %1;" : "=f"(y) : "f"(x));
    return y;
}

__device__ __forceinline__ void mma_tf32(float d[4], const uint32_t a[4],
                                         const uint32_t b[2], const float c[4]) {
    asm volatile(
        "mma.sync.aligned.m16n8k8.row.col.f32.tf32.tf32.f32 "
        "{%0,%1,%2,%3}, {%4,%5,%6,%7}, {%8,%9}, {%10,%11,%12,%13};"
        : "=f"(d[0]), "=f"(d[1]), "=f"(d[2]), "=f"(d[3])
        : "r"(a[0]), "r"(a[1]), "r"(a[2]), "r"(a[3]),
          "r"(b[0]), "r"(b[1]),
          "f"(c[0]), "f"(c[1]), "f"(c[2]), "f"(c[3]));
}

// ---------------------------------------------------------------------------
// TF32 tensor-core GEMM (unchanged from R2)
// ---------------------------------------------------------------------------
#define TBM 128
#define TBN 128
#define TBK 32
#define AS_STRIDE 36
#define BS_STRIDE 136

__global__ __launch_bounds__(256)
void gemm_tf32_kernel(const float* __restrict__ A, const float* __restrict__ B,
                      float* __restrict__ C, int M, int N, int K)
{
    __shared__ uint32_t As[TBM * AS_STRIDE];
    __shared__ uint32_t Bs[TBK * BS_STRIDE];

    const int tid = threadIdx.x;
    const int lane = tid & 31;
    const int warp = tid >> 5;
    const int q = lane >> 2;
    const int r = lane & 3;

    const int bm = blockIdx.y * TBM;
    const int bn = blockIdx.x * TBN;
    const int warpM = (warp & 1) * 64;
    const int warpN = (warp >> 1) * 32;

    float acc[4][4][4];
#pragma unroll
    for (int mi = 0; mi < 4; mi++)
#pragma unroll
        for (int ni = 0; ni < 4; ni++)
#pragma unroll
            for (int e = 0; e < 4; e++) acc[mi][ni][e] = 0.f;

    const int a_row = tid >> 3;
    const int a_col4 = (tid & 7) * 4;
    const int b_row = tid >> 5;
    const int b_col4 = (tid & 31) * 4;

    for (int k0 = 0; k0 < K; k0 += TBK) {
#pragma unroll
        for (int i = 0; i < 4; i++) {
            int row = a_row + i * 32;
            float4 v = *(const float4*)(A + (size_t)(bm + row) * K + k0 + a_col4);
            uint32_t* dst = &As[row * AS_STRIDE + a_col4];
            dst[0] = f2tf32(v.x); dst[1] = f2tf32(v.y);
            dst[2] = f2tf32(v.z); dst[3] = f2tf32(v.w);
        }
#pragma unroll
        for (int i = 0; i < 4; i++) {
            int row = b_row + i * 8;
            float4 v = *(const float4*)(B + (size_t)(k0 + row) * N + bn + b_col4);
            uint32_t* dst = &Bs[row * BS_STRIDE + b_col4];
            dst[0] = f2tf32(v.x); dst[1] = f2tf32(v.y);
            dst[2] = f2tf32(v.z); dst[3] = f2tf32(v.w);
        }
        __syncthreads();

#pragma unroll
        for (int ki = 0; ki < 4; ki++) {
            uint32_t afr[4][4];
            uint32_t bfr[4][2];
#pragma unroll
            for (int mi = 0; mi < 4; mi++) {
                const uint32_t* ap = &As[(warpM + mi * 16 + q) * AS_STRIDE + ki * 8 + r];
                afr[mi][0] = ap[0];
                afr[mi][1] = ap[8 * AS_STRIDE];
                afr[mi][2] = ap[4];
                afr[mi][3] = ap[8 * AS_STRIDE + 4];
            }
#pragma unroll
            for (int ni = 0; ni < 4; ni++) {
                const uint32_t* bp = &Bs[(ki * 8 + r) * BS_STRIDE + warpN + ni * 8 + q];
                bfr[ni][0] = bp[0];
                bfr[ni][1] = bp[4 * BS_STRIDE];
            }
#pragma unroll
            for (int mi = 0; mi < 4; mi++)
#pragma unroll
                for (int ni = 0; ni < 4; ni++)
                    mma_tf32(acc[mi][ni], afr[mi], bfr[ni], acc[mi][ni]);
        }
        __syncthreads();
    }

#pragma unroll
    for (int mi = 0; mi < 4; mi++) {
        int row0 = bm + warpM + mi * 16 + q;
#pragma unroll
        for (int ni = 0; ni < 4; ni++) {
            int col = bn + warpN + ni * 8 + 2 * r;
            float2 v01 = make_float2(acc[mi][ni][0], acc[mi][ni][1]);
            float2 v23 = make_float2(acc[mi][ni][2], acc[mi][ni][3]);
            *(float2*)(C + (size_t)row0 * N + col) = v01;
            *(float2*)(C + (size_t)(row0 + 8) * N + col) = v23;
        }
    }
}

// ---------------------------------------------------------------------------
// RoPE + transpose kernels (unchanged)
// ---------------------------------------------------------------------------
__global__ void rope_q_kernel(const float* __restrict__ qraw,
                              const float* __restrict__ cosT,
                              const float* __restrict__ sinT,
                              float* __restrict__ qt)
{
    int idx = blockIdx.x * blockDim.x + threadIdx.x;
    if (idx >= BB * SS * HH * HDIM) return;
    int d = idx & 63;
    int h = (idx >> 6) & (HH - 1);
    int s = (idx >> 10) & (SS - 1);
    int b = idx >> 21;
    float v = qraw[idx];
    float rot = (d < 32) ? -qraw[idx + 32] : qraw[idx - 32];
    float o = v * cosT[s * HDIM + d] + rot * sinT[s * HDIM + d];
    qt[(((size_t)(b * HH + h) * SS) + s) * HDIM + d] = o;
}

__global__ void rope_k_kernel(const float* __restrict__ kraw,
                              const float* __restrict__ cosT,
                              const float* __restrict__ sinT,
                              float* __restrict__ kt)
{
    int idx = blockIdx.x * blockDim.x + threadIdx.x;
    if (idx >= BB * SS * KVH * HDIM) return;
    int d = idx & 63;
    int h = (idx >> 6) & (KVH - 1);
    int s = (idx >> 8) & (SS - 1);
    int b = idx >> 19;
    float v = kraw[idx];
    float rot = (d < 32) ? -kraw[idx + 32] : kraw[idx - 32];
    float o = v * cosT[s * HDIM + d] + rot * sinT[s * HDIM + d];
    kt[(((size_t)(b * KVH + h) * SS) + s) * HDIM + d] = o;
}

__global__ void trans_v_kernel(const float* __restrict__ vraw,
                               float* __restrict__ vt)
{
    int idx = blockIdx.x * blockDim.x + threadIdx.x;
    if (idx >= BB * SS * KVH * HDIM) return;
    int d = idx & 63;
    int h = (idx >> 6) & (KVH - 1);
    int s = (idx >> 8) & (SS - 1);
    int b = idx >> 19;
    vt[(((size_t)(b * KVH + h) * SS) + s) * HDIM + d] = vraw[idx];
}

// ---------------------------------------------------------------------------
// TF32 MMA flash attention, causal, GQA.
// CTA: 128 threads (4 warps), 64 queries; key tiles of 64. HD = 64.
// smem: Ks[64][68] (K, [key][dim]), Vs[64][72] ([key][dim]), Ps[64][68]
// (Q staging, then P per-warp). All tf32 bits, padded strides chosen so every
// fragment access pattern is bank-conflict-free (4q+r / 8r+q patterns).
// Softmax in exp2 domain: Q pre-scaled by 0.125*log2(e).
// ---------------------------------------------------------------------------
#define KS_STRIDE 68
#define VS_STRIDE 72
#define PS_STRIDE 68
#define FLASH_SMEM ((64 * KS_STRIDE + 64 * VS_STRIDE + 64 * PS_STRIDE) * 4)
#define FSC 0.18033688011112042f   // 0.125 * log2(e)

__global__ __launch_bounds__(128)
void flash_mma_kernel(const float* __restrict__ Qt, const float* __restrict__ Kt,
                      const float* __restrict__ Vt, float* __restrict__ attn)
{
    extern __shared__ uint32_t sm[];
    uint32_t* Ks = sm;
    uint32_t* Vs = sm + 64 * KS_STRIDE;
    uint32_t* Ps = sm + 64 * KS_STRIDE + 64 * VS_STRIDE;

    const int tid = threadIdx.x;
    const int lane = tid & 31;
    const int w = tid >> 5;
    const int q = lane >> 2;
    const int r = lane & 3;

    const int bx = gridDim.x - 1 - blockIdx.x;  // long CTAs first
    const int bh = blockIdx.y;
    const int b = bh >> 4;
    const int h = bh & 15;
    const int kvh = h >> 2;

    const float* qbase = Qt + ((size_t)bh * SS + bx * 64) * HDIM;
    const float* kbase = Kt + (size_t)(b * KVH + kvh) * SS * HDIM;
    const float* vbase = Vt + (size_t)(b * KVH + kvh) * SS * HDIM;

    // Stage Q tile (scaled, tf32) into Ps
#pragma unroll
    for (int it = 0; it < 8; it++) {
        int e = tid + it * 128;          // float4 index, 0..1023
        int row = e >> 4;
        int c4 = (e & 15) << 2;
        float4 v = *(const float4*)(qbase + row * HDIM + c4);
        uint4 u;
        u.x = f2tf32(v.x * FSC); u.y = f2tf32(v.y * FSC);
        u.z = f2tf32(v.z * FSC); u.w = f2tf32(v.w * FSC);
        *(uint4*)(Ps + row * PS_STRIDE + c4) = u;
    }
    __syncthreads();

    // Q fragments (each warp its own 16 rows)
    uint32_t qf[8][4];
#pragma unroll
    for (int ki = 0; ki < 8; ki++) {
        const uint32_t* p = Ps + (w * 16 + q) * PS_STRIDE + ki * 8 + r;
        qf[ki][0] = p[0];
        qf[ki][1] = p[8 * PS_STRIDE];
        qf[ki][2] = p[4];
        qf[ki][3] = p[8 * PS_STRIDE + 4];
    }
    __syncthreads();   // all warps done reading Q staging before P overwrites

    float of[8][4];
#pragma unroll
    for (int nt = 0; nt < 8; nt++)
#pragma unroll
        for (int e = 0; e < 4; e++) of[nt][e] = 0.f;
    float m0 = -INFINITY, m1 = -INFINITY, l0 = 0.f, l1 = 0.f;

    for (int jt = 0; jt <= bx; jt++) {
        __syncthreads();   // prior tile's smem reads complete
        // Load K,V tile (64 keys x 64 dims), convert to tf32
#pragma unroll
        for (int it = 0; it < 8; it++) {
            int e = tid + it * 128;
            int row = e >> 4;
            int c4 = (e & 15) << 2;
            size_t goff = (size_t)(jt * 64 + row) * HDIM + c4;
            float4 kv = *(const float4*)(kbase + goff);
            uint4 ku;
            ku.x = f2tf32(kv.x); ku.y = f2tf32(kv.y);
            ku.z = f2tf32(kv.z); ku.w = f2tf32(kv.w);
            *(uint4*)(Ks + row * KS_STRIDE + c4) = ku;
            float4 vv = *(const float4*)(vbase + goff);
            uint4 vu;
            vu.x = f2tf32(vv.x); vu.y = f2tf32(vv.y);
            vu.z = f2tf32(vv.z); vu.w = f2tf32(vv.w);
            *(uint4*)(Vs + row * VS_STRIDE + c4) = vu;
        }
        __syncthreads();

        // S = Q @ K^T  (scores in exp2 domain)
        float sf[8][4];
#pragma unroll
        for (int nt = 0; nt < 8; nt++)
#pragma unroll
            for (int e = 0; e < 4; e++) sf[nt][e] = 0.f;
#pragma unroll
        for (int ki = 0; ki < 8; ki++) {
#pragma unroll
            for (int nt = 0; nt < 8; nt++) {
                uint32_t bfr[2];
                const uint32_t* kp = Ks + (nt * 8 + q) * KS_STRIDE + ki * 8 + r;
                bfr[0] = kp[0];
                bfr[1] = kp[4];
                mma_tf32(sf[nt], qf[ki], bfr, sf[nt]);
            }
        }

        // Causal mask on diagonal tile
        if (jt == bx) {
            const int rowA = w * 16 + q;
            const int rowB = rowA + 8;
#pragma unroll
            for (int nt = 0; nt < 8; nt++) {
                int col = nt * 8 + 2 * r;
                if (col     > rowA) sf[nt][0] = -1e30f;
                if (col + 1 > rowA) sf[nt][1] = -1e30f;
                if (col     > rowB) sf[nt][2] = -1e30f;
                if (col + 1 > rowB) sf[nt][3] = -1e30f;
            }
        }

        // Online softmax (rows q and q+8)
        float mxA = -1e30f, mxB = -1e30f;
#pragma unroll
        for (int nt = 0; nt < 8; nt++) {
            mxA = fmaxf(mxA, fmaxf(sf[nt][0], sf[nt][1]));
            mxB = fmaxf(mxB, fmaxf(sf[nt][2], sf[nt][3]));
        }
        mxA = fmaxf(mxA, __shfl_xor_sync(0xffffffffu, mxA, 1));
        mxA = fmaxf(mxA, __shfl_xor_sync(0xffffffffu, mxA, 2));
        mxB = fmaxf(mxB, __shfl_xor_sync(0xffffffffu, mxB, 1));
        mxB = fmaxf(mxB, __shfl_xor_sync(0xffffffffu, mxB, 2));

        float mn0 = fmaxf(m0, mxA);
        float mn1 = fmaxf(m1, mxB);
        float sc0 = ex2(m0 - mn0);
        float sc1 = ex2(m1 - mn1);
        m0 = mn0; m1 = mn1;

        float rs0 = 0.f, rs1 = 0.f;
        uint32_t* prow = Ps + (w * 16 + q) * PS_STRIDE;
#pragma unroll
        for (int nt = 0; nt < 8; nt++) {
            float p00 = ex2(sf[nt][0] - m0);
            float p01 = ex2(sf[nt][1] - m0);
            float p10 = ex2(sf[nt][2] - m1);
            float p11 = ex2(sf[nt][3] - m1);
            rs0 += p00 + p01;
            rs1 += p10 + p11;
            uint32_t* pp = prow + nt * 8 + 2 * r;
            pp[0] = f2tf32(p00);
            pp[1] = f2tf32(p01);
            pp[8 * PS_STRIDE]     = f2tf32(p10);
            pp[8 * PS_STRIDE + 1] = f2tf32(p11);
        }
        rs0 += __shfl_xor_sync(0xffffffffu, rs0, 1);
        rs0 += __shfl_xor_sync(0xffffffffu, rs0, 2);
        rs1 += __shfl_xor_sync(0xffffffffu, rs1, 1);
        rs1 += __shfl_xor_sync(0xffffffffu, rs1, 2);
        l0 = l0 * sc0 + rs0;
        l1 = l1 * sc1 + rs1;
#pragma unroll
        for (int nt = 0; nt < 8; nt++) {
            of[nt][0] *= sc0; of[nt][1] *= sc0;
            of[nt][2] *= sc1; of[nt][3] *= sc1;
        }
        __syncwarp();

        // O += P @ V
#pragma unroll
        for (int kk = 0; kk < 8; kk++) {
            uint32_t af[4];
            const uint32_t* ap = prow + kk * 8 + r;
            af[0] = ap[0];
            af[1] = ap[8 * PS_STRIDE];
            af[2] = ap[4];
            af[3] = ap[8 * PS_STRIDE + 4];
#pragma unroll
            for (int nt = 0; nt < 8; nt++) {
                uint32_t bfr[2];
                const uint32_t* vp = Vs + (kk * 8 + r) * VS_STRIDE + nt * 8 + q;
                bfr[0] = vp[0];
                bfr[1] = vp[4 * VS_STRIDE];
                mma_tf32(of[nt], af, bfr, of[nt]);
            }
        }
    }

    // Normalize + store to (b, s, h*64+d)
    const float il0 = 1.f / l0;
    const float il1 = 1.f / l1;
    float* ob = attn + ((size_t)b * SS + bx * 64 + w * 16) * (HH * HDIM) + h * HDIM;
#pragma unroll
    for (int nt = 0; nt < 8; nt++) {
        int col = nt * 8 + 2 * r;
        float2 vA = make_float2(of[nt][0] * il0, of[nt][1] * il0);
        float2 vB = make_float2(of[nt][2] * il1, of[nt][3] * il1);
        *(float2*)(ob + (size_t)q * (HH * HDIM) + col) = vA;
        *(float2*)(ob + (size_t)(q + 8) * (HH * HDIM) + col) = vB;
    }
}

// ---------------------------------------------------------------------------
// Launch
// ---------------------------------------------------------------------------
extern "C" void kernel_launch(void* const* d_in, const int* in_sizes, int n_in,
                              void* d_out, int out_size)
{
    (void)in_sizes; (void)n_in; (void)out_size;
    const float* x    = (const float*)d_in[0];
    const float* cosT = (const float*)d_in[1];
    const float* sinT = (const float*)d_in[2];
    const float* Wq   = (const float*)d_in[3];
    const float* Wk   = (const float*)d_in[4];
    const float* Wv   = (const float*)d_in[5];
    const float* Wo   = (const float*)d_in[6];
    float* out = (float*)d_out;

    static bool attr_set = false;
    if (!attr_set) {
        cudaFuncSetAttribute(flash_mma_kernel,
                             cudaFuncAttributeMaxDynamicSharedMemorySize,
                             FLASH_SMEM);
        attr_set = true;
    }

    float *qraw, *kraw, *vraw, *qt, *kt, *vt, *attn;
    cudaGetSymbolAddress((void**)&qraw, g_qraw);
    cudaGetSymbolAddress((void**)&kraw, g_kraw);
    cudaGetSymbolAddress((void**)&vraw, g_vraw);
    cudaGetSymbolAddress((void**)&qt,   g_qt);
    cudaGetSymbolAddress((void**)&kt,   g_kt);
    cudaGetSymbolAddress((void**)&vt,   g_vt);
    cudaGetSymbolAddress((void**)&attn, g_attn);

    const int M = BB * SS;
    const int NQ = HH * HDIM;
    const int NKV = KVH * HDIM;

    gemm_tf32_kernel<<<dim3(NQ / TBN,  M / TBM), 256>>>(x, Wq, qraw, M, NQ,  DD);
    gemm_tf32_kernel<<<dim3(NKV / TBN, M / TBM), 256>>>(x, Wk, kraw, M, NKV, DD);
    gemm_tf32_kernel<<<dim3(NKV / TBN, M / TBM), 256>>>(x, Wv, vraw, M, NKV, DD);

    {
        int nq = BB * SS * HH * HDIM;
        rope_q_kernel<<<(nq + 255) / 256, 256>>>(qraw, cosT, sinT, qt);
        int nk = BB * SS * KVH * HDIM;
        rope_k_kernel<<<(nk + 255) / 256, 256>>>(kraw, cosT, sinT, kt);
        trans_v_kernel<<<(nk + 255) / 256, 256>>>(vraw, vt);
    }

    flash_mma_kernel<<<dim3(SS / 64, BB * HH), 128, FLASH_SMEM>>>(qt, kt, vt, attn);

    gemm_tf32_kernel<<<dim3(DD / TBN, M / TBM), 256>>>(attn, Wo, out, M, DD, DD);
}

// round 5
// speedup vs baseline: 4.8941x; 1.1750x over previous
#include <cuda_runtime.h>
#include <math.h>
#include <stdint.h>

// Problem constants
#define BB 2
#define SS 2048
#define DD 1024
#define HH 16
#define KVH 4
#define HDIM 64
#define NREP (HH / KVH)   // 4

// Scratch (allocation-free: __device__ globals)
__device__ float g_qraw[BB * SS * HH * HDIM];
__device__ float g_kraw[BB * SS * KVH * HDIM];
__device__ float g_vraw[BB * SS * KVH * HDIM];
__device__ float g_qt[BB * HH * SS * HDIM];
__device__ float g_kt[BB * KVH * SS * HDIM];
__device__ float g_vt[BB * KVH * SS * HDIM];
__device__ float g_attn[BB * SS * HH * HDIM];

__device__ __forceinline__ uint32_t f2tf32(float f) {
    uint32_t u;
    asm("cvt.rna.tf32.f32 %0, %1;" : "=r"(u) : "f"(f));
    return u;
}

__device__ __forceinline__ float ex2(float x) {
    float y;
    asm("ex2.approx.ftz.f32 %0, %1;" : "=f"(y) : "f"(x));
    return y;
}

__device__ __forceinline__ void mma_tf32(float d[4], const uint32_t a[4],
                                         const uint32_t b[2], const float c[4]) {
    asm volatile(
        "mma.sync.aligned.m16n8k8.row.col.f32.tf32.tf32.f32 "
        "{%0,%1,%2,%3}, {%4,%5,%6,%7}, {%8,%9}, {%10,%11,%12,%13};"
        : "=f"(d[0]), "=f"(d[1]), "=f"(d[2]), "=f"(d[3])
        : "r"(a[0]), "r"(a[1]), "r"(a[2]), "r"(a[3]),
          "r"(b[0]), "r"(b[1]),
          "f"(c[0]), "f"(c[1]), "f"(c[2]), "f"(c[3]));
}

__device__ __forceinline__ void cpa8(uint32_t dst, const void* src) {
    asm volatile("cp.async.ca.shared.global [%0], [%1], 8;"
                 :: "r"(dst), "l"(src));
}
__device__ __forceinline__ void cp_commit() {
    asm volatile("cp.async.commit_group;" ::: "memory");
}
template <int N>
__device__ __forceinline__ void cp_wait() {
    asm volatile("cp.async.wait_group %0;" :: "n"(N) : "memory");
}

// ---------------------------------------------------------------------------
// Pipelined TF32 tensor-core GEMM core. C[M,N] = A[M,K] @ B[K,N] row-major.
// BM=128, BN=128, BK=32, 256 threads (8 warps 2x4), warp tile 64x32.
// 2-stage cp.async double buffer; fp32 in smem, tf32 cvt at fragment load.
// Padded strides: As bank = 4q+r, Bs bank = 8r+... (proven conflict-free R2).
// ---------------------------------------------------------------------------
#define TBM 128
#define TBN 128
#define TBK 32
#define AS_STRIDE 36
#define BS_STRIDE 136
#define ASZ (TBM * AS_STRIDE)          // words
#define BSZ (TBK * BS_STRIDE)          // words
#define GSMEM ((ASZ + BSZ) * 2 * 4)    // bytes (2 stages)

struct GemmSmem {
    float* sA[2];
    float* sB[2];
};

__device__ __forceinline__ void gemm_copy_tile(
    const float* __restrict__ A, const float* __restrict__ B,
    int K, int N, int bm, int bn, int k0,
    float* sA, float* sB, int tid)
{
    uint32_t abase = (uint32_t)__cvta_generic_to_shared(sA);
    uint32_t bbase = (uint32_t)__cvta_generic_to_shared(sB);
#pragma unroll
    for (int i = 0; i < 8; i++) {
        int e = tid + i * 256;
        int row = e >> 4;
        int c2 = (e & 15) * 2;
        cpa8(abase + (row * AS_STRIDE + c2) * 4,
             A + (size_t)(bm + row) * K + k0 + c2);
    }
#pragma unroll
    for (int i = 0; i < 8; i++) {
        int e = tid + i * 256;
        int row = e >> 6;
        int c2 = (e & 63) * 2;
        cpa8(bbase + (row * BS_STRIDE + c2) * 4,
             B + (size_t)(k0 + row) * N + bn + c2);
    }
}

__device__ __forceinline__ void gemm_compute_tile(
    const float* __restrict__ sA, const float* __restrict__ sB,
    float acc[4][4][4], int warpM, int warpN, int q, int r)
{
#pragma unroll
    for (int ki = 0; ki < 4; ki++) {
        uint32_t afr[4][4];
        uint32_t bfr[4][2];
#pragma unroll
        for (int mi = 0; mi < 4; mi++) {
            const float* ap = &sA[(warpM + mi * 16 + q) * AS_STRIDE + ki * 8 + r];
            afr[mi][0] = f2tf32(ap[0]);
            afr[mi][1] = f2tf32(ap[8 * AS_STRIDE]);
            afr[mi][2] = f2tf32(ap[4]);
            afr[mi][3] = f2tf32(ap[8 * AS_STRIDE + 4]);
        }
#pragma unroll
        for (int ni = 0; ni < 4; ni++) {
            const float* bp = &sB[(ki * 8 + r) * BS_STRIDE + warpN + ni * 8 + q];
            bfr[ni][0] = f2tf32(bp[0]);
            bfr[ni][1] = f2tf32(bp[4 * BS_STRIDE]);
        }
#pragma unroll
        for (int mi = 0; mi < 4; mi++)
#pragma unroll
            for (int ni = 0; ni < 4; ni++)
                mma_tf32(acc[mi][ni], afr[mi], bfr[ni], acc[mi][ni]);
    }
}

__device__ __forceinline__ void gemm_body(
    const float* __restrict__ A, const float* __restrict__ B,
    float* __restrict__ C, int N, int K, int bm, int bn)
{
    extern __shared__ float gsm[];
    float* sA0 = gsm;
    float* sB0 = gsm + ASZ;
    float* sA1 = gsm + ASZ + BSZ;
    float* sB1 = gsm + 2 * ASZ + BSZ;

    const int tid = threadIdx.x;
    const int lane = tid & 31;
    const int warp = tid >> 5;
    const int q = lane >> 2;
    const int r = lane & 3;
    const int warpM = (warp & 1) * 64;
    const int warpN = (warp >> 1) * 32;

    float acc[4][4][4];
#pragma unroll
    for (int mi = 0; mi < 4; mi++)
#pragma unroll
        for (int ni = 0; ni < 4; ni++)
#pragma unroll
            for (int e = 0; e < 4; e++) acc[mi][ni][e] = 0.f;

    const int T = K / TBK;

    gemm_copy_tile(A, B, K, N, bm, bn, 0, sA0, sB0, tid);
    cp_commit();

    for (int t = 0; t < T - 1; t++) {
        float* la = (t & 1) ? sA1 : sA0;
        float* lb = (t & 1) ? sB1 : sB0;
        float* na = (t & 1) ? sA0 : sA1;
        float* nb = (t & 1) ? sB0 : sB1;
        gemm_copy_tile(A, B, K, N, bm, bn, (t + 1) * TBK, na, nb, tid);
        cp_commit();
        cp_wait<1>();
        __syncthreads();
        gemm_compute_tile(la, lb, acc, warpM, warpN, q, r);
        __syncthreads();
    }
    cp_wait<0>();
    __syncthreads();
    {
        float* la = ((T - 1) & 1) ? sA1 : sA0;
        float* lb = ((T - 1) & 1) ? sB1 : sB0;
        gemm_compute_tile(la, lb, acc, warpM, warpN, q, r);
    }

#pragma unroll
    for (int mi = 0; mi < 4; mi++) {
        int row0 = bm + warpM + mi * 16 + q;
#pragma unroll
        for (int ni = 0; ni < 4; ni++) {
            int col = bn + warpN + ni * 8 + 2 * r;
            float2 v01 = make_float2(acc[mi][ni][0], acc[mi][ni][1]);
            float2 v23 = make_float2(acc[mi][ni][2], acc[mi][ni][3]);
            *(float2*)(C + (size_t)row0 * N + col) = v01;
            *(float2*)(C + (size_t)(row0 + 8) * N + col) = v23;
        }
    }
}

// Fused Q/K/V projection: grid.x = 12 tiles (8 Q, 2 K, 2 V), grid.y = M/128.
__global__ __launch_bounds__(256, 2)
void gemm_qkv_kernel(const float* __restrict__ x,
                     const float* __restrict__ Wq,
                     const float* __restrict__ Wk,
                     const float* __restrict__ Wv,
                     float* __restrict__ qraw,
                     float* __restrict__ kraw,
                     float* __restrict__ vraw)
{
    const int bx = blockIdx.x;
    const int bm = blockIdx.y * TBM;
    const float* B;
    float* C;
    int N, bn;
    if (bx < 8)       { B = Wq; C = qraw; N = 1024; bn = bx * 128; }
    else if (bx < 10) { B = Wk; C = kraw; N = 256;  bn = (bx - 8) * 128; }
    else              { B = Wv; C = vraw; N = 256;  bn = (bx - 10) * 128; }
    gemm_body(x, B, C, N, DD, bm, bn);
}

__global__ __launch_bounds__(256, 2)
void gemm_o_kernel(const float* __restrict__ A, const float* __restrict__ B,
                   float* __restrict__ C)
{
    gemm_body(A, B, C, DD, DD, blockIdx.y * TBM, blockIdx.x * TBN);
}

// ---------------------------------------------------------------------------
// RoPE + transpose kernels (unchanged)
// ---------------------------------------------------------------------------
__global__ void rope_q_kernel(const float* __restrict__ qraw,
                              const float* __restrict__ cosT,
                              const float* __restrict__ sinT,
                              float* __restrict__ qt)
{
    int idx = blockIdx.x * blockDim.x + threadIdx.x;
    if (idx >= BB * SS * HH * HDIM) return;
    int d = idx & 63;
    int h = (idx >> 6) & (HH - 1);
    int s = (idx >> 10) & (SS - 1);
    int b = idx >> 21;
    float v = qraw[idx];
    float rot = (d < 32) ? -qraw[idx + 32] : qraw[idx - 32];
    float o = v * cosT[s * HDIM + d] + rot * sinT[s * HDIM + d];
    qt[(((size_t)(b * HH + h) * SS) + s) * HDIM + d] = o;
}

__global__ void rope_k_kernel(const float* __restrict__ kraw,
                              const float* __restrict__ cosT,
                              const float* __restrict__ sinT,
                              float* __restrict__ kt)
{
    int idx = blockIdx.x * blockDim.x + threadIdx.x;
    if (idx >= BB * SS * KVH * HDIM) return;
    int d = idx & 63;
    int h = (idx >> 6) & (KVH - 1);
    int s = (idx >> 8) & (SS - 1);
    int b = idx >> 19;
    float v = kraw[idx];
    float rot = (d < 32) ? -kraw[idx + 32] : kraw[idx - 32];
    float o = v * cosT[s * HDIM + d] + rot * sinT[s * HDIM + d];
    kt[(((size_t)(b * KVH + h) * SS) + s) * HDIM + d] = o;
}

__global__ void trans_v_kernel(const float* __restrict__ vraw,
                               float* __restrict__ vt)
{
    int idx = blockIdx.x * blockDim.x + threadIdx.x;
    if (idx >= BB * SS * KVH * HDIM) return;
    int d = idx & 63;
    int h = (idx >> 6) & (KVH - 1);
    int s = (idx >> 8) & (SS - 1);
    int b = idx >> 19;
    vt[(((size_t)(b * KVH + h) * SS) + s) * HDIM + d] = vraw[idx];
}

// ---------------------------------------------------------------------------
// TF32 MMA flash attention (unchanged from R3)
// ---------------------------------------------------------------------------
#define KS_STRIDE 68
#define VS_STRIDE 72
#define PS_STRIDE 68
#define FLASH_SMEM ((64 * KS_STRIDE + 64 * VS_STRIDE + 64 * PS_STRIDE) * 4)
#define FSC 0.18033688011112042f   // 0.125 * log2(e)

__global__ __launch_bounds__(128)
void flash_mma_kernel(const float* __restrict__ Qt, const float* __restrict__ Kt,
                      const float* __restrict__ Vt, float* __restrict__ attn)
{
    extern __shared__ uint32_t sm[];
    uint32_t* Ks = sm;
    uint32_t* Vs = sm + 64 * KS_STRIDE;
    uint32_t* Ps = sm + 64 * KS_STRIDE + 64 * VS_STRIDE;

    const int tid = threadIdx.x;
    const int lane = tid & 31;
    const int w = tid >> 5;
    const int q = lane >> 2;
    const int r = lane & 3;

    const int bx = gridDim.x - 1 - blockIdx.x;
    const int bh = blockIdx.y;
    const int b = bh >> 4;
    const int h = bh & 15;
    const int kvh = h >> 2;

    const float* qbase = Qt + ((size_t)bh * SS + bx * 64) * HDIM;
    const float* kbase = Kt + (size_t)(b * KVH + kvh) * SS * HDIM;
    const float* vbase = Vt + (size_t)(b * KVH + kvh) * SS * HDIM;

#pragma unroll
    for (int it = 0; it < 8; it++) {
        int e = tid + it * 128;
        int row = e >> 4;
        int c4 = (e & 15) << 2;
        float4 v = *(const float4*)(qbase + row * HDIM + c4);
        uint4 u;
        u.x = f2tf32(v.x * FSC); u.y = f2tf32(v.y * FSC);
        u.z = f2tf32(v.z * FSC); u.w = f2tf32(v.w * FSC);
        *(uint4*)(Ps + row * PS_STRIDE + c4) = u;
    }
    __syncthreads();

    uint32_t qf[8][4];
#pragma unroll
    for (int ki = 0; ki < 8; ki++) {
        const uint32_t* p = Ps + (w * 16 + q) * PS_STRIDE + ki * 8 + r;
        qf[ki][0] = p[0];
        qf[ki][1] = p[8 * PS_STRIDE];
        qf[ki][2] = p[4];
        qf[ki][3] = p[8 * PS_STRIDE + 4];
    }
    __syncthreads();

    float of[8][4];
#pragma unroll
    for (int nt = 0; nt < 8; nt++)
#pragma unroll
        for (int e = 0; e < 4; e++) of[nt][e] = 0.f;
    float m0 = -INFINITY, m1 = -INFINITY, l0 = 0.f, l1 = 0.f;

    for (int jt = 0; jt <= bx; jt++) {
        __syncthreads();
#pragma unroll
        for (int it = 0; it < 8; it++) {
            int e = tid + it * 128;
            int row = e >> 4;
            int c4 = (e & 15) << 2;
            size_t goff = (size_t)(jt * 64 + row) * HDIM + c4;
            float4 kv = *(const float4*)(kbase + goff);
            uint4 ku;
            ku.x = f2tf32(kv.x); ku.y = f2tf32(kv.y);
            ku.z = f2tf32(kv.z); ku.w = f2tf32(kv.w);
            *(uint4*)(Ks + row * KS_STRIDE + c4) = ku;
            float4 vv = *(const float4*)(vbase + goff);
            uint4 vu;
            vu.x = f2tf32(vv.x); vu.y = f2tf32(vv.y);
            vu.z = f2tf32(vv.z); vu.w = f2tf32(vv.w);
            *(uint4*)(Vs + row * VS_STRIDE + c4) = vu;
        }
        __syncthreads();

        float sf[8][4];
#pragma unroll
        for (int nt = 0; nt < 8; nt++)
#pragma unroll
            for (int e = 0; e < 4; e++) sf[nt][e] = 0.f;
#pragma unroll
        for (int ki = 0; ki < 8; ki++) {
#pragma unroll
            for (int nt = 0; nt < 8; nt++) {
                uint32_t bfr[2];
                const uint32_t* kp = Ks + (nt * 8 + q) * KS_STRIDE + ki * 8 + r;
                bfr[0] = kp[0];
                bfr[1] = kp[4];
                mma_tf32(sf[nt], qf[ki], bfr, sf[nt]);
            }
        }

        if (jt == bx) {
            const int rowA = w * 16 + q;
            const int rowB = rowA + 8;
#pragma unroll
            for (int nt = 0; nt < 8; nt++) {
                int col = nt * 8 + 2 * r;
                if (col     > rowA) sf[nt][0] = -1e30f;
                if (col + 1 > rowA) sf[nt][1] = -1e30f;
                if (col     > rowB) sf[nt][2] = -1e30f;
                if (col + 1 > rowB) sf[nt][3] = -1e30f;
            }
        }

        float mxA = -1e30f, mxB = -1e30f;
#pragma unroll
        for (int nt = 0; nt < 8; nt++) {
            mxA = fmaxf(mxA, fmaxf(sf[nt][0], sf[nt][1]));
            mxB = fmaxf(mxB, fmaxf(sf[nt][2], sf[nt][3]));
        }
        mxA = fmaxf(mxA, __shfl_xor_sync(0xffffffffu, mxA, 1));
        mxA = fmaxf(mxA, __shfl_xor_sync(0xffffffffu, mxA, 2));
        mxB = fmaxf(mxB, __shfl_xor_sync(0xffffffffu, mxB, 1));
        mxB = fmaxf(mxB, __shfl_xor_sync(0xffffffffu, mxB, 2));

        float mn0 = fmaxf(m0, mxA);
        float mn1 = fmaxf(m1, mxB);
        float sc0 = ex2(m0 - mn0);
        float sc1 = ex2(m1 - mn1);
        m0 = mn0; m1 = mn1;

        float rs0 = 0.f, rs1 = 0.f;
        uint32_t* prow = Ps + (w * 16 + q) * PS_STRIDE;
#pragma unroll
        for (int nt = 0; nt < 8; nt++) {
            float p00 = ex2(sf[nt][0] - m0);
            float p01 = ex2(sf[nt][1] - m0);
            float p10 = ex2(sf[nt][2] - m1);
            float p11 = ex2(sf[nt][3] - m1);
            rs0 += p00 + p01;
            rs1 += p10 + p11;
            uint32_t* pp = prow + nt * 8 + 2 * r;
            pp[0] = f2tf32(p00);
            pp[1] = f2tf32(p01);
            pp[8 * PS_STRIDE]     = f2tf32(p10);
            pp[8 * PS_STRIDE + 1] = f2tf32(p11);
        }
        rs0 += __shfl_xor_sync(0xffffffffu, rs0, 1);
        rs0 += __shfl_xor_sync(0xffffffffu, rs0, 2);
        rs1 += __shfl_xor_sync(0xffffffffu, rs1, 1);
        rs1 += __shfl_xor_sync(0xffffffffu, rs1, 2);
        l0 = l0 * sc0 + rs0;
        l1 = l1 * sc1 + rs1;
#pragma unroll
        for (int nt = 0; nt < 8; nt++) {
            of[nt][0] *= sc0; of[nt][1] *= sc0;
            of[nt][2] *= sc1; of[nt][3] *= sc1;
        }
        __syncwarp();

#pragma unroll
        for (int kk = 0; kk < 8; kk++) {
            uint32_t af[4];
            const uint32_t* ap = prow + kk * 8 + r;
            af[0] = ap[0];
            af[1] = ap[8 * PS_STRIDE];
            af[2] = ap[4];
            af[3] = ap[8 * PS_STRIDE + 4];
#pragma unroll
            for (int nt = 0; nt < 8; nt++) {
                uint32_t bfr[2];
                const uint32_t* vp = Vs + (kk * 8 + r) * VS_STRIDE + nt * 8 + q;
                bfr[0] = vp[0];
                bfr[1] = vp[4 * VS_STRIDE];
                mma_tf32(of[nt], af, bfr, of[nt]);
            }
        }
    }

    const float il0 = 1.f / l0;
    const float il1 = 1.f / l1;
    float* ob = attn + ((size_t)b * SS + bx * 64 + w * 16) * (HH * HDIM) + h * HDIM;
#pragma unroll
    for (int nt = 0; nt < 8; nt++) {
        int col = nt * 8 + 2 * r;
        float2 vA = make_float2(of[nt][0] * il0, of[nt][1] * il0);
        float2 vB = make_float2(of[nt][2] * il1, of[nt][3] * il1);
        *(float2*)(ob + (size_t)q * (HH * HDIM) + col) = vA;
        *(float2*)(ob + (size_t)(q + 8) * (HH * HDIM) + col) = vB;
    }
}

// ---------------------------------------------------------------------------
// Launch
// ---------------------------------------------------------------------------
extern "C" void kernel_launch(void* const* d_in, const int* in_sizes, int n_in,
                              void* d_out, int out_size)
{
    (void)in_sizes; (void)n_in; (void)out_size;
    const float* x    = (const float*)d_in[0];
    const float* cosT = (const float*)d_in[1];
    const float* sinT = (const float*)d_in[2];
    const float* Wq   = (const float*)d_in[3];
    const float* Wk   = (const float*)d_in[4];
    const float* Wv   = (const float*)d_in[5];
    const float* Wo   = (const float*)d_in[6];
    float* out = (float*)d_out;

    static bool attr_set = false;
    if (!attr_set) {
        cudaFuncSetAttribute(flash_mma_kernel,
                             cudaFuncAttributeMaxDynamicSharedMemorySize,
                             FLASH_SMEM);
        cudaFuncSetAttribute(gemm_qkv_kernel,
                             cudaFuncAttributeMaxDynamicSharedMemorySize,
                             GSMEM);
        cudaFuncSetAttribute(gemm_o_kernel,
                             cudaFuncAttributeMaxDynamicSharedMemorySize,
                             GSMEM);
        attr_set = true;
    }

    float *qraw, *kraw, *vraw, *qt, *kt, *vt, *attn;
    cudaGetSymbolAddress((void**)&qraw, g_qraw);
    cudaGetSymbolAddress((void**)&kraw, g_kraw);
    cudaGetSymbolAddress((void**)&vraw, g_vraw);
    cudaGetSymbolAddress((void**)&qt,   g_qt);
    cudaGetSymbolAddress((void**)&kt,   g_kt);
    cudaGetSymbolAddress((void**)&vt,   g_vt);
    cudaGetSymbolAddress((void**)&attn, g_attn);

    const int M = BB * SS;   // 4096

    // 1) Fused Q/K/V projections (pipelined TF32 MMA)
    gemm_qkv_kernel<<<dim3(12, M / TBM), 256, GSMEM>>>(x, Wq, Wk, Wv,
                                                       qraw, kraw, vraw);

    // 2) RoPE + transpose
    {
        int nq = BB * SS * HH * HDIM;
        rope_q_kernel<<<(nq + 255) / 256, 256>>>(qraw, cosT, sinT, qt);
        int nk = BB * SS * KVH * HDIM;
        rope_k_kernel<<<(nk + 255) / 256, 256>>>(kraw, cosT, sinT, kt);
        trans_v_kernel<<<(nk + 255) / 256, 256>>>(vraw, vt);
    }

    // 3) Causal GQA attention (TF32 MMA flash)
    flash_mma_kernel<<<dim3(SS / 64, BB * HH), 128, FLASH_SMEM>>>(qt, kt, vt, attn);

    // 4) Output projection
    gemm_o_kernel<<<dim3(DD / TBN, M / TBM), 256, GSMEM>>>(attn, Wo, out);
}

// round 7
// speedup vs baseline: 5.1079x; 1.0437x over previous
#include <cuda_runtime.h>
#include <math.h>
#include <stdint.h>

// Problem constants
#define BB 2
#define SS 2048
#define DD 1024
#define HH 16
#define KVH 4
#define HDIM 64
#define NREP (HH / KVH)   // 4

// Scratch (allocation-free: __device__ globals)
__device__ float g_qraw[BB * SS * HH * HDIM];
__device__ float g_kraw[BB * SS * KVH * HDIM];
__device__ float g_vraw[BB * SS * KVH * HDIM];
__device__ float g_qt[BB * HH * SS * HDIM];
__device__ float g_kt[BB * KVH * SS * HDIM];
__device__ float g_vt[BB * KVH * SS * HDIM];
__device__ float g_attn[BB * SS * HH * HDIM];   // rounded tf32 by flash epilogue
__device__ float g_xr[BB * SS * DD];            // x rounded to tf32
__device__ float g_wq[DD * DD];                 // rounded weights (same layout)
__device__ float g_wk[DD * 256];
__device__ float g_wv[DD * 256];
__device__ float g_wo[DD * DD];

__device__ __forceinline__ uint32_t f2tf32(float f) {
    uint32_t u;
    asm("cvt.rna.tf32.f32 %0, %1;" : "=r"(u) : "f"(f));
    return u;
}
__device__ __forceinline__ float round_tf32(float f) {
    return __uint_as_float(f2tf32(f));
}
__device__ __forceinline__ float ex2(float x) {
    float y;
    asm("ex2.approx.ftz.f32 %0, %1;" : "=f"(y) : "f"(x));
    return y;
}
__device__ __forceinline__ void mma_tf32(float d[4], const uint32_t a[4],
                                         const uint32_t b[2], const float c[4]) {
    asm volatile(
        "mma.sync.aligned.m16n8k8.row.col.f32.tf32.tf32.f32 "
        "{%0,%1,%2,%3}, {%4,%5,%6,%7}, {%8,%9}, {%10,%11,%12,%13};"
        : "=f"(d[0]), "=f"(d[1]), "=f"(d[2]), "=f"(d[3])
        : "r"(a[0]), "r"(a[1]), "r"(a[2]), "r"(a[3]),
          "r"(b[0]), "r"(b[1]),
          "f"(c[0]), "f"(c[1]), "f"(c[2]), "f"(c[3]));
}

__device__ __forceinline__ void cpa8(uint32_t dst, const void* src) {
    asm volatile("cp.async.ca.shared.global [%0], [%1], 8;"
                 :: "r"(dst), "l"(src));
}
__device__ __forceinline__ void cp_commit() {
    asm volatile("cp.async.commit_group;" ::: "memory");
}
template <int N>
__device__ __forceinline__ void cp_wait() {
    asm volatile("cp.async.wait_group %0;" :: "n"(N) : "memory");
}

// ---------------------------------------------------------------------------
// Prep: round tensors to tf32-rna in place-copy (removes all CVTs from GEMM
// mainloops; numerics identical to cvt-at-load).
// ---------------------------------------------------------------------------
__global__ void round_kernel(const float* __restrict__ src,
                             float* __restrict__ dst, int n4)
{
    int i = blockIdx.x * blockDim.x + threadIdx.x;
    if (i >= n4) return;
    float4 v = ((const float4*)src)[i];
    v.x = round_tf32(v.x); v.y = round_tf32(v.y);
    v.z = round_tf32(v.z); v.w = round_tf32(v.w);
    ((float4*)dst)[i] = v;
}

// ---------------------------------------------------------------------------
// Pipelined TF32 tensor-core GEMM. C[M,N] = A[M,K] @ B[K,N] row-major.
// Operands pre-rounded to tf32 -> fragment loads are plain LDS (no CVT).
// BM=128, BN=128, BK=32, 256 threads (8 warps 2x4), warp tile 64x32.
// ---------------------------------------------------------------------------
#define TBM 128
#define TBN 128
#define TBK 32
#define AS_STRIDE 36
#define BS_STRIDE 136
#define ASZ (TBM * AS_STRIDE)
#define BSZ (TBK * BS_STRIDE)
#define GSMEM ((ASZ + BSZ) * 2 * 4)

__device__ __forceinline__ void gemm_copy_tile(
    const float* __restrict__ A, const float* __restrict__ B,
    int K, int N, int bm, int bn, int k0,
    float* sA, float* sB, int tid)
{
    uint32_t abase = (uint32_t)__cvta_generic_to_shared(sA);
    uint32_t bbase = (uint32_t)__cvta_generic_to_shared(sB);
#pragma unroll
    for (int i = 0; i < 8; i++) {
        int e = tid + i * 256;
        int row = e >> 4;
        int c2 = (e & 15) * 2;
        cpa8(abase + (row * AS_STRIDE + c2) * 4,
             A + (size_t)(bm + row) * K + k0 + c2);
    }
#pragma unroll
    for (int i = 0; i < 8; i++) {
        int e = tid + i * 256;
        int row = e >> 6;
        int c2 = (e & 63) * 2;
        cpa8(bbase + (row * BS_STRIDE + c2) * 4,
             B + (size_t)(k0 + row) * N + bn + c2);
    }
}

__device__ __forceinline__ void gemm_compute_tile(
    const uint32_t* __restrict__ sA, const uint32_t* __restrict__ sB,
    float acc[4][4][4], int warpM, int warpN, int q, int r)
{
#pragma unroll
    for (int ki = 0; ki < 4; ki++) {
        uint32_t afr[4][4];
        uint32_t bfr[4][2];
#pragma unroll
        for (int mi = 0; mi < 4; mi++) {
            const uint32_t* ap = &sA[(warpM + mi * 16 + q) * AS_STRIDE + ki * 8 + r];
            afr[mi][0] = ap[0];
            afr[mi][1] = ap[8 * AS_STRIDE];
            afr[mi][2] = ap[4];
            afr[mi][3] = ap[8 * AS_STRIDE + 4];
        }
#pragma unroll
        for (int ni = 0; ni < 4; ni++) {
            const uint32_t* bp = &sB[(ki * 8 + r) * BS_STRIDE + warpN + ni * 8 + q];
            bfr[ni][0] = bp[0];
            bfr[ni][1] = bp[4 * BS_STRIDE];
        }
#pragma unroll
        for (int mi = 0; mi < 4; mi++)
#pragma unroll
            for (int ni = 0; ni < 4; ni++)
                mma_tf32(acc[mi][ni], afr[mi], bfr[ni], acc[mi][ni]);
    }
}

__device__ __forceinline__ void gemm_body(
    const float* __restrict__ A, const float* __restrict__ B,
    float* __restrict__ C, int N, int K, int bm, int bn)
{
    extern __shared__ float gsm[];
    float* sA0 = gsm;
    float* sB0 = gsm + ASZ;
    float* sA1 = gsm + ASZ + BSZ;
    float* sB1 = gsm + 2 * ASZ + BSZ;

    const int tid = threadIdx.x;
    const int lane = tid & 31;
    const int warp = tid >> 5;
    const int q = lane >> 2;
    const int r = lane & 3;
    const int warpM = (warp & 1) * 64;
    const int warpN = (warp >> 1) * 32;

    float acc[4][4][4];
#pragma unroll
    for (int mi = 0; mi < 4; mi++)
#pragma unroll
        for (int ni = 0; ni < 4; ni++)
#pragma unroll
            for (int e = 0; e < 4; e++) acc[mi][ni][e] = 0.f;

    const int T = K / TBK;

    gemm_copy_tile(A, B, K, N, bm, bn, 0, sA0, sB0, tid);
    cp_commit();

    for (int t = 0; t < T - 1; t++) {
        float* la = (t & 1) ? sA1 : sA0;
        float* lb = (t & 1) ? sB1 : sB0;
        float* na = (t & 1) ? sA0 : sA1;
        float* nb = (t & 1) ? sB0 : sB1;
        gemm_copy_tile(A, B, K, N, bm, bn, (t + 1) * TBK, na, nb, tid);
        cp_commit();
        cp_wait<1>();
        __syncthreads();
        gemm_compute_tile((const uint32_t*)la, (const uint32_t*)lb,
                          acc, warpM, warpN, q, r);
        __syncthreads();
    }
    cp_wait<0>();
    __syncthreads();
    {
        float* la = ((T - 1) & 1) ? sA1 : sA0;
        float* lb = ((T - 1) & 1) ? sB1 : sB0;
        gemm_compute_tile((const uint32_t*)la, (const uint32_t*)lb,
                          acc, warpM, warpN, q, r);
    }

#pragma unroll
    for (int mi = 0; mi < 4; mi++) {
        int row0 = bm + warpM + mi * 16 + q;
#pragma unroll
        for (int ni = 0; ni < 4; ni++) {
            int col = bn + warpN + ni * 8 + 2 * r;
            float2 v01 = make_float2(acc[mi][ni][0], acc[mi][ni][1]);
            float2 v23 = make_float2(acc[mi][ni][2], acc[mi][ni][3]);
            *(float2*)(C + (size_t)row0 * N + col) = v01;
            *(float2*)(C + (size_t)(row0 + 8) * N + col) = v23;
        }
    }
}

// Fused Q/K/V projection: grid.x = 12 tiles (8 Q, 2 K, 2 V), grid.y = M/128.
__global__ __launch_bounds__(256, 2)
void gemm_qkv_kernel(const float* __restrict__ x,
                     const float* __restrict__ Wq,
                     const float* __restrict__ Wk,
                     const float* __restrict__ Wv,
                     float* __restrict__ qraw,
                     float* __restrict__ kraw,
                     float* __restrict__ vraw)
{
    const int bx = blockIdx.x;
    const int bm = blockIdx.y * TBM;
    const float* B;
    float* C;
    int N, bn;
    if (bx < 8)       { B = Wq; C = qraw; N = 1024; bn = bx * 128; }
    else if (bx < 10) { B = Wk; C = kraw; N = 256;  bn = (bx - 8) * 128; }
    else              { B = Wv; C = vraw; N = 256;  bn = (bx - 10) * 128; }
    gemm_body(x, B, C, N, DD, bm, bn);
}

__global__ __launch_bounds__(256, 2)
void gemm_o_kernel(const float* __restrict__ A, const float* __restrict__ B,
                   float* __restrict__ C)
{
    gemm_body(A, B, C, DD, DD, blockIdx.y * TBM, blockIdx.x * TBN);
}

// ---------------------------------------------------------------------------
// RoPE + transpose kernels (float4-vectorized)
// ---------------------------------------------------------------------------
__global__ void rope_q_kernel(const float* __restrict__ qraw,
                              const float* __restrict__ cosT,
                              const float* __restrict__ sinT,
                              float* __restrict__ qt)
{
    int i = blockIdx.x * blockDim.x + threadIdx.x;   // float4 index
    if (i >= BB * SS * HH * 16) return;
    int d4 = i & 15;
    int h = (i >> 4) & 15;
    int s = (i >> 8) & 2047;
    int b = i >> 19;
    const float4* q4 = (const float4*)qraw;
    float4 v = q4[i];
    float4 rot;
    if (d4 < 8) {
        float4 u = q4[i + 8];
        rot = make_float4(-u.x, -u.y, -u.z, -u.w);
    } else {
        rot = q4[i - 8];
    }
    float4 cs = ((const float4*)cosT)[s * 16 + d4];
    float4 sn = ((const float4*)sinT)[s * 16 + d4];
    float4 o;
    o.x = v.x * cs.x + rot.x * sn.x;
    o.y = v.y * cs.y + rot.y * sn.y;
    o.z = v.z * cs.z + rot.z * sn.z;
    o.w = v.w * cs.w + rot.w * sn.w;
    ((float4*)qt)[(((size_t)(b * HH + h) * SS) + s) * 16 + d4] = o;
}

__global__ void rope_k_kernel(const float* __restrict__ kraw,
                              const float* __restrict__ cosT,
                              const float* __restrict__ sinT,
                              float* __restrict__ kt)
{
    int i = blockIdx.x * blockDim.x + threadIdx.x;
    if (i >= BB * SS * KVH * 16) return;
    int d4 = i & 15;
    int kv = (i >> 4) & 3;
    int s = (i >> 6) & 2047;
    int b = i >> 17;
    const float4* k4 = (const float4*)kraw;
    float4 v = k4[i];
    float4 rot;
    if (d4 < 8) {
        float4 u = k4[i + 8];
        rot = make_float4(-u.x, -u.y, -u.z, -u.w);
    } else {
        rot = k4[i - 8];
    }
    float4 cs = ((const float4*)cosT)[s * 16 + d4];
    float4 sn = ((const float4*)sinT)[s * 16 + d4];
    float4 o;
    o.x = v.x * cs.x + rot.x * sn.x;
    o.y = v.y * cs.y + rot.y * sn.y;
    o.z = v.z * cs.z + rot.z * sn.z;
    o.w = v.w * cs.w + rot.w * sn.w;
    ((float4*)kt)[(((size_t)(b * KVH + kv) * SS) + s) * 16 + d4] = o;
}

__global__ void trans_v_kernel(const float* __restrict__ vraw,
                               float* __restrict__ vt)
{
    int i = blockIdx.x * blockDim.x + threadIdx.x;
    if (i >= BB * SS * KVH * 16) return;
    int d4 = i & 15;
    int kv = (i >> 4) & 3;
    int s = (i >> 6) & 2047;
    int b = i >> 17;
    ((float4*)vt)[(((size_t)(b * KVH + kv) * SS) + s) * 16 + d4] =
        ((const float4*)vraw)[i];
}

// ---------------------------------------------------------------------------
// TF32 MMA flash attention (R3 design; epilogue rounds output to tf32-rna
// so the O-projection needs no cvt on its A operand)
// ---------------------------------------------------------------------------
#define KS_STRIDE 68
#define VS_STRIDE 72
#define PS_STRIDE 68
#define FLASH_SMEM ((64 * KS_STRIDE + 64 * VS_STRIDE + 64 * PS_STRIDE) * 4)
#define FSC 0.18033688011112042f   // 0.125 * log2(e)

__global__ __launch_bounds__(128)
void flash_mma_kernel(const float* __restrict__ Qt, const float* __restrict__ Kt,
                      const float* __restrict__ Vt, float* __restrict__ attn)
{
    extern __shared__ uint32_t sm[];
    uint32_t* Ks = sm;
    uint32_t* Vs = sm + 64 * KS_STRIDE;
    uint32_t* Ps = sm + 64 * KS_STRIDE + 64 * VS_STRIDE;

    const int tid = threadIdx.x;
    const int lane = tid & 31;
    const int w = tid >> 5;
    const int q = lane >> 2;
    const int r = lane & 3;

    const int bx = gridDim.x - 1 - blockIdx.x;
    const int bh = blockIdx.y;
    const int b = bh >> 4;
    const int h = bh & 15;
    const int kvh = h >> 2;

    const float* qbase = Qt + ((size_t)bh * SS + bx * 64) * HDIM;
    const float* kbase = Kt + (size_t)(b * KVH + kvh) * SS * HDIM;
    const float* vbase = Vt + (size_t)(b * KVH + kvh) * SS * HDIM;

#pragma unroll
    for (int it = 0; it < 8; it++) {
        int e = tid + it * 128;
        int row = e >> 4;
        int c4 = (e & 15) << 2;
        float4 v = *(const float4*)(qbase + row * HDIM + c4);
        uint4 u;
        u.x = f2tf32(v.x * FSC); u.y = f2tf32(v.y * FSC);
        u.z = f2tf32(v.z * FSC); u.w = f2tf32(v.w * FSC);
        *(uint4*)(Ps + row * PS_STRIDE + c4) = u;
    }
    __syncthreads();

    uint32_t qf[8][4];
#pragma unroll
    for (int ki = 0; ki < 8; ki++) {
        const uint32_t* p = Ps + (w * 16 + q) * PS_STRIDE + ki * 8 + r;
        qf[ki][0] = p[0];
        qf[ki][1] = p[8 * PS_STRIDE];
        qf[ki][2] = p[4];
        qf[ki][3] = p[8 * PS_STRIDE + 4];
    }
    __syncthreads();

    float of[8][4];
#pragma unroll
    for (int nt = 0; nt < 8; nt++)
#pragma unroll
        for (int e = 0; e < 4; e++) of[nt][e] = 0.f;
    float m0 = -INFINITY, m1 = -INFINITY, l0 = 0.f, l1 = 0.f;

    for (int jt = 0; jt <= bx; jt++) {
        __syncthreads();
#pragma unroll
        for (int it = 0; it < 8; it++) {
            int e = tid + it * 128;
            int row = e >> 4;
            int c4 = (e & 15) << 2;
            size_t goff = (size_t)(jt * 64 + row) * HDIM + c4;
            float4 kv = *(const float4*)(kbase + goff);
            uint4 ku;
            ku.x = f2tf32(kv.x); ku.y = f2tf32(kv.y);
            ku.z = f2tf32(kv.z); ku.w = f2tf32(kv.w);
            *(uint4*)(Ks + row * KS_STRIDE + c4) = ku;
            float4 vv = *(const float4*)(vbase + goff);
            uint4 vu;
            vu.x = f2tf32(vv.x); vu.y = f2tf32(vv.y);
            vu.z = f2tf32(vv.z); vu.w = f2tf32(vv.w);
            *(uint4*)(Vs + row * VS_STRIDE + c4) = vu;
        }
        __syncthreads();

        float sf[8][4];
#pragma unroll
        for (int nt = 0; nt < 8; nt++)
#pragma unroll
            for (int e = 0; e < 4; e++) sf[nt][e] = 0.f;
#pragma unroll
        for (int ki = 0; ki < 8; ki++) {
#pragma unroll
            for (int nt = 0; nt < 8; nt++) {
                uint32_t bfr[2];
                const uint32_t* kp = Ks + (nt * 8 + q) * KS_STRIDE + ki * 8 + r;
                bfr[0] = kp[0];
                bfr[1] = kp[4];
                mma_tf32(sf[nt], qf[ki], bfr, sf[nt]);
            }
        }

        if (jt == bx) {
            const int rowA = w * 16 + q;
            const int rowB = rowA + 8;
#pragma unroll
            for (int nt = 0; nt < 8; nt++) {
                int col = nt * 8 + 2 * r;
                if (col     > rowA) sf[nt][0] = -1e30f;
                if (col + 1 > rowA) sf[nt][1] = -1e30f;
                if (col     > rowB) sf[nt][2] = -1e30f;
                if (col + 1 > rowB) sf[nt][3] = -1e30f;
            }
        }

        float mxA = -1e30f, mxB = -1e30f;
#pragma unroll
        for (int nt = 0; nt < 8; nt++) {
            mxA = fmaxf(mxA, fmaxf(sf[nt][0], sf[nt][1]));
            mxB = fmaxf(mxB, fmaxf(sf[nt][2], sf[nt][3]));
        }
        mxA = fmaxf(mxA, __shfl_xor_sync(0xffffffffu, mxA, 1));
        mxA = fmaxf(mxA, __shfl_xor_sync(0xffffffffu, mxA, 2));
        mxB = fmaxf(mxB, __shfl_xor_sync(0xffffffffu, mxB, 1));
        mxB = fmaxf(mxB, __shfl_xor_sync(0xffffffffu, mxB, 2));

        float mn0 = fmaxf(m0, mxA);
        float mn1 = fmaxf(m1, mxB);
        float sc0 = ex2(m0 - mn0);
        float sc1 = ex2(m1 - mn1);
        m0 = mn0; m1 = mn1;

        float rs0 = 0.f, rs1 = 0.f;
        uint32_t* prow = Ps + (w * 16 + q) * PS_STRIDE;
#pragma unroll
        for (int nt = 0; nt < 8; nt++) {
            float p00 = ex2(sf[nt][0] - m0);
            float p01 = ex2(sf[nt][1] - m0);
            float p10 = ex2(sf[nt][2] - m1);
            float p11 = ex2(sf[nt][3] - m1);
            rs0 += p00 + p01;
            rs1 += p10 + p11;
            uint32_t* pp = prow + nt * 8 + 2 * r;
            pp[0] = f2tf32(p00);
            pp[1] = f2tf32(p01);
            pp[8 * PS_STRIDE]     = f2tf32(p10);
            pp[8 * PS_STRIDE + 1] = f2tf32(p11);
        }
        rs0 += __shfl_xor_sync(0xffffffffu, rs0, 1);
        rs0 += __shfl_xor_sync(0xffffffffu, rs0, 2);
        rs1 += __shfl_xor_sync(0xffffffffu, rs1, 1);
        rs1 += __shfl_xor_sync(0xffffffffu, rs1, 2);
        l0 = l0 * sc0 + rs0;
        l1 = l1 * sc1 + rs1;
#pragma unroll
        for (int nt = 0; nt < 8; nt++) {
            of[nt][0] *= sc0; of[nt][1] *= sc0;
            of[nt][2] *= sc1; of[nt][3] *= sc1;
        }
        __syncwarp();

#pragma unroll
        for (int kk = 0; kk < 8; kk++) {
            uint32_t af[4];
            const uint32_t* ap = prow + kk * 8 + r;
            af[0] = ap[0];
            af[1] = ap[8 * PS_STRIDE];
            af[2] = ap[4];
            af[3] = ap[8 * PS_STRIDE + 4];
#pragma unroll
            for (int nt = 0; nt < 8; nt++) {
                uint32_t bfr[2];
                const uint32_t* vp = Vs + (kk * 8 + r) * VS_STRIDE + nt * 8 + q;
                bfr[0] = vp[0];
                bfr[1] = vp[4 * VS_STRIDE];
                mma_tf32(of[nt], af, bfr, of[nt]);
            }
        }
    }

    const float il0 = 1.f / l0;
    const float il1 = 1.f / l1;
    float* ob = attn + ((size_t)b * SS + bx * 64 + w * 16) * (HH * HDIM) + h * HDIM;
#pragma unroll
    for (int nt = 0; nt < 8; nt++) {
        int col = nt * 8 + 2 * r;
        float2 vA = make_float2(round_tf32(of[nt][0] * il0),
                                round_tf32(of[nt][1] * il0));
        float2 vB = make_float2(round_tf32(of[nt][2] * il1),
                                round_tf32(of[nt][3] * il1));
        *(float2*)(ob + (size_t)q * (HH * HDIM) + col) = vA;
        *(float2*)(ob + (size_t)(q + 8) * (HH * HDIM) + col) = vB;
    }
}

// ---------------------------------------------------------------------------
// Launch
// ---------------------------------------------------------------------------
extern "C" void kernel_launch(void* const* d_in, const int* in_sizes, int n_in,
                              void* d_out, int out_size)
{
    (void)in_sizes; (void)n_in; (void)out_size;
    const float* x    = (const float*)d_in[0];
    const float* cosT = (const float*)d_in[1];
    const float* sinT = (const float*)d_in[2];
    const float* Wq   = (const float*)d_in[3];
    const float* Wk   = (const float*)d_in[4];
    const float* Wv   = (const float*)d_in[5];
    const float* Wo   = (const float*)d_in[6];
    float* out = (float*)d_out;

    static bool attr_set = false;
    if (!attr_set) {
        cudaFuncSetAttribute(flash_mma_kernel,
                             cudaFuncAttributeMaxDynamicSharedMemorySize,
                             FLASH_SMEM);
        cudaFuncSetAttribute(gemm_qkv_kernel,
                             cudaFuncAttributeMaxDynamicSharedMemorySize,
                             GSMEM);
        cudaFuncSetAttribute(gemm_o_kernel,
                             cudaFuncAttributeMaxDynamicSharedMemorySize,
                             GSMEM);
        attr_set = true;
    }

    float *qraw, *kraw, *vraw, *qt, *kt, *vt, *attn;
    float *xr, *wq, *wk, *wv, *wo;
    cudaGetSymbolAddress((void**)&qraw, g_qraw);
    cudaGetSymbolAddress((void**)&kraw, g_kraw);
    cudaGetSymbolAddress((void**)&vraw, g_vraw);
    cudaGetSymbolAddress((void**)&qt,   g_qt);
    cudaGetSymbolAddress((void**)&kt,   g_kt);
    cudaGetSymbolAddress((void**)&vt,   g_vt);
    cudaGetSymbolAddress((void**)&attn, g_attn);
    cudaGetSymbolAddress((void**)&xr,   g_xr);
    cudaGetSymbolAddress((void**)&wq,   g_wq);
    cudaGetSymbolAddress((void**)&wk,   g_wk);
    cudaGetSymbolAddress((void**)&wv,   g_wv);
    cudaGetSymbolAddress((void**)&wo,   g_wo);

    const int M = BB * SS;   // 4096

    // 0) Pre-round operands to tf32-rna (eliminates CVTs in GEMM mainloops)
    round_kernel<<<(M * DD / 4 + 255) / 256, 256>>>(x, xr, M * DD / 4);
    round_kernel<<<(DD * DD / 4 + 255) / 256, 256>>>(Wq, wq, DD * DD / 4);
    round_kernel<<<(DD * 256 / 4 + 255) / 256, 256>>>(Wk, wk, DD * 256 / 4);
    round_kernel<<<(DD * 256 / 4 + 255) / 256, 256>>>(Wv, wv, DD * 256 / 4);
    round_kernel<<<(DD * DD / 4 + 255) / 256, 256>>>(Wo, wo, DD * DD / 4);

    // 1) Fused Q/K/V projections (pipelined TF32 MMA, no CVT in loop)
    gemm_qkv_kernel<<<dim3(12, M / TBM), 256, GSMEM>>>(xr, wq, wk, wv,
                                                       qraw, kraw, vraw);

    // 2) RoPE + transpose (float4)
    rope_q_kernel<<<(BB * SS * HH * 16 + 255) / 256, 256>>>(qraw, cosT, sinT, qt);
    rope_k_kernel<<<(BB * SS * KVH * 16 + 255) / 256, 256>>>(kraw, cosT, sinT, kt);
    trans_v_kernel<<<(BB * SS * KVH * 16 + 255) / 256, 256>>>(vraw, vt);

    // 3) Causal GQA attention (TF32 MMA flash)
    flash_mma_kernel<<<dim3(SS / 64, BB * HH), 128, FLASH_SMEM>>>(qt, kt, vt, attn);

    // 4) Output projection (attn already tf32-rounded by flash epilogue)
    gemm_o_kernel<<<dim3(DD / TBN, M / TBM), 256, GSMEM>>>(attn, wo, out);
}

// round 8
// speedup vs baseline: 6.3579x; 1.2447x over previous
#include <cuda_runtime.h>
#include <cuda_fp16.h>
#include <math.h>
#include <stdint.h>

// Problem constants
#define BB 2
#define SS 2048
#define DD 1024
#define HH 16
#define KVH 4
#define HDIM 64
#define NREP (HH / KVH)   // 4

// Scratch (allocation-free: __device__ globals)
__device__ float  g_qraw[BB * SS * HH * HDIM];
__device__ float  g_kraw[BB * SS * KVH * HDIM];
__device__ float  g_vraw[BB * SS * KVH * HDIM];
__device__ float  g_qt[BB * HH * SS * HDIM];
__device__ float  g_kt[BB * KVH * SS * HDIM];
__device__ float  g_vt[BB * KVH * SS * HDIM];
__device__ __half g_attn[BB * SS * HH * HDIM];  // fp16, written by flash epilogue
__device__ __half g_xh[BB * SS * DD];           // x in fp16 [M][K]
__device__ __half g_wqt[DD * DD];               // Wq^T fp16 [N=1024][K=1024]
__device__ __half g_wkt[256 * DD];              // Wk^T fp16 [256][1024]
__device__ __half g_wvt[256 * DD];
__device__ __half g_wot[DD * DD];               // Wo^T fp16

__device__ __forceinline__ uint32_t f2tf32(float f) {
    uint32_t u;
    asm("cvt.rna.tf32.f32 %0, %1;" : "=r"(u) : "f"(f));
    return u;
}
__device__ __forceinline__ float ex2(float x) {
    float y;
    asm("ex2.approx.ftz.f32 %0, %1;" : "=f"(y) : "f"(x));
    return y;
}
__device__ __forceinline__ void mma_tf32(float d[4], const uint32_t a[4],
                                         const uint32_t b[2], const float c[4]) {
    asm volatile(
        "mma.sync.aligned.m16n8k8.row.col.f32.tf32.tf32.f32 "
        "{%0,%1,%2,%3}, {%4,%5,%6,%7}, {%8,%9}, {%10,%11,%12,%13};"
        : "=f"(d[0]), "=f"(d[1]), "=f"(d[2]), "=f"(d[3])
        : "r"(a[0]), "r"(a[1]), "r"(a[2]), "r"(a[3]),
          "r"(b[0]), "r"(b[1]),
          "f"(c[0]), "f"(c[1]), "f"(c[2]), "f"(c[3]));
}
__device__ __forceinline__ void mma_f16(float d[4], const uint32_t a[4],
                                        const uint32_t b[2], const float c[4]) {
    asm volatile(
        "mma.sync.aligned.m16n8k16.row.col.f32.f16.f16.f32 "
        "{%0,%1,%2,%3}, {%4,%5,%6,%7}, {%8,%9}, {%10,%11,%12,%13};"
        : "=f"(d[0]), "=f"(d[1]), "=f"(d[2]), "=f"(d[3])
        : "r"(a[0]), "r"(a[1]), "r"(a[2]), "r"(a[3]),
          "r"(b[0]), "r"(b[1]),
          "f"(c[0]), "f"(c[1]), "f"(c[2]), "f"(c[3]));
}

__device__ __forceinline__ void cpa16(uint32_t dst, const void* src) {
    asm volatile("cp.async.ca.shared.global [%0], [%1], 16;"
                 :: "r"(dst), "l"(src));
}
__device__ __forceinline__ void cp_commit() {
    asm volatile("cp.async.commit_group;" ::: "memory");
}
template <int N>
__device__ __forceinline__ void cp_wait() {
    asm volatile("cp.async.wait_group %0;" :: "n"(N) : "memory");
}

// ---------------------------------------------------------------------------
// Prep kernels: convert x -> fp16; transpose+convert W -> fp16 [N][K]
// ---------------------------------------------------------------------------
__global__ void conv_x_kernel(const float* __restrict__ x,
                              __half* __restrict__ xh, int n4)
{
    int i = blockIdx.x * blockDim.x + threadIdx.x;
    if (i >= n4) return;
    float4 v = ((const float4*)x)[i];
    __half2* o = (__half2*)xh;
    o[2 * i]     = __floats2half2_rn(v.x, v.y);
    o[2 * i + 1] = __floats2half2_rn(v.z, v.w);
}

__global__ void transpose_w_kernel(const float* __restrict__ W,
                                   __half* __restrict__ Wt, int K, int N)
{
    __shared__ float tile[32][33];
    const int n0 = blockIdx.x * 32;
    const int k0 = blockIdx.y * 32;
    const int tx = threadIdx.x;
#pragma unroll
    for (int ty = threadIdx.y; ty < 32; ty += 8)
        tile[ty][tx] = W[(size_t)(k0 + ty) * N + n0 + tx];
    __syncthreads();
#pragma unroll
    for (int ty = threadIdx.y; ty < 32; ty += 8)
        Wt[(size_t)(n0 + ty) * K + k0 + tx] = __float2half_rn(tile[tx][ty]);
}

// ---------------------------------------------------------------------------
// fp16 tensor-core GEMM: C[M,N] = A[M,K] @ Bt[N,K]^T, C fp32.
// BM=128, BN=128, BK=64 (halves), 256 threads (8 warps 2x4), warp 64x32.
// m16n8k16 fp16 MMA, fp32 accum. Smem stride 72 halves (36 words):
// fragment bank = 4q + r, conflict-free. 2-stage cp.async.
// ---------------------------------------------------------------------------
#define TBM 128
#define TBN 128
#define TBK 64
#define HS 72                       // smem stride in halves
#define HSW 36                      // in words
#define TILE_H (128 * HS)           // halves per tile
#define STAGE_B (TILE_H * 2 * 2)    // bytes per stage (A+B)
#define GSMEM (STAGE_B * 2)         // 73728 bytes

__device__ __forceinline__ void gemm_copy_tile(
    const __half* __restrict__ A, const __half* __restrict__ Bt,
    int K, int bm, int bn, int k0,
    uint32_t abase, uint32_t bbase, int tid)
{
#pragma unroll
    for (int i = 0; i < 4; i++) {
        int e = tid + i * 256;
        int row = e >> 3;
        int ch = e & 7;
        cpa16(abase + row * (HS * 2) + ch * 16,
              A + (size_t)(bm + row) * K + k0 + ch * 8);
    }
#pragma unroll
    for (int i = 0; i < 4; i++) {
        int e = tid + i * 256;
        int row = e >> 3;
        int ch = e & 7;
        cpa16(bbase + row * (HS * 2) + ch * 16,
              Bt + (size_t)(bn + row) * K + k0 + ch * 8);
    }
}

__device__ __forceinline__ void gemm_compute_tile(
    const uint32_t* __restrict__ sA, const uint32_t* __restrict__ sB,
    float acc[4][4][4], int warpM, int warpN, int q, int r)
{
#pragma unroll
    for (int ki = 0; ki < 4; ki++) {
        uint32_t afr[4][4];
        uint32_t bfr[4][2];
#pragma unroll
        for (int mi = 0; mi < 4; mi++) {
            const uint32_t* ap = &sA[(warpM + mi * 16 + q) * HSW + ki * 8 + r];
            afr[mi][0] = ap[0];
            afr[mi][1] = ap[8 * HSW];
            afr[mi][2] = ap[4];
            afr[mi][3] = ap[8 * HSW + 4];
        }
#pragma unroll
        for (int ni = 0; ni < 4; ni++) {
            const uint32_t* bp = &sB[(warpN + ni * 8 + q) * HSW + ki * 8 + r];
            bfr[ni][0] = bp[0];
            bfr[ni][1] = bp[4];
        }
#pragma unroll
        for (int mi = 0; mi < 4; mi++)
#pragma unroll
            for (int ni = 0; ni < 4; ni++)
                mma_f16(acc[mi][ni], afr[mi], bfr[ni], acc[mi][ni]);
    }
}

__device__ __forceinline__ void gemm_body(
    const __half* __restrict__ A, const __half* __restrict__ Bt,
    float* __restrict__ C, int N, int K, int bm, int bn)
{
    extern __shared__ __half hsm[];
    __half* sA0 = hsm;
    __half* sB0 = hsm + TILE_H;
    __half* sA1 = hsm + 2 * TILE_H;
    __half* sB1 = hsm + 3 * TILE_H;

    const int tid = threadIdx.x;
    const int lane = tid & 31;
    const int warp = tid >> 5;
    const int q = lane >> 2;
    const int r = lane & 3;
    const int warpM = (warp & 1) * 64;
    const int warpN = (warp >> 1) * 32;

    const uint32_t a0 = (uint32_t)__cvta_generic_to_shared(sA0);
    const uint32_t b0 = (uint32_t)__cvta_generic_to_shared(sB0);
    const uint32_t a1 = (uint32_t)__cvta_generic_to_shared(sA1);
    const uint32_t b1 = (uint32_t)__cvta_generic_to_shared(sB1);

    float acc[4][4][4];
#pragma unroll
    for (int mi = 0; mi < 4; mi++)
#pragma unroll
        for (int ni = 0; ni < 4; ni++)
#pragma unroll
            for (int e = 0; e < 4; e++) acc[mi][ni][e] = 0.f;

    const int T = K / TBK;

    gemm_copy_tile(A, Bt, K, bm, bn, 0, a0, b0, tid);
    cp_commit();

    for (int t = 0; t < T - 1; t++) {
        uint32_t na = (t & 1) ? a0 : a1;
        uint32_t nb = (t & 1) ? b0 : b1;
        const __half* la = (t & 1) ? sA1 : sA0;
        const __half* lb = (t & 1) ? sB1 : sB0;
        gemm_copy_tile(A, Bt, K, bm, bn, (t + 1) * TBK, na, nb, tid);
        cp_commit();
        cp_wait<1>();
        __syncthreads();
        gemm_compute_tile((const uint32_t*)la, (const uint32_t*)lb,
                          acc, warpM, warpN, q, r);
        __syncthreads();
    }
    cp_wait<0>();
    __syncthreads();
    {
        const __half* la = ((T - 1) & 1) ? sA1 : sA0;
        const __half* lb = ((T - 1) & 1) ? sB1 : sB0;
        gemm_compute_tile((const uint32_t*)la, (const uint32_t*)lb,
                          acc, warpM, warpN, q, r);
    }

#pragma unroll
    for (int mi = 0; mi < 4; mi++) {
        int row0 = bm + warpM + mi * 16 + q;
#pragma unroll
        for (int ni = 0; ni < 4; ni++) {
            int col = bn + warpN + ni * 8 + 2 * r;
            *(float2*)(C + (size_t)row0 * N + col) =
                make_float2(acc[mi][ni][0], acc[mi][ni][1]);
            *(float2*)(C + (size_t)(row0 + 8) * N + col) =
                make_float2(acc[mi][ni][2], acc[mi][ni][3]);
        }
    }
}

// Fused Q/K/V projection: grid.x = 12 tiles (8 Q, 2 K, 2 V), grid.y = M/128.
__global__ __launch_bounds__(256)
void gemm_qkv_kernel(const __half* __restrict__ xh,
                     const __half* __restrict__ Wqt,
                     const __half* __restrict__ Wkt,
                     const __half* __restrict__ Wvt,
                     float* __restrict__ qraw,
                     float* __restrict__ kraw,
                     float* __restrict__ vraw)
{
    const int bx = blockIdx.x;
    const int bm = blockIdx.y * TBM;
    const __half* Bt;
    float* C;
    int N, bn;
    if (bx < 8)       { Bt = Wqt; C = qraw; N = 1024; bn = bx * 128; }
    else if (bx < 10) { Bt = Wkt; C = kraw; N = 256;  bn = (bx - 8) * 128; }
    else              { Bt = Wvt; C = vraw; N = 256;  bn = (bx - 10) * 128; }
    gemm_body(xh, Bt, C, N, DD, bm, bn);
}

__global__ __launch_bounds__(256)
void gemm_o_kernel(const __half* __restrict__ A, const __half* __restrict__ Bt,
                   float* __restrict__ C)
{
    gemm_body(A, Bt, C, DD, DD, blockIdx.y * TBM, blockIdx.x * TBN);
}

// ---------------------------------------------------------------------------
// RoPE + transpose kernels (float4-vectorized)
// ---------------------------------------------------------------------------
__global__ void rope_q_kernel(const float* __restrict__ qraw,
                              const float* __restrict__ cosT,
                              const float* __restrict__ sinT,
                              float* __restrict__ qt)
{
    int i = blockIdx.x * blockDim.x + threadIdx.x;
    if (i >= BB * SS * HH * 16) return;
    int d4 = i & 15;
    int h = (i >> 4) & 15;
    int s = (i >> 8) & 2047;
    int b = i >> 19;
    const float4* q4 = (const float4*)qraw;
    float4 v = q4[i];
    float4 rot;
    if (d4 < 8) {
        float4 u = q4[i + 8];
        rot = make_float4(-u.x, -u.y, -u.z, -u.w);
    } else {
        rot = q4[i - 8];
    }
    float4 cs = ((const float4*)cosT)[s * 16 + d4];
    float4 sn = ((const float4*)sinT)[s * 16 + d4];
    float4 o;
    o.x = v.x * cs.x + rot.x * sn.x;
    o.y = v.y * cs.y + rot.y * sn.y;
    o.z = v.z * cs.z + rot.z * sn.z;
    o.w = v.w * cs.w + rot.w * sn.w;
    ((float4*)qt)[(((size_t)(b * HH + h) * SS) + s) * 16 + d4] = o;
}

__global__ void rope_k_kernel(const float* __restrict__ kraw,
                              const float* __restrict__ cosT,
                              const float* __restrict__ sinT,
                              float* __restrict__ kt)
{
    int i = blockIdx.x * blockDim.x + threadIdx.x;
    if (i >= BB * SS * KVH * 16) return;
    int d4 = i & 15;
    int kv = (i >> 4) & 3;
    int s = (i >> 6) & 2047;
    int b = i >> 17;
    const float4* k4 = (const float4*)kraw;
    float4 v = k4[i];
    float4 rot;
    if (d4 < 8) {
        float4 u = k4[i + 8];
        rot = make_float4(-u.x, -u.y, -u.z, -u.w);
    } else {
        rot = k4[i - 8];
    }
    float4 cs = ((const float4*)cosT)[s * 16 + d4];
    float4 sn = ((const float4*)sinT)[s * 16 + d4];
    float4 o;
    o.x = v.x * cs.x + rot.x * sn.x;
    o.y = v.y * cs.y + rot.y * sn.y;
    o.z = v.z * cs.z + rot.z * sn.z;
    o.w = v.w * cs.w + rot.w * sn.w;
    ((float4*)kt)[(((size_t)(b * KVH + kv) * SS) + s) * 16 + d4] = o;
}

__global__ void trans_v_kernel(const float* __restrict__ vraw,
                               float* __restrict__ vt)
{
    int i = blockIdx.x * blockDim.x + threadIdx.x;
    if (i >= BB * SS * KVH * 16) return;
    int d4 = i & 15;
    int kv = (i >> 4) & 3;
    int s = (i >> 6) & 2047;
    int b = i >> 17;
    ((float4*)vt)[(((size_t)(b * KVH + kv) * SS) + s) * 16 + d4] =
        ((const float4*)vraw)[i];
}

// ---------------------------------------------------------------------------
// TF32 MMA flash attention (epilogue writes fp16 for the O-projection)
// ---------------------------------------------------------------------------
#define KS_STRIDE 68
#define VS_STRIDE 72
#define PS_STRIDE 68
#define FLASH_SMEM ((64 * KS_STRIDE + 64 * VS_STRIDE + 64 * PS_STRIDE) * 4)
#define FSC 0.18033688011112042f   // 0.125 * log2(e)

__global__ __launch_bounds__(128)
void flash_mma_kernel(const float* __restrict__ Qt, const float* __restrict__ Kt,
                      const float* __restrict__ Vt, __half* __restrict__ attn)
{
    extern __shared__ uint32_t sm[];
    uint32_t* Ks = sm;
    uint32_t* Vs = sm + 64 * KS_STRIDE;
    uint32_t* Ps = sm + 64 * KS_STRIDE + 64 * VS_STRIDE;

    const int tid = threadIdx.x;
    const int lane = tid & 31;
    const int w = tid >> 5;
    const int q = lane >> 2;
    const int r = lane & 3;

    const int bx = gridDim.x - 1 - blockIdx.x;
    const int bh = blockIdx.y;
    const int b = bh >> 4;
    const int h = bh & 15;
    const int kvh = h >> 2;

    const float* qbase = Qt + ((size_t)bh * SS + bx * 64) * HDIM;
    const float* kbase = Kt + (size_t)(b * KVH + kvh) * SS * HDIM;
    const float* vbase = Vt + (size_t)(b * KVH + kvh) * SS * HDIM;

#pragma unroll
    for (int it = 0; it < 8; it++) {
        int e = tid + it * 128;
        int row = e >> 4;
        int c4 = (e & 15) << 2;
        float4 v = *(const float4*)(qbase + row * HDIM + c4);
        uint4 u;
        u.x = f2tf32(v.x * FSC); u.y = f2tf32(v.y * FSC);
        u.z = f2tf32(v.z * FSC); u.w = f2tf32(v.w * FSC);
        *(uint4*)(Ps + row * PS_STRIDE + c4) = u;
    }
    __syncthreads();

    uint32_t qf[8][4];
#pragma unroll
    for (int ki = 0; ki < 8; ki++) {
        const uint32_t* p = Ps + (w * 16 + q) * PS_STRIDE + ki * 8 + r;
        qf[ki][0] = p[0];
        qf[ki][1] = p[8 * PS_STRIDE];
        qf[ki][2] = p[4];
        qf[ki][3] = p[8 * PS_STRIDE + 4];
    }
    __syncthreads();

    float of[8][4];
#pragma unroll
    for (int nt = 0; nt < 8; nt++)
#pragma unroll
        for (int e = 0; e < 4; e++) of[nt][e] = 0.f;
    float m0 = -INFINITY, m1 = -INFINITY, l0 = 0.f, l1 = 0.f;

    for (int jt = 0; jt <= bx; jt++) {
        __syncthreads();
#pragma unroll
        for (int it = 0; it < 8; it++) {
            int e = tid + it * 128;
            int row = e >> 4;
            int c4 = (e & 15) << 2;
            size_t goff = (size_t)(jt * 64 + row) * HDIM + c4;
            float4 kv = *(const float4*)(kbase + goff);
            uint4 ku;
            ku.x = f2tf32(kv.x); ku.y = f2tf32(kv.y);
            ku.z = f2tf32(kv.z); ku.w = f2tf32(kv.w);
            *(uint4*)(Ks + row * KS_STRIDE + c4) = ku;
            float4 vv = *(const float4*)(vbase + goff);
            uint4 vu;
            vu.x = f2tf32(vv.x); vu.y = f2tf32(vv.y);
            vu.z = f2tf32(vv.z); vu.w = f2tf32(vv.w);
            *(uint4*)(Vs + row * VS_STRIDE + c4) = vu;
        }
        __syncthreads();

        float sf[8][4];
#pragma unroll
        for (int nt = 0; nt < 8; nt++)
#pragma unroll
            for (int e = 0; e < 4; e++) sf[nt][e] = 0.f;
#pragma unroll
        for (int ki = 0; ki < 8; ki++) {
#pragma unroll
            for (int nt = 0; nt < 8; nt++) {
                uint32_t bfr[2];
                const uint32_t* kp = Ks + (nt * 8 + q) * KS_STRIDE + ki * 8 + r;
                bfr[0] = kp[0];
                bfr[1] = kp[4];
                mma_tf32(sf[nt], qf[ki], bfr, sf[nt]);
            }
        }

        if (jt == bx) {
            const int rowA = w * 16 + q;
            const int rowB = rowA + 8;
#pragma unroll
            for (int nt = 0; nt < 8; nt++) {
                int col = nt * 8 + 2 * r;
                if (col     > rowA) sf[nt][0] = -1e30f;
                if (col + 1 > rowA) sf[nt][1] = -1e30f;
                if (col     > rowB) sf[nt][2] = -1e30f;
                if (col + 1 > rowB) sf[nt][3] = -1e30f;
            }
        }

        float mxA = -1e30f, mxB = -1e30f;
#pragma unroll
        for (int nt = 0; nt < 8; nt++) {
            mxA = fmaxf(mxA, fmaxf(sf[nt][0], sf[nt][1]));
            mxB = fmaxf(mxB, fmaxf(sf[nt][2], sf[nt][3]));
        }
        mxA = fmaxf(mxA, __shfl_xor_sync(0xffffffffu, mxA, 1));
        mxA = fmaxf(mxA, __shfl_xor_sync(0xffffffffu, mxA, 2));
        mxB = fmaxf(mxB, __shfl_xor_sync(0xffffffffu, mxB, 1));
        mxB = fmaxf(mxB, __shfl_xor_sync(0xffffffffu, mxB, 2));

        float mn0 = fmaxf(m0, mxA);
        float mn1 = fmaxf(m1, mxB);
        float sc0 = ex2(m0 - mn0);
        float sc1 = ex2(m1 - mn1);
        m0 = mn0; m1 = mn1;

        float rs0 = 0.f, rs1 = 0.f;
        uint32_t* prow = Ps + (w * 16 + q) * PS_STRIDE;
#pragma unroll
        for (int nt = 0; nt < 8; nt++) {
            float p00 = ex2(sf[nt][0] - m0);
            float p01 = ex2(sf[nt][1] - m0);
            float p10 = ex2(sf[nt][2] - m1);
            float p11 = ex2(sf[nt][3] - m1);
            rs0 += p00 + p01;
            rs1 += p10 + p11;
            uint32_t* pp = prow + nt * 8 + 2 * r;
            pp[0] = f2tf32(p00);
            pp[1] = f2tf32(p01);
            pp[8 * PS_STRIDE]     = f2tf32(p10);
            pp[8 * PS_STRIDE + 1] = f2tf32(p11);
        }
        rs0 += __shfl_xor_sync(0xffffffffu, rs0, 1);
        rs0 += __shfl_xor_sync(0xffffffffu, rs0, 2);
        rs1 += __shfl_xor_sync(0xffffffffu, rs1, 1);
        rs1 += __shfl_xor_sync(0xffffffffu, rs1, 2);
        l0 = l0 * sc0 + rs0;
        l1 = l1 * sc1 + rs1;
#pragma unroll
        for (int nt = 0; nt < 8; nt++) {
            of[nt][0] *= sc0; of[nt][1] *= sc0;
            of[nt][2] *= sc1; of[nt][3] *= sc1;
        }
        __syncwarp();

#pragma unroll
        for (int kk = 0; kk < 8; kk++) {
            uint32_t af[4];
            const uint32_t* ap = prow + kk * 8 + r;
            af[0] = ap[0];
            af[1] = ap[8 * PS_STRIDE];
            af[2] = ap[4];
            af[3] = ap[8 * PS_STRIDE + 4];
#pragma unroll
            for (int nt = 0; nt < 8; nt++) {
                uint32_t bfr[2];
                const uint32_t* vp = Vs + (kk * 8 + r) * VS_STRIDE + nt * 8 + q;
                bfr[0] = vp[0];
                bfr[1] = vp[4 * VS_STRIDE];
                mma_tf32(of[nt], af, bfr, of[nt]);
            }
        }
    }

    const float il0 = 1.f / l0;
    const float il1 = 1.f / l1;
    __half* ob = attn + ((size_t)b * SS + bx * 64 + w * 16) * (HH * HDIM) + h * HDIM;
#pragma unroll
    for (int nt = 0; nt < 8; nt++) {
        int col = nt * 8 + 2 * r;
        *(__half2*)(ob + (size_t)q * (HH * HDIM) + col) =
            __floats2half2_rn(of[nt][0] * il0, of[nt][1] * il0);
        *(__half2*)(ob + (size_t)(q + 8) * (HH * HDIM) + col) =
            __floats2half2_rn(of[nt][2] * il1, of[nt][3] * il1);
    }
}

// ---------------------------------------------------------------------------
// Launch
// ---------------------------------------------------------------------------
extern "C" void kernel_launch(void* const* d_in, const int* in_sizes, int n_in,
                              void* d_out, int out_size)
{
    (void)in_sizes; (void)n_in; (void)out_size;
    const float* x    = (const float*)d_in[0];
    const float* cosT = (const float*)d_in[1];
    const float* sinT = (const float*)d_in[2];
    const float* Wq   = (const float*)d_in[3];
    const float* Wk   = (const float*)d_in[4];
    const float* Wv   = (const float*)d_in[5];
    const float* Wo   = (const float*)d_in[6];
    float* out = (float*)d_out;

    static bool attr_set = false;
    if (!attr_set) {
        cudaFuncSetAttribute(flash_mma_kernel,
                             cudaFuncAttributeMaxDynamicSharedMemorySize,
                             FLASH_SMEM);
        cudaFuncSetAttribute(gemm_qkv_kernel,
                             cudaFuncAttributeMaxDynamicSharedMemorySize,
                             GSMEM);
        cudaFuncSetAttribute(gemm_o_kernel,
                             cudaFuncAttributeMaxDynamicSharedMemorySize,
                             GSMEM);
        attr_set = true;
    }

    float *qraw, *kraw, *vraw, *qt, *kt, *vt;
    __half *attn, *xh, *wqt, *wkt, *wvt, *wot;
    cudaGetSymbolAddress((void**)&qraw, g_qraw);
    cudaGetSymbolAddress((void**)&kraw, g_kraw);
    cudaGetSymbolAddress((void**)&vraw, g_vraw);
    cudaGetSymbolAddress((void**)&qt,   g_qt);
    cudaGetSymbolAddress((void**)&kt,   g_kt);
    cudaGetSymbolAddress((void**)&vt,   g_vt);
    cudaGetSymbolAddress((void**)&attn, g_attn);
    cudaGetSymbolAddress((void**)&xh,   g_xh);
    cudaGetSymbolAddress((void**)&wqt,  g_wqt);
    cudaGetSymbolAddress((void**)&wkt,  g_wkt);
    cudaGetSymbolAddress((void**)&wvt,  g_wvt);
    cudaGetSymbolAddress((void**)&wot,  g_wot);

    const int M = BB * SS;   // 4096

    // 0) Prep: x -> fp16; W -> fp16 transposed [N][K]
    conv_x_kernel<<<(M * DD / 4 + 255) / 256, 256>>>(x, xh, M * DD / 4);
    transpose_w_kernel<<<dim3(1024 / 32, 1024 / 32), dim3(32, 8)>>>(Wq, wqt, DD, 1024);
    transpose_w_kernel<<<dim3(256 / 32, 1024 / 32), dim3(32, 8)>>>(Wk, wkt, DD, 256);
    transpose_w_kernel<<<dim3(256 / 32, 1024 / 32), dim3(32, 8)>>>(Wv, wvt, DD, 256);
    transpose_w_kernel<<<dim3(1024 / 32, 1024 / 32), dim3(32, 8)>>>(Wo, wot, DD, 1024);

    // 1) Fused Q/K/V projections (fp16 MMA)
    gemm_qkv_kernel<<<dim3(12, M / TBM), 256, GSMEM>>>(xh, wqt, wkt, wvt,
                                                       qraw, kraw, vraw);

    // 2) RoPE + transpose (float4)
    rope_q_kernel<<<(BB * SS * HH * 16 + 255) / 256, 256>>>(qraw, cosT, sinT, qt);
    rope_k_kernel<<<(BB * SS * KVH * 16 + 255) / 256, 256>>>(kraw, cosT, sinT, kt);
    trans_v_kernel<<<(BB * SS * KVH * 16 + 255) / 256, 256>>>(vraw, vt);

    // 3) Causal GQA attention (TF32 MMA flash; fp16 output)
    flash_mma_kernel<<<dim3(SS / 64, BB * HH), 128, FLASH_SMEM>>>(qt, kt, vt, attn);

    // 4) Output projection (fp16 MMA)
    gemm_o_kernel<<<dim3(DD / TBN, M / TBM), 256, GSMEM>>>(attn, wot, out);
}

// round 9
// speedup vs baseline: 9.1489x; 1.4390x over previous
#include <cuda_runtime.h>
#include <cuda_fp16.h>
#include <math.h>
#include <stdint.h>

// Problem constants
#define BB 2
#define SS 2048
#define DD 1024
#define HH 16
#define KVH 4
#define HDIM 64
#define NREP (HH / KVH)   // 4

// Scratch (allocation-free: __device__ globals)
__device__ float  g_qraw[BB * SS * HH * HDIM];
__device__ float  g_kraw[BB * SS * KVH * HDIM];
__device__ float  g_vraw[BB * SS * KVH * HDIM];
__device__ __half g_qt[BB * HH * SS * HDIM];    // roped Q, fp16, pre-scaled by FSC
__device__ __half g_kt[BB * KVH * SS * HDIM];   // roped K, fp16
__device__ __half g_vtT[BB * KVH * HDIM * SS];  // V^T fp16: [b][kv][d][s]
__device__ __half g_attn[BB * SS * HH * HDIM];  // attention out, fp16
__device__ __half g_xh[BB * SS * DD];           // x fp16 [M][K]
__device__ __half g_wqt[DD * DD];               // Wq^T fp16 [N][K]
__device__ __half g_wkt[256 * DD];
__device__ __half g_wvt[256 * DD];
__device__ __half g_wot[DD * DD];

#define FSC 0.18033688011112042f   // 0.125 * log2(e)

__device__ __forceinline__ float ex2(float x) {
    float y;
    asm("ex2.approx.ftz.f32 %0, %1;" : "=f"(y) : "f"(x));
    return y;
}
__device__ __forceinline__ void mma_f16(float d[4], const uint32_t a[4],
                                        const uint32_t b[2], const float c[4]) {
    asm volatile(
        "mma.sync.aligned.m16n8k16.row.col.f32.f16.f16.f32 "
        "{%0,%1,%2,%3}, {%4,%5,%6,%7}, {%8,%9}, {%10,%11,%12,%13};"
        : "=f"(d[0]), "=f"(d[1]), "=f"(d[2]), "=f"(d[3])
        : "r"(a[0]), "r"(a[1]), "r"(a[2]), "r"(a[3]),
          "r"(b[0]), "r"(b[1]),
          "f"(c[0]), "f"(c[1]), "f"(c[2]), "f"(c[3]));
}

__device__ __forceinline__ void cpa16(uint32_t dst, const void* src) {
    asm volatile("cp.async.ca.shared.global [%0], [%1], 16;"
                 :: "r"(dst), "l"(src));
}
__device__ __forceinline__ void cp_commit() {
    asm volatile("cp.async.commit_group;" ::: "memory");
}
template <int N>
__device__ __forceinline__ void cp_wait() {
    asm volatile("cp.async.wait_group %0;" :: "n"(N) : "memory");
}

// ---------------------------------------------------------------------------
// Prep: x -> fp16; all four W -> fp16 transposed [N][K] (one kernel)
// ---------------------------------------------------------------------------
__global__ void conv_x_kernel(const float* __restrict__ x,
                              __half* __restrict__ xh, int n4)
{
    int i = blockIdx.x * blockDim.x + threadIdx.x;
    if (i >= n4) return;
    float4 v = ((const float4*)x)[i];
    __half2* o = (__half2*)xh;
    o[2 * i]     = __floats2half2_rn(v.x, v.y);
    o[2 * i + 1] = __floats2half2_rn(v.z, v.w);
}

// 32x32 tile transpose, W[K][N] float -> Wt[N][K] half.
// block ids: [0,1024) Wq, [1024,1280) Wk, [1280,1536) Wv, [1536,2560) Wo
__global__ void prep_w_kernel(const float* __restrict__ Wq,
                              const float* __restrict__ Wk,
                              const float* __restrict__ Wv,
                              const float* __restrict__ Wo,
                              __half* __restrict__ wqt,
                              __half* __restrict__ wkt,
                              __half* __restrict__ wvt,
                              __half* __restrict__ wot)
{
    __shared__ float tile[32][33];
    int bid = blockIdx.x;
    const float* W;
    __half* Wt;
    int N, n_t, k_t;
    if (bid < 1024)      { W = Wq; Wt = wqt; N = 1024; n_t = bid & 31; k_t = bid >> 5; }
    else if (bid < 1280) { W = Wk; Wt = wkt; N = 256;  bid -= 1024; n_t = bid & 7; k_t = bid >> 3; }
    else if (bid < 1536) { W = Wv; Wt = wvt; N = 256;  bid -= 1280; n_t = bid & 7; k_t = bid >> 3; }
    else                 { W = Wo; Wt = wot; N = 1024; bid -= 1536; n_t = bid & 31; k_t = bid >> 5; }
    const int n0 = n_t * 32, k0 = k_t * 32;
    const int tx = threadIdx.x;
#pragma unroll
    for (int ty = threadIdx.y; ty < 32; ty += 8)
        tile[ty][tx] = W[(size_t)(k0 + ty) * N + n0 + tx];
    __syncthreads();
#pragma unroll
    for (int ty = threadIdx.y; ty < 32; ty += 8)
        Wt[(size_t)(n0 + ty) * DD + k0 + tx] = __float2half_rn(tile[tx][ty]);
}

// ---------------------------------------------------------------------------
// fp16 tensor-core GEMM (unchanged from R8): C[M,N] = A[M,K] @ Bt[N,K]^T
// ---------------------------------------------------------------------------
#define TBM 128
#define TBN 128
#define TBK 64
#define HS 72
#define HSW 36
#define TILE_H (128 * HS)
#define STAGE_B (TILE_H * 2 * 2)
#define GSMEM (STAGE_B * 2)

__device__ __forceinline__ void gemm_copy_tile(
    const __half* __restrict__ A, const __half* __restrict__ Bt,
    int K, int bm, int bn, int k0,
    uint32_t abase, uint32_t bbase, int tid)
{
#pragma unroll
    for (int i = 0; i < 4; i++) {
        int e = tid + i * 256;
        int row = e >> 3;
        int ch = e & 7;
        cpa16(abase + row * (HS * 2) + ch * 16,
              A + (size_t)(bm + row) * K + k0 + ch * 8);
    }
#pragma unroll
    for (int i = 0; i < 4; i++) {
        int e = tid + i * 256;
        int row = e >> 3;
        int ch = e & 7;
        cpa16(bbase + row * (HS * 2) + ch * 16,
              Bt + (size_t)(bn + row) * K + k0 + ch * 8);
    }
}

__device__ __forceinline__ void gemm_compute_tile(
    const uint32_t* __restrict__ sA, const uint32_t* __restrict__ sB,
    float acc[4][4][4], int warpM, int warpN, int q, int r)
{
#pragma unroll
    for (int ki = 0; ki < 4; ki++) {
        uint32_t afr[4][4];
        uint32_t bfr[4][2];
#pragma unroll
        for (int mi = 0; mi < 4; mi++) {
            const uint32_t* ap = &sA[(warpM + mi * 16 + q) * HSW + ki * 8 + r];
            afr[mi][0] = ap[0];
            afr[mi][1] = ap[8 * HSW];
            afr[mi][2] = ap[4];
            afr[mi][3] = ap[8 * HSW + 4];
        }
#pragma unroll
        for (int ni = 0; ni < 4; ni++) {
            const uint32_t* bp = &sB[(warpN + ni * 8 + q) * HSW + ki * 8 + r];
            bfr[ni][0] = bp[0];
            bfr[ni][1] = bp[4];
        }
#pragma unroll
        for (int mi = 0; mi < 4; mi++)
#pragma unroll
            for (int ni = 0; ni < 4; ni++)
                mma_f16(acc[mi][ni], afr[mi], bfr[ni], acc[mi][ni]);
    }
}

__device__ __forceinline__ void gemm_body(
    const __half* __restrict__ A, const __half* __restrict__ Bt,
    float* __restrict__ C, int N, int K, int bm, int bn)
{
    extern __shared__ __half hsm[];
    __half* sA0 = hsm;
    __half* sB0 = hsm + TILE_H;
    __half* sA1 = hsm + 2 * TILE_H;
    __half* sB1 = hsm + 3 * TILE_H;

    const int tid = threadIdx.x;
    const int lane = tid & 31;
    const int warp = tid >> 5;
    const int q = lane >> 2;
    const int r = lane & 3;
    const int warpM = (warp & 1) * 64;
    const int warpN = (warp >> 1) * 32;

    const uint32_t a0 = (uint32_t)__cvta_generic_to_shared(sA0);
    const uint32_t b0 = (uint32_t)__cvta_generic_to_shared(sB0);
    const uint32_t a1 = (uint32_t)__cvta_generic_to_shared(sA1);
    const uint32_t b1 = (uint32_t)__cvta_generic_to_shared(sB1);

    float acc[4][4][4];
#pragma unroll
    for (int mi = 0; mi < 4; mi++)
#pragma unroll
        for (int ni = 0; ni < 4; ni++)
#pragma unroll
            for (int e = 0; e < 4; e++) acc[mi][ni][e] = 0.f;

    const int T = K / TBK;

    gemm_copy_tile(A, Bt, K, bm, bn, 0, a0, b0, tid);
    cp_commit();

    for (int t = 0; t < T - 1; t++) {
        uint32_t na = (t & 1) ? a0 : a1;
        uint32_t nb = (t & 1) ? b0 : b1;
        const __half* la = (t & 1) ? sA1 : sA0;
        const __half* lb = (t & 1) ? sB1 : sB0;
        gemm_copy_tile(A, Bt, K, bm, bn, (t + 1) * TBK, na, nb, tid);
        cp_commit();
        cp_wait<1>();
        __syncthreads();
        gemm_compute_tile((const uint32_t*)la, (const uint32_t*)lb,
                          acc, warpM, warpN, q, r);
        __syncthreads();
    }
    cp_wait<0>();
    __syncthreads();
    {
        const __half* la = ((T - 1) & 1) ? sA1 : sA0;
        const __half* lb = ((T - 1) & 1) ? sB1 : sB0;
        gemm_compute_tile((const uint32_t*)la, (const uint32_t*)lb,
                          acc, warpM, warpN, q, r);
    }

#pragma unroll
    for (int mi = 0; mi < 4; mi++) {
        int row0 = bm + warpM + mi * 16 + q;
#pragma unroll
        for (int ni = 0; ni < 4; ni++) {
            int col = bn + warpN + ni * 8 + 2 * r;
            *(float2*)(C + (size_t)row0 * N + col) =
                make_float2(acc[mi][ni][0], acc[mi][ni][1]);
            *(float2*)(C + (size_t)(row0 + 8) * N + col) =
                make_float2(acc[mi][ni][2], acc[mi][ni][3]);
        }
    }
}

__global__ __launch_bounds__(256)
void gemm_qkv_kernel(const __half* __restrict__ xh,
                     const __half* __restrict__ Wqt,
                     const __half* __restrict__ Wkt,
                     const __half* __restrict__ Wvt,
                     float* __restrict__ qraw,
                     float* __restrict__ kraw,
                     float* __restrict__ vraw)
{
    const int bx = blockIdx.x;
    const int bm = blockIdx.y * TBM;
    const __half* Bt;
    float* C;
    int N, bn;
    if (bx < 8)       { Bt = Wqt; C = qraw; N = 1024; bn = bx * 128; }
    else if (bx < 10) { Bt = Wkt; C = kraw; N = 256;  bn = (bx - 8) * 128; }
    else              { Bt = Wvt; C = vraw; N = 256;  bn = (bx - 10) * 128; }
    gemm_body(xh, Bt, C, N, DD, bm, bn);
}

__global__ __launch_bounds__(256)
void gemm_o_kernel(const __half* __restrict__ A, const __half* __restrict__ Bt,
                   float* __restrict__ C)
{
    gemm_body(A, Bt, C, DD, DD, blockIdx.y * TBM, blockIdx.x * TBN);
}

// ---------------------------------------------------------------------------
// RoPE kernels -> fp16 outputs. rope_q folds FSC (softmax scale * log2e).
// ---------------------------------------------------------------------------
__global__ void rope_q_kernel(const float* __restrict__ qraw,
                              const float* __restrict__ cosT,
                              const float* __restrict__ sinT,
                              __half* __restrict__ qt)
{
    int i = blockIdx.x * blockDim.x + threadIdx.x;   // float4 index
    if (i >= BB * SS * HH * 16) return;
    int d4 = i & 15;
    int h = (i >> 4) & 15;
    int s = (i >> 8) & 2047;
    int b = i >> 19;
    const float4* q4 = (const float4*)qraw;
    float4 v = q4[i];
    float4 rot;
    if (d4 < 8) {
        float4 u = q4[i + 8];
        rot = make_float4(-u.x, -u.y, -u.z, -u.w);
    } else {
        rot = q4[i - 8];
    }
    float4 cs = ((const float4*)cosT)[s * 16 + d4];
    float4 sn = ((const float4*)sinT)[s * 16 + d4];
    float ox = (v.x * cs.x + rot.x * sn.x) * FSC;
    float oy = (v.y * cs.y + rot.y * sn.y) * FSC;
    float oz = (v.z * cs.z + rot.z * sn.z) * FSC;
    float ow = (v.w * cs.w + rot.w * sn.w) * FSC;
    __half2* dst = (__half2*)(qt + ((((size_t)(b * HH + h) * SS) + s) * HDIM + d4 * 4));
    dst[0] = __floats2half2_rn(ox, oy);
    dst[1] = __floats2half2_rn(oz, ow);
}

__global__ void rope_k_kernel(const float* __restrict__ kraw,
                              const float* __restrict__ cosT,
                              const float* __restrict__ sinT,
                              __half* __restrict__ kt)
{
    int i = blockIdx.x * blockDim.x + threadIdx.x;
    if (i >= BB * SS * KVH * 16) return;
    int d4 = i & 15;
    int kv = (i >> 4) & 3;
    int s = (i >> 6) & 2047;
    int b = i >> 17;
    const float4* k4 = (const float4*)kraw;
    float4 v = k4[i];
    float4 rot;
    if (d4 < 8) {
        float4 u = k4[i + 8];
        rot = make_float4(-u.x, -u.y, -u.z, -u.w);
    } else {
        rot = k4[i - 8];
    }
    float4 cs = ((const float4*)cosT)[s * 16 + d4];
    float4 sn = ((const float4*)sinT)[s * 16 + d4];
    float ox = v.x * cs.x + rot.x * sn.x;
    float oy = v.y * cs.y + rot.y * sn.y;
    float oz = v.z * cs.z + rot.z * sn.z;
    float ow = v.w * cs.w + rot.w * sn.w;
    __half2* dst = (__half2*)(kt + ((((size_t)(b * KVH + kv) * SS) + s) * HDIM + d4 * 4));
    dst[0] = __floats2half2_rn(ox, oy);
    dst[1] = __floats2half2_rn(oz, ow);
}

// V transpose: vraw (b,s,kv,d) fp32 -> vtT (b,kv,d,s) fp16
__global__ void vtrans_kernel(const float* __restrict__ vraw,
                              __half* __restrict__ vtT)
{
    __shared__ float tile[32][33];
    const int s0 = blockIdx.x * 32;
    const int d0 = (blockIdx.y & 1) * 32;
    const int bkv = blockIdx.y >> 1;      // 0..7  (b*KVH+kv)
    const int b = bkv >> 2;
    const int kv = bkv & 3;
    const int tx = threadIdx.x;
#pragma unroll
    for (int ty = threadIdx.y; ty < 32; ty += 8)
        tile[ty][tx] = vraw[(((size_t)(b * SS + s0 + ty)) * KVH + kv) * HDIM + d0 + tx];
    __syncthreads();
#pragma unroll
    for (int ty = threadIdx.y; ty < 32; ty += 8)
        vtT[((size_t)bkv * HDIM + d0 + ty) * SS + s0 + tx] =
            __float2half_rn(tile[tx][ty]);
}

// ---------------------------------------------------------------------------
// fp16 MMA flash attention, causal, GQA.
// CTA: 128 threads (4 warps), 64 queries; 64-key tiles; HD=64.
// K smem [key][dim], V smem [dim][key] (from V^T), P smem [row][key].
// All fp16, stride 72 halves -> fragment bank = 4q+r, conflict-free.
// m16n8k16: 32 MMAs QK + 32 MMAs PV per tile.
// ---------------------------------------------------------------------------
__global__ __launch_bounds__(128)
void flash_mma_kernel(const __half* __restrict__ Qt, const __half* __restrict__ Kt,
                      const __half* __restrict__ VtT, __half* __restrict__ attn)
{
    __shared__ __align__(16) __half Ks[64 * HS];
    __shared__ __align__(16) __half Vs[64 * HS];
    __shared__ __align__(16) __half Ps[64 * HS];

    const int tid = threadIdx.x;
    const int lane = tid & 31;
    const int w = tid >> 5;
    const int q = lane >> 2;
    const int r = lane & 3;

    const int bx = gridDim.x - 1 - blockIdx.x;   // long CTAs first
    const int bh = blockIdx.y;
    const int b = bh >> 4;
    const int h = bh & 15;
    const int kvh = h >> 2;

    const __half* qbase = Qt + ((size_t)bh * SS + bx * 64) * HDIM;
    const __half* kbase = Kt + (size_t)(b * KVH + kvh) * SS * HDIM;
    const __half* vbase = VtT + (size_t)(b * KVH + kvh) * HDIM * SS;

    // Stage Q tile (64x64 halves) into Ps
#pragma unroll
    for (int it = 0; it < 4; it++) {
        int e = tid + it * 128;
        int row = e >> 3;
        int ch = e & 7;
        *(uint4*)(Ps + row * HS + ch * 8) =
            *(const uint4*)(qbase + row * HDIM + ch * 8);
    }
    __syncthreads();

    // Q fragments (each warp its 16 rows); 4 k16-steps
    uint32_t qf[4][4];
    {
        const uint32_t* Pw = (const uint32_t*)Ps;
#pragma unroll
        for (int ki = 0; ki < 4; ki++) {
            const uint32_t* p = Pw + (w * 16 + q) * HSW + ki * 8 + r;
            qf[ki][0] = p[0];
            qf[ki][1] = p[8 * HSW];
            qf[ki][2] = p[4];
            qf[ki][3] = p[8 * HSW + 4];
        }
    }
    __syncthreads();   // done reading Q staging before P overwrites

    float of[8][4];
#pragma unroll
    for (int nt = 0; nt < 8; nt++)
#pragma unroll
        for (int e = 0; e < 4; e++) of[nt][e] = 0.f;
    float m0 = -INFINITY, m1 = -INFINITY, l0 = 0.f, l1 = 0.f;

    for (int jt = 0; jt <= bx; jt++) {
        __syncthreads();
        // Load K tile [key][dim] and V tile [dim][key]
#pragma unroll
        for (int it = 0; it < 4; it++) {
            int e = tid + it * 128;
            int row = e >> 3;
            int ch = e & 7;
            *(uint4*)(Ks + row * HS + ch * 8) =
                *(const uint4*)(kbase + (size_t)(jt * 64 + row) * HDIM + ch * 8);
            *(uint4*)(Vs + row * HS + ch * 8) =
                *(const uint4*)(vbase + (size_t)row * SS + jt * 64 + ch * 8);
        }
        __syncthreads();

        // S = Q @ K^T (exp2 domain; Q pre-scaled)
        float sf[8][4];
#pragma unroll
        for (int nt = 0; nt < 8; nt++)
#pragma unroll
            for (int e = 0; e < 4; e++) sf[nt][e] = 0.f;
        {
            const uint32_t* Kw = (const uint32_t*)Ks;
#pragma unroll
            for (int ki = 0; ki < 4; ki++) {
#pragma unroll
                for (int nt = 0; nt < 8; nt++) {
                    uint32_t bfr[2];
                    const uint32_t* kp = Kw + (nt * 8 + q) * HSW + ki * 8 + r;
                    bfr[0] = kp[0];
                    bfr[1] = kp[4];
                    mma_f16(sf[nt], qf[ki], bfr, sf[nt]);
                }
            }
        }

        // Causal mask on diagonal tile
        if (jt == bx) {
            const int rowA = w * 16 + q;
            const int rowB = rowA + 8;
#pragma unroll
            for (int nt = 0; nt < 8; nt++) {
                int col = nt * 8 + 2 * r;
                if (col     > rowA) sf[nt][0] = -1e30f;
                if (col + 1 > rowA) sf[nt][1] = -1e30f;
                if (col     > rowB) sf[nt][2] = -1e30f;
                if (col + 1 > rowB) sf[nt][3] = -1e30f;
            }
        }

        // Online softmax (rows q and q+8)
        float mxA = -1e30f, mxB = -1e30f;
#pragma unroll
        for (int nt = 0; nt < 8; nt++) {
            mxA = fmaxf(mxA, fmaxf(sf[nt][0], sf[nt][1]));
            mxB = fmaxf(mxB, fmaxf(sf[nt][2], sf[nt][3]));
        }
        mxA = fmaxf(mxA, __shfl_xor_sync(0xffffffffu, mxA, 1));
        mxA = fmaxf(mxA, __shfl_xor_sync(0xffffffffu, mxA, 2));
        mxB = fmaxf(mxB, __shfl_xor_sync(0xffffffffu, mxB, 1));
        mxB = fmaxf(mxB, __shfl_xor_sync(0xffffffffu, mxB, 2));

        float mn0 = fmaxf(m0, mxA);
        float mn1 = fmaxf(m1, mxB);
        float sc0 = ex2(m0 - mn0);
        float sc1 = ex2(m1 - mn1);
        m0 = mn0; m1 = mn1;

        float rs0 = 0.f, rs1 = 0.f;
        __half* prow = Ps + (w * 16 + q) * HS;
#pragma unroll
        for (int nt = 0; nt < 8; nt++) {
            float p00 = ex2(sf[nt][0] - m0);
            float p01 = ex2(sf[nt][1] - m0);
            float p10 = ex2(sf[nt][2] - m1);
            float p11 = ex2(sf[nt][3] - m1);
            rs0 += p00 + p01;
            rs1 += p10 + p11;
            *(__half2*)(prow + nt * 8 + 2 * r) = __floats2half2_rn(p00, p01);
            *(__half2*)(prow + 8 * HS + nt * 8 + 2 * r) = __floats2half2_rn(p10, p11);
        }
        rs0 += __shfl_xor_sync(0xffffffffu, rs0, 1);
        rs0 += __shfl_xor_sync(0xffffffffu, rs0, 2);
        rs1 += __shfl_xor_sync(0xffffffffu, rs1, 1);
        rs1 += __shfl_xor_sync(0xffffffffu, rs1, 2);
        l0 = l0 * sc0 + rs0;
        l1 = l1 * sc1 + rs1;
#pragma unroll
        for (int nt = 0; nt < 8; nt++) {
            of[nt][0] *= sc0; of[nt][1] *= sc0;
            of[nt][2] *= sc1; of[nt][3] *= sc1;
        }
        __syncwarp();

        // O += P @ V   (A = P [16 x 64keys], B = V [keys x dims] via Vs[dim][key])
        {
            const uint32_t* prw = (const uint32_t*)Ps + (w * 16 + q) * HSW;
            const uint32_t* Vw = (const uint32_t*)Vs;
#pragma unroll
            for (int kk = 0; kk < 4; kk++) {
                uint32_t af[4];
                af[0] = prw[kk * 8 + r];
                af[1] = prw[8 * HSW + kk * 8 + r];
                af[2] = prw[kk * 8 + 4 + r];
                af[3] = prw[8 * HSW + kk * 8 + 4 + r];
#pragma unroll
                for (int nt = 0; nt < 8; nt++) {
                    uint32_t bfr[2];
                    const uint32_t* vp = Vw + (nt * 8 + q) * HSW + kk * 8 + r;
                    bfr[0] = vp[0];
                    bfr[1] = vp[4];
                    mma_f16(of[nt], af, bfr, of[nt]);
                }
            }
        }
    }

    // Normalize + store fp16 to (b, s, h*64+d)
    const float il0 = 1.f / l0;
    const float il1 = 1.f / l1;
    __half* ob = attn + ((size_t)b * SS + bx * 64 + w * 16) * (HH * HDIM) + h * HDIM;
#pragma unroll
    for (int nt = 0; nt < 8; nt++) {
        int col = nt * 8 + 2 * r;
        *(__half2*)(ob + (size_t)q * (HH * HDIM) + col) =
            __floats2half2_rn(of[nt][0] * il0, of[nt][1] * il0);
        *(__half2*)(ob + (size_t)(q + 8) * (HH * HDIM) + col) =
            __floats2half2_rn(of[nt][2] * il1, of[nt][3] * il1);
    }
}

// ---------------------------------------------------------------------------
// Launch
// ---------------------------------------------------------------------------
extern "C" void kernel_launch(void* const* d_in, const int* in_sizes, int n_in,
                              void* d_out, int out_size)
{
    (void)in_sizes; (void)n_in; (void)out_size;
    const float* x    = (const float*)d_in[0];
    const float* cosT = (const float*)d_in[1];
    const float* sinT = (const float*)d_in[2];
    const float* Wq   = (const float*)d_in[3];
    const float* Wk   = (const float*)d_in[4];
    const float* Wv   = (const float*)d_in[5];
    const float* Wo   = (const float*)d_in[6];
    float* out = (float*)d_out;

    static bool attr_set = false;
    if (!attr_set) {
        cudaFuncSetAttribute(gemm_qkv_kernel,
                             cudaFuncAttributeMaxDynamicSharedMemorySize, GSMEM);
        cudaFuncSetAttribute(gemm_o_kernel,
                             cudaFuncAttributeMaxDynamicSharedMemorySize, GSMEM);
        attr_set = true;
    }

    float *qraw, *kraw, *vraw;
    __half *qt, *kt, *vtT, *attn, *xh, *wqt, *wkt, *wvt, *wot;
    cudaGetSymbolAddress((void**)&qraw, g_qraw);
    cudaGetSymbolAddress((void**)&kraw, g_kraw);
    cudaGetSymbolAddress((void**)&vraw, g_vraw);
    cudaGetSymbolAddress((void**)&qt,   g_qt);
    cudaGetSymbolAddress((void**)&kt,   g_kt);
    cudaGetSymbolAddress((void**)&vtT,  g_vtT);
    cudaGetSymbolAddress((void**)&attn, g_attn);
    cudaGetSymbolAddress((void**)&xh,   g_xh);
    cudaGetSymbolAddress((void**)&wqt,  g_wqt);
    cudaGetSymbolAddress((void**)&wkt,  g_wkt);
    cudaGetSymbolAddress((void**)&wvt,  g_wvt);
    cudaGetSymbolAddress((void**)&wot,  g_wot);

    const int M = BB * SS;   // 4096

    // 0) Prep
    conv_x_kernel<<<(M * DD / 4 + 255) / 256, 256>>>(x, xh, M * DD / 4);
    prep_w_kernel<<<2560, dim3(32, 8)>>>(Wq, Wk, Wv, Wo, wqt, wkt, wvt, wot);

    // 1) Fused Q/K/V projections (fp16 MMA)
    gemm_qkv_kernel<<<dim3(12, M / TBM), 256, GSMEM>>>(xh, wqt, wkt, wvt,
                                                       qraw, kraw, vraw);

    // 2) RoPE (fp16 out, FSC folded into Q) + V transpose (fp16 [d][s])
    rope_q_kernel<<<(BB * SS * HH * 16 + 255) / 256, 256>>>(qraw, cosT, sinT, qt);
    rope_k_kernel<<<(BB * SS * KVH * 16 + 255) / 256, 256>>>(kraw, cosT, sinT, kt);
    vtrans_kernel<<<dim3(SS / 32, 2 * BB * KVH), dim3(32, 8)>>>(vraw, vtT);

    // 3) Causal GQA attention (fp16 MMA flash)
    flash_mma_kernel<<<dim3(SS / 64, BB * HH), 128>>>(qt, kt, vtT, attn);

    // 4) Output projection (fp16 MMA)
    gemm_o_kernel<<<dim3(DD / TBN, M / TBM), 256, GSMEM>>>(attn, wot, out);
}

// round 10
// speedup vs baseline: 9.3619x; 1.0233x over previous
#include <cuda_runtime.h>
#include <cuda_fp16.h>
#include <math.h>
#include <stdint.h>

// Problem constants
#define BB 2
#define SS 2048
#define DD 1024
#define HH 16
#define KVH 4
#define HDIM 64
#define NREP (HH / KVH)   // 4

// Scratch (allocation-free: __device__ globals)
__device__ float  g_qraw[BB * SS * HH * HDIM];
__device__ float  g_kraw[BB * SS * KVH * HDIM];
__device__ float  g_vraw[BB * SS * KVH * HDIM];
__device__ __half g_qt[BB * HH * SS * HDIM];    // roped Q, fp16, pre-scaled by FSC
__device__ __half g_kt[BB * KVH * SS * HDIM];   // roped K, fp16
__device__ __half g_vtT[BB * KVH * HDIM * SS];  // V^T fp16: [b][kv][d][s]
__device__ __half g_attn[BB * SS * HH * HDIM];  // attention out, fp16
__device__ __half g_xh[BB * SS * DD];           // x fp16 [M][K]
__device__ __half g_wqt[DD * DD];               // Wq^T fp16 [N][K]
__device__ __half g_wkt[256 * DD];
__device__ __half g_wvt[256 * DD];
__device__ __half g_wot[DD * DD];

#define FSC 0.18033688011112042f   // 0.125 * log2(e)

__device__ __forceinline__ float ex2(float x) {
    float y;
    asm("ex2.approx.ftz.f32 %0, %1;" : "=f"(y) : "f"(x));
    return y;
}
__device__ __forceinline__ void mma_f16(float d[4], const uint32_t a[4],
                                        const uint32_t b[2], const float c[4]) {
    asm volatile(
        "mma.sync.aligned.m16n8k16.row.col.f32.f16.f16.f32 "
        "{%0,%1,%2,%3}, {%4,%5,%6,%7}, {%8,%9}, {%10,%11,%12,%13};"
        : "=f"(d[0]), "=f"(d[1]), "=f"(d[2]), "=f"(d[3])
        : "r"(a[0]), "r"(a[1]), "r"(a[2]), "r"(a[3]),
          "r"(b[0]), "r"(b[1]),
          "f"(c[0]), "f"(c[1]), "f"(c[2]), "f"(c[3]));
}
__device__ __forceinline__ void ldsm_x4(uint32_t& r0, uint32_t& r1,
                                        uint32_t& r2, uint32_t& r3, uint32_t addr) {
    asm volatile("ldmatrix.sync.aligned.m8n8.x4.shared.b16 {%0,%1,%2,%3}, [%4];"
                 : "=r"(r0), "=r"(r1), "=r"(r2), "=r"(r3) : "r"(addr));
}
__device__ __forceinline__ void cpa16(uint32_t dst, const void* src) {
    asm volatile("cp.async.ca.shared.global [%0], [%1], 16;"
                 :: "r"(dst), "l"(src));
}
__device__ __forceinline__ void cp_commit() {
    asm volatile("cp.async.commit_group;" ::: "memory");
}
template <int N>
__device__ __forceinline__ void cp_wait() {
    asm volatile("cp.async.wait_group %0;" :: "n"(N) : "memory");
}

// ---------------------------------------------------------------------------
// Prep: x -> fp16; all four W -> fp16 transposed [N][K] (one kernel)
// ---------------------------------------------------------------------------
__global__ void conv_x_kernel(const float* __restrict__ x,
                              __half* __restrict__ xh, int n4)
{
    int i = blockIdx.x * blockDim.x + threadIdx.x;
    if (i >= n4) return;
    float4 v = ((const float4*)x)[i];
    __half2* o = (__half2*)xh;
    o[2 * i]     = __floats2half2_rn(v.x, v.y);
    o[2 * i + 1] = __floats2half2_rn(v.z, v.w);
}

__global__ void prep_w_kernel(const float* __restrict__ Wq,
                              const float* __restrict__ Wk,
                              const float* __restrict__ Wv,
                              const float* __restrict__ Wo,
                              __half* __restrict__ wqt,
                              __half* __restrict__ wkt,
                              __half* __restrict__ wvt,
                              __half* __restrict__ wot)
{
    __shared__ float tile[32][33];
    int bid = blockIdx.x;
    const float* W;
    __half* Wt;
    int N, n_t, k_t;
    if (bid < 1024)      { W = Wq; Wt = wqt; N = 1024; n_t = bid & 31; k_t = bid >> 5; }
    else if (bid < 1280) { W = Wk; Wt = wkt; N = 256;  bid -= 1024; n_t = bid & 7; k_t = bid >> 3; }
    else if (bid < 1536) { W = Wv; Wt = wvt; N = 256;  bid -= 1280; n_t = bid & 7; k_t = bid >> 3; }
    else                 { W = Wo; Wt = wot; N = 1024; bid -= 1536; n_t = bid & 31; k_t = bid >> 5; }
    const int n0 = n_t * 32, k0 = k_t * 32;
    const int tx = threadIdx.x;
#pragma unroll
    for (int ty = threadIdx.y; ty < 32; ty += 8)
        tile[ty][tx] = W[(size_t)(k0 + ty) * N + n0 + tx];
    __syncthreads();
#pragma unroll
    for (int ty = threadIdx.y; ty < 32; ty += 8)
        Wt[(size_t)(n0 + ty) * DD + k0 + tx] = __float2half_rn(tile[tx][ty]);
}

// ---------------------------------------------------------------------------
// fp16 ldmatrix GEMM: C[M,N] = A[M,K] @ Bt[N,K]^T, C fp32.
// CTA 128x128, 128 threads (4 warps 2x2), warp tile 64x64, BK=64.
// Smem: row-major 64 halves (128B) per row, SW128 chunk swizzle
// (chunk' = chunk ^ (row & 7)) -> conflict-free cp.async AND ldmatrix.
// Per k16: 8 ldmatrix.x4 feed 32 HMMA.16816.
// ---------------------------------------------------------------------------
#define XTILE_B 16384                 // bytes per operand tile (128 x 128B)
#define XSTAGE_B (XTILE_B * 2)        // A+B per stage
#define XGSMEM (XSTAGE_B * 2)         // 2 stages = 64 KB

__device__ __forceinline__ void xgemm_copy_tile(
    const __half* __restrict__ A, const __half* __restrict__ Bt,
    int K, int bm, int bn, int k0,
    uint32_t abase, uint32_t bbase, int tid)
{
#pragma unroll
    for (int i = 0; i < 8; i++) {
        int e = tid + i * 128;
        int row = e >> 3;
        int ch = e & 7;
        int sch = ch ^ (row & 7);
        cpa16(abase + row * 128 + sch * 16,
              A + (size_t)(bm + row) * K + k0 + ch * 8);
    }
#pragma unroll
    for (int i = 0; i < 8; i++) {
        int e = tid + i * 128;
        int row = e >> 3;
        int ch = e & 7;
        int sch = ch ^ (row & 7);
        cpa16(bbase + row * 128 + sch * 16,
              Bt + (size_t)(bn + row) * K + k0 + ch * 8);
    }
}

__device__ __forceinline__ void xgemm_compute_tile(
    uint32_t abase, uint32_t bbase, float acc[4][8][4],
    int warpM, int warpN, int lane)
{
    const int lrow = lane & 15;      // row within 16-row group
    const int lhi = lane >> 4;       // 0/1: k-half select
#pragma unroll
    for (int ki = 0; ki < 4; ki++) {
        uint32_t av[4][4];
        uint32_t bv[4][4];
#pragma unroll
        for (int mi = 0; mi < 4; mi++) {
            int row = warpM + mi * 16 + lrow;
            int ch = (ki * 2 + lhi) ^ (row & 7);
            ldsm_x4(av[mi][0], av[mi][1], av[mi][2], av[mi][3],
                    abase + row * 128 + ch * 16);
        }
#pragma unroll
        for (int nj = 0; nj < 4; nj++) {
            int row = warpN + nj * 16 + lrow;
            int ch = (ki * 2 + lhi) ^ (row & 7);
            ldsm_x4(bv[nj][0], bv[nj][1], bv[nj][2], bv[nj][3],
                    bbase + row * 128 + ch * 16);
        }
#pragma unroll
        for (int mi = 0; mi < 4; mi++)
#pragma unroll
            for (int nt = 0; nt < 8; nt++) {
                uint32_t b[2];
                b[0] = bv[nt >> 1][nt & 1];
                b[1] = bv[nt >> 1][2 + (nt & 1)];
                mma_f16(acc[mi][nt], av[mi], b, acc[mi][nt]);
            }
    }
}

__device__ __forceinline__ void xgemm_body(
    const __half* __restrict__ A, const __half* __restrict__ Bt,
    float* __restrict__ C, int N, int K, int bm, int bn)
{
    extern __shared__ __align__(16) char xsm[];
    const uint32_t s0 = (uint32_t)__cvta_generic_to_shared(xsm);
    const uint32_t a0 = s0;
    const uint32_t b0 = s0 + XTILE_B;
    const uint32_t a1 = s0 + XSTAGE_B;
    const uint32_t b1 = s0 + XSTAGE_B + XTILE_B;

    const int tid = threadIdx.x;
    const int lane = tid & 31;
    const int warp = tid >> 5;
    const int q = lane >> 2;
    const int r = lane & 3;
    const int warpM = (warp >> 1) * 64;
    const int warpN = (warp & 1) * 64;

    float acc[4][8][4];
#pragma unroll
    for (int mi = 0; mi < 4; mi++)
#pragma unroll
        for (int nt = 0; nt < 8; nt++)
#pragma unroll
            for (int e = 0; e < 4; e++) acc[mi][nt][e] = 0.f;

    const int T = K / 64;

    xgemm_copy_tile(A, Bt, K, bm, bn, 0, a0, b0, tid);
    cp_commit();

    for (int t = 0; t < T - 1; t++) {
        uint32_t na = (t & 1) ? a0 : a1;
        uint32_t nb = (t & 1) ? b0 : b1;
        uint32_t la = (t & 1) ? a1 : a0;
        uint32_t lb = (t & 1) ? b1 : b0;
        xgemm_copy_tile(A, Bt, K, bm, bn, (t + 1) * 64, na, nb, tid);
        cp_commit();
        cp_wait<1>();
        __syncthreads();
        xgemm_compute_tile(la, lb, acc, warpM, warpN, lane);
        __syncthreads();
    }
    cp_wait<0>();
    __syncthreads();
    {
        uint32_t la = ((T - 1) & 1) ? a1 : a0;
        uint32_t lb = ((T - 1) & 1) ? b1 : b0;
        xgemm_compute_tile(la, lb, acc, warpM, warpN, lane);
    }

#pragma unroll
    for (int mi = 0; mi < 4; mi++) {
        int row0 = bm + warpM + mi * 16 + q;
#pragma unroll
        for (int nt = 0; nt < 8; nt++) {
            int col = bn + warpN + nt * 8 + 2 * r;
            *(float2*)(C + (size_t)row0 * N + col) =
                make_float2(acc[mi][nt][0], acc[mi][nt][1]);
            *(float2*)(C + (size_t)(row0 + 8) * N + col) =
                make_float2(acc[mi][nt][2], acc[mi][nt][3]);
        }
    }
}

__global__ __launch_bounds__(128)
void gemm_qkv_kernel(const __half* __restrict__ xh,
                     const __half* __restrict__ Wqt,
                     const __half* __restrict__ Wkt,
                     const __half* __restrict__ Wvt,
                     float* __restrict__ qraw,
                     float* __restrict__ kraw,
                     float* __restrict__ vraw)
{
    const int bx = blockIdx.x;
    const int bm = blockIdx.y * 128;
    const __half* Bt;
    float* C;
    int N, bn;
    if (bx < 8)       { Bt = Wqt; C = qraw; N = 1024; bn = bx * 128; }
    else if (bx < 10) { Bt = Wkt; C = kraw; N = 256;  bn = (bx - 8) * 128; }
    else              { Bt = Wvt; C = vraw; N = 256;  bn = (bx - 10) * 128; }
    xgemm_body(xh, Bt, C, N, DD, bm, bn);
}

__global__ __launch_bounds__(128)
void gemm_o_kernel(const __half* __restrict__ A, const __half* __restrict__ Bt,
                   float* __restrict__ C)
{
    xgemm_body(A, Bt, C, DD, DD, blockIdx.y * 128, blockIdx.x * 128);
}

// ---------------------------------------------------------------------------
// RoPE kernels -> fp16 outputs. rope_q folds FSC. V transpose -> fp16 [d][s].
// ---------------------------------------------------------------------------
__global__ void rope_q_kernel(const float* __restrict__ qraw,
                              const float* __restrict__ cosT,
                              const float* __restrict__ sinT,
                              __half* __restrict__ qt)
{
    int i = blockIdx.x * blockDim.x + threadIdx.x;
    if (i >= BB * SS * HH * 16) return;
    int d4 = i & 15;
    int h = (i >> 4) & 15;
    int s = (i >> 8) & 2047;
    int b = i >> 19;
    const float4* q4 = (const float4*)qraw;
    float4 v = q4[i];
    float4 rot;
    if (d4 < 8) {
        float4 u = q4[i + 8];
        rot = make_float4(-u.x, -u.y, -u.z, -u.w);
    } else {
        rot = q4[i - 8];
    }
    float4 cs = ((const float4*)cosT)[s * 16 + d4];
    float4 sn = ((const float4*)sinT)[s * 16 + d4];
    float ox = (v.x * cs.x + rot.x * sn.x) * FSC;
    float oy = (v.y * cs.y + rot.y * sn.y) * FSC;
    float oz = (v.z * cs.z + rot.z * sn.z) * FSC;
    float ow = (v.w * cs.w + rot.w * sn.w) * FSC;
    __half2* dst = (__half2*)(qt + ((((size_t)(b * HH + h) * SS) + s) * HDIM + d4 * 4));
    dst[0] = __floats2half2_rn(ox, oy);
    dst[1] = __floats2half2_rn(oz, ow);
}

__global__ void rope_k_kernel(const float* __restrict__ kraw,
                              const float* __restrict__ cosT,
                              const float* __restrict__ sinT,
                              __half* __restrict__ kt)
{
    int i = blockIdx.x * blockDim.x + threadIdx.x;
    if (i >= BB * SS * KVH * 16) return;
    int d4 = i & 15;
    int kv = (i >> 4) & 3;
    int s = (i >> 6) & 2047;
    int b = i >> 17;
    const float4* k4 = (const float4*)kraw;
    float4 v = k4[i];
    float4 rot;
    if (d4 < 8) {
        float4 u = k4[i + 8];
        rot = make_float4(-u.x, -u.y, -u.z, -u.w);
    } else {
        rot = k4[i - 8];
    }
    float4 cs = ((const float4*)cosT)[s * 16 + d4];
    float4 sn = ((const float4*)sinT)[s * 16 + d4];
    float ox = v.x * cs.x + rot.x * sn.x;
    float oy = v.y * cs.y + rot.y * sn.y;
    float oz = v.z * cs.z + rot.z * sn.z;
    float ow = v.w * cs.w + rot.w * sn.w;
    __half2* dst = (__half2*)(kt + ((((size_t)(b * KVH + kv) * SS) + s) * HDIM + d4 * 4));
    dst[0] = __floats2half2_rn(ox, oy);
    dst[1] = __floats2half2_rn(oz, ow);
}

__global__ void vtrans_kernel(const float* __restrict__ vraw,
                              __half* __restrict__ vtT)
{
    __shared__ float tile[32][33];
    const int s0 = blockIdx.x * 32;
    const int d0 = (blockIdx.y & 1) * 32;
    const int bkv = blockIdx.y >> 1;
    const int b = bkv >> 2;
    const int kv = bkv & 3;
    const int tx = threadIdx.x;
#pragma unroll
    for (int ty = threadIdx.y; ty < 32; ty += 8)
        tile[ty][tx] = vraw[(((size_t)(b * SS + s0 + ty)) * KVH + kv) * HDIM + d0 + tx];
    __syncthreads();
#pragma unroll
    for (int ty = threadIdx.y; ty < 32; ty += 8)
        vtT[((size_t)bkv * HDIM + d0 + ty) * SS + s0 + tx] =
            __float2half_rn(tile[tx][ty]);
}

// ---------------------------------------------------------------------------
// fp16 MMA flash attention (unchanged from R9)
// ---------------------------------------------------------------------------
#define HS 72
#define HSW 36

__global__ __launch_bounds__(128)
void flash_mma_kernel(const __half* __restrict__ Qt, const __half* __restrict__ Kt,
                      const __half* __restrict__ VtT, __half* __restrict__ attn)
{
    __shared__ __align__(16) __half Ks[64 * HS];
    __shared__ __align__(16) __half Vs[64 * HS];
    __shared__ __align__(16) __half Ps[64 * HS];

    const int tid = threadIdx.x;
    const int lane = tid & 31;
    const int w = tid >> 5;
    const int q = lane >> 2;
    const int r = lane & 3;

    const int bx = gridDim.x - 1 - blockIdx.x;
    const int bh = blockIdx.y;
    const int b = bh >> 4;
    const int h = bh & 15;
    const int kvh = h >> 2;

    const __half* qbase = Qt + ((size_t)bh * SS + bx * 64) * HDIM;
    const __half* kbase = Kt + (size_t)(b * KVH + kvh) * SS * HDIM;
    const __half* vbase = VtT + (size_t)(b * KVH + kvh) * HDIM * SS;

#pragma unroll
    for (int it = 0; it < 4; it++) {
        int e = tid + it * 128;
        int row = e >> 3;
        int ch = e & 7;
        *(uint4*)(Ps + row * HS + ch * 8) =
            *(const uint4*)(qbase + row * HDIM + ch * 8);
    }
    __syncthreads();

    uint32_t qf[4][4];
    {
        const uint32_t* Pw = (const uint32_t*)Ps;
#pragma unroll
        for (int ki = 0; ki < 4; ki++) {
            const uint32_t* p = Pw + (w * 16 + q) * HSW + ki * 8 + r;
            qf[ki][0] = p[0];
            qf[ki][1] = p[8 * HSW];
            qf[ki][2] = p[4];
            qf[ki][3] = p[8 * HSW + 4];
        }
    }
    __syncthreads();

    float of[8][4];
#pragma unroll
    for (int nt = 0; nt < 8; nt++)
#pragma unroll
        for (int e = 0; e < 4; e++) of[nt][e] = 0.f;
    float m0 = -INFINITY, m1 = -INFINITY, l0 = 0.f, l1 = 0.f;

    for (int jt = 0; jt <= bx; jt++) {
        __syncthreads();
#pragma unroll
        for (int it = 0; it < 4; it++) {
            int e = tid + it * 128;
            int row = e >> 3;
            int ch = e & 7;
            *(uint4*)(Ks + row * HS + ch * 8) =
                *(const uint4*)(kbase + (size_t)(jt * 64 + row) * HDIM + ch * 8);
            *(uint4*)(Vs + row * HS + ch * 8) =
                *(const uint4*)(vbase + (size_t)row * SS + jt * 64 + ch * 8);
        }
        __syncthreads();

        float sf[8][4];
#pragma unroll
        for (int nt = 0; nt < 8; nt++)
#pragma unroll
            for (int e = 0; e < 4; e++) sf[nt][e] = 0.f;
        {
            const uint32_t* Kw = (const uint32_t*)Ks;
#pragma unroll
            for (int ki = 0; ki < 4; ki++) {
#pragma unroll
                for (int nt = 0; nt < 8; nt++) {
                    uint32_t bfr[2];
                    const uint32_t* kp = Kw + (nt * 8 + q) * HSW + ki * 8 + r;
                    bfr[0] = kp[0];
                    bfr[1] = kp[4];
                    mma_f16(sf[nt], qf[ki], bfr, sf[nt]);
                }
            }
        }

        if (jt == bx) {
            const int rowA = w * 16 + q;
            const int rowB = rowA + 8;
#pragma unroll
            for (int nt = 0; nt < 8; nt++) {
                int col = nt * 8 + 2 * r;
                if (col     > rowA) sf[nt][0] = -1e30f;
                if (col + 1 > rowA) sf[nt][1] = -1e30f;
                if (col     > rowB) sf[nt][2] = -1e30f;
                if (col + 1 > rowB) sf[nt][3] = -1e30f;
            }
        }

        float mxA = -1e30f, mxB = -1e30f;
#pragma unroll
        for (int nt = 0; nt < 8; nt++) {
            mxA = fmaxf(mxA, fmaxf(sf[nt][0], sf[nt][1]));
            mxB = fmaxf(mxB, fmaxf(sf[nt][2], sf[nt][3]));
        }
        mxA = fmaxf(mxA, __shfl_xor_sync(0xffffffffu, mxA, 1));
        mxA = fmaxf(mxA, __shfl_xor_sync(0xffffffffu, mxA, 2));
        mxB = fmaxf(mxB, __shfl_xor_sync(0xffffffffu, mxB, 1));
        mxB = fmaxf(mxB, __shfl_xor_sync(0xffffffffu, mxB, 2));

        float mn0 = fmaxf(m0, mxA);
        float mn1 = fmaxf(m1, mxB);
        float sc0 = ex2(m0 - mn0);
        float sc1 = ex2(m1 - mn1);
        m0 = mn0; m1 = mn1;

        float rs0 = 0.f, rs1 = 0.f;
        __half* prow = Ps + (w * 16 + q) * HS;
#pragma unroll
        for (int nt = 0; nt < 8; nt++) {
            float p00 = ex2(sf[nt][0] - m0);
            float p01 = ex2(sf[nt][1] - m0);
            float p10 = ex2(sf[nt][2] - m1);
            float p11 = ex2(sf[nt][3] - m1);
            rs0 += p00 + p01;
            rs1 += p10 + p11;
            *(__half2*)(prow + nt * 8 + 2 * r) = __floats2half2_rn(p00, p01);
            *(__half2*)(prow + 8 * HS + nt * 8 + 2 * r) = __floats2half2_rn(p10, p11);
        }
        rs0 += __shfl_xor_sync(0xffffffffu, rs0, 1);
        rs0 += __shfl_xor_sync(0xffffffffu, rs0, 2);
        rs1 += __shfl_xor_sync(0xffffffffu, rs1, 1);
        rs1 += __shfl_xor_sync(0xffffffffu, rs1, 2);
        l0 = l0 * sc0 + rs0;
        l1 = l1 * sc1 + rs1;
#pragma unroll
        for (int nt = 0; nt < 8; nt++) {
            of[nt][0] *= sc0; of[nt][1] *= sc0;
            of[nt][2] *= sc1; of[nt][3] *= sc1;
        }
        __syncwarp();

        {
            const uint32_t* prw = (const uint32_t*)Ps + (w * 16 + q) * HSW;
            const uint32_t* Vw = (const uint32_t*)Vs;
#pragma unroll
            for (int kk = 0; kk < 4; kk++) {
                uint32_t af[4];
                af[0] = prw[kk * 8 + r];
                af[1] = prw[8 * HSW + kk * 8 + r];
                af[2] = prw[kk * 8 + 4 + r];
                af[3] = prw[8 * HSW + kk * 8 + 4 + r];
#pragma unroll
                for (int nt = 0; nt < 8; nt++) {
                    uint32_t bfr[2];
                    const uint32_t* vp = Vw + (nt * 8 + q) * HSW + kk * 8 + r;
                    bfr[0] = vp[0];
                    bfr[1] = vp[4];
                    mma_f16(of[nt], af, bfr, of[nt]);
                }
            }
        }
    }

    const float il0 = 1.f / l0;
    const float il1 = 1.f / l1;
    __half* ob = attn + ((size_t)b * SS + bx * 64 + w * 16) * (HH * HDIM) + h * HDIM;
#pragma unroll
    for (int nt = 0; nt < 8; nt++) {
        int col = nt * 8 + 2 * r;
        *(__half2*)(ob + (size_t)q * (HH * HDIM) + col) =
            __floats2half2_rn(of[nt][0] * il0, of[nt][1] * il0);
        *(__half2*)(ob + (size_t)(q + 8) * (HH * HDIM) + col) =
            __floats2half2_rn(of[nt][2] * il1, of[nt][3] * il1);
    }
}

// ---------------------------------------------------------------------------
// Launch
// ---------------------------------------------------------------------------
extern "C" void kernel_launch(void* const* d_in, const int* in_sizes, int n_in,
                              void* d_out, int out_size)
{
    (void)in_sizes; (void)n_in; (void)out_size;
    const float* x    = (const float*)d_in[0];
    const float* cosT = (const float*)d_in[1];
    const float* sinT = (const float*)d_in[2];
    const float* Wq   = (const float*)d_in[3];
    const float* Wk   = (const float*)d_in[4];
    const float* Wv   = (const float*)d_in[5];
    const float* Wo   = (const float*)d_in[6];
    float* out = (float*)d_out;

    static bool attr_set = false;
    if (!attr_set) {
        cudaFuncSetAttribute(gemm_qkv_kernel,
                             cudaFuncAttributeMaxDynamicSharedMemorySize, XGSMEM);
        cudaFuncSetAttribute(gemm_o_kernel,
                             cudaFuncAttributeMaxDynamicSharedMemorySize, XGSMEM);
        attr_set = true;
    }

    float *qraw, *kraw, *vraw;
    __half *qt, *kt, *vtT, *attn, *xh, *wqt, *wkt, *wvt, *wot;
    cudaGetSymbolAddress((void**)&qraw, g_qraw);
    cudaGetSymbolAddress((void**)&kraw, g_kraw);
    cudaGetSymbolAddress((void**)&vraw, g_vraw);
    cudaGetSymbolAddress((void**)&qt,   g_qt);
    cudaGetSymbolAddress((void**)&kt,   g_kt);
    cudaGetSymbolAddress((void**)&vtT,  g_vtT);
    cudaGetSymbolAddress((void**)&attn, g_attn);
    cudaGetSymbolAddress((void**)&xh,   g_xh);
    cudaGetSymbolAddress((void**)&wqt,  g_wqt);
    cudaGetSymbolAddress((void**)&wkt,  g_wkt);
    cudaGetSymbolAddress((void**)&wvt,  g_wvt);
    cudaGetSymbolAddress((void**)&wot,  g_wot);

    const int M = BB * SS;   // 4096

    // 0) Prep
    conv_x_kernel<<<(M * DD / 4 + 255) / 256, 256>>>(x, xh, M * DD / 4);
    prep_w_kernel<<<2560, dim3(32, 8)>>>(Wq, Wk, Wv, Wo, wqt, wkt, wvt, wot);

    // 1) Fused Q/K/V projections (fp16 ldmatrix MMA)
    gemm_qkv_kernel<<<dim3(12, M / 128), 128, XGSMEM>>>(xh, wqt, wkt, wvt,
                                                        qraw, kraw, vraw);

    // 2) RoPE (fp16, FSC folded into Q) + V transpose
    rope_q_kernel<<<(BB * SS * HH * 16 + 255) / 256, 256>>>(qraw, cosT, sinT, qt);
    rope_k_kernel<<<(BB * SS * KVH * 16 + 255) / 256, 256>>>(kraw, cosT, sinT, kt);
    vtrans_kernel<<<dim3(SS / 32, 2 * BB * KVH), dim3(32, 8)>>>(vraw, vtT);

    // 3) Causal GQA attention (fp16 MMA flash)
    flash_mma_kernel<<<dim3(SS / 64, BB * HH), 128>>>(qt, kt, vtT, attn);

    // 4) Output projection (fp16 ldmatrix MMA)
    gemm_o_kernel<<<dim3(DD / 128, M / 128), 128, XGSMEM>>>(attn, wot, out);
}

// round 11
// speedup vs baseline: 9.5711x; 1.0223x over previous
#include <cuda_runtime.h>
#include <cuda_fp16.h>
#include <math.h>
#include <stdint.h>

// Problem constants
#define BB 2
#define SS 2048
#define DD 1024
#define HH 16
#define KVH 4
#define HDIM 64
#define NREP (HH / KVH)   // 4

// Scratch (allocation-free: __device__ globals)
__device__ __half g_qt[BB * HH * SS * HDIM];    // roped Q fp16, FSC folded
__device__ __half g_kt[BB * KVH * SS * HDIM];   // roped K fp16
__device__ __half g_vh[BB * SS * KVH * HDIM];   // V fp16 (b,s,kv,d)
__device__ __half g_vtT[BB * KVH * HDIM * SS];  // V^T fp16: [b][kv][d][s]
__device__ __half g_attn[BB * SS * HH * HDIM];  // attention out, fp16
__device__ __half g_xh[BB * SS * DD];           // x fp16 [M][K]
__device__ __half g_wqt[DD * DD];               // Wq^T fp16 [N][K]
__device__ __half g_wkt[256 * DD];
__device__ __half g_wvt[256 * DD];
__device__ __half g_wot[DD * DD];

#define FSC 0.18033688011112042f   // 0.125 * log2(e)

__device__ __forceinline__ float ex2(float x) {
    float y;
    asm("ex2.approx.ftz.f32 %0, %1;" : "=f"(y) : "f"(x));
    return y;
}
__device__ __forceinline__ void mma_f16(float d[4], const uint32_t a[4],
                                        const uint32_t b[2], const float c[4]) {
    asm volatile(
        "mma.sync.aligned.m16n8k16.row.col.f32.f16.f16.f32 "
        "{%0,%1,%2,%3}, {%4,%5,%6,%7}, {%8,%9}, {%10,%11,%12,%13};"
        : "=f"(d[0]), "=f"(d[1]), "=f"(d[2]), "=f"(d[3])
        : "r"(a[0]), "r"(a[1]), "r"(a[2]), "r"(a[3]),
          "r"(b[0]), "r"(b[1]),
          "f"(c[0]), "f"(c[1]), "f"(c[2]), "f"(c[3]));
}
__device__ __forceinline__ void ldsm_x4(uint32_t& r0, uint32_t& r1,
                                        uint32_t& r2, uint32_t& r3, uint32_t addr) {
    asm volatile("ldmatrix.sync.aligned.m8n8.x4.shared.b16 {%0,%1,%2,%3}, [%4];"
                 : "=r"(r0), "=r"(r1), "=r"(r2), "=r"(r3) : "r"(addr));
}
__device__ __forceinline__ void cpa16(uint32_t dst, const void* src) {
    asm volatile("cp.async.ca.shared.global [%0], [%1], 16;"
                 :: "r"(dst), "l"(src));
}
__device__ __forceinline__ void cp_commit() {
    asm volatile("cp.async.commit_group;" ::: "memory");
}
template <int N>
__device__ __forceinline__ void cp_wait() {
    asm volatile("cp.async.wait_group %0;" :: "n"(N) : "memory");
}

// ---------------------------------------------------------------------------
// Prep: x -> fp16; all four W -> fp16 transposed [N][K]
// ---------------------------------------------------------------------------
__global__ void conv_x_kernel(const float* __restrict__ x,
                              __half* __restrict__ xh, int n4)
{
    int i = blockIdx.x * blockDim.x + threadIdx.x;
    if (i >= n4) return;
    float4 v = ((const float4*)x)[i];
    __half2* o = (__half2*)xh;
    o[2 * i]     = __floats2half2_rn(v.x, v.y);
    o[2 * i + 1] = __floats2half2_rn(v.z, v.w);
}

__global__ void prep_w_kernel(const float* __restrict__ Wq,
                              const float* __restrict__ Wk,
                              const float* __restrict__ Wv,
                              const float* __restrict__ Wo,
                              __half* __restrict__ wqt,
                              __half* __restrict__ wkt,
                              __half* __restrict__ wvt,
                              __half* __restrict__ wot)
{
    __shared__ float tile[32][33];
    int bid = blockIdx.x;
    const float* W;
    __half* Wt;
    int N, n_t, k_t;
    if (bid < 1024)      { W = Wq; Wt = wqt; N = 1024; n_t = bid & 31; k_t = bid >> 5; }
    else if (bid < 1280) { W = Wk; Wt = wkt; N = 256;  bid -= 1024; n_t = bid & 7; k_t = bid >> 3; }
    else if (bid < 1536) { W = Wv; Wt = wvt; N = 256;  bid -= 1280; n_t = bid & 7; k_t = bid >> 3; }
    else                 { W = Wo; Wt = wot; N = 1024; bid -= 1536; n_t = bid & 31; k_t = bid >> 5; }
    const int n0 = n_t * 32, k0 = k_t * 32;
    const int tx = threadIdx.x;
#pragma unroll
    for (int ty = threadIdx.y; ty < 32; ty += 8)
        tile[ty][tx] = W[(size_t)(k0 + ty) * N + n0 + tx];
    __syncthreads();
#pragma unroll
    for (int ty = threadIdx.y; ty < 32; ty += 8)
        Wt[(size_t)(n0 + ty) * DD + k0 + tx] = __float2half_rn(tile[tx][ty]);
}

// ---------------------------------------------------------------------------
// fp16 ldmatrix GEMM mainloop (R10 design): acc[4][8][4] for a 128x128 CTA
// tile, 128 threads (4 warps 2x2), warp tile 64x64, BK=64, SW128 swizzle.
// ---------------------------------------------------------------------------
#define XTILE_B 16384
#define XSTAGE_B (XTILE_B * 2)
#define XGSMEM (XSTAGE_B * 2)

__device__ __forceinline__ void xgemm_copy_tile(
    const __half* __restrict__ A, const __half* __restrict__ Bt,
    int K, int bm, int bn, int k0,
    uint32_t abase, uint32_t bbase, int tid)
{
#pragma unroll
    for (int i = 0; i < 8; i++) {
        int e = tid + i * 128;
        int row = e >> 3;
        int ch = e & 7;
        int sch = ch ^ (row & 7);
        cpa16(abase + row * 128 + sch * 16,
              A + (size_t)(bm + row) * K + k0 + ch * 8);
    }
#pragma unroll
    for (int i = 0; i < 8; i++) {
        int e = tid + i * 128;
        int row = e >> 3;
        int ch = e & 7;
        int sch = ch ^ (row & 7);
        cpa16(bbase + row * 128 + sch * 16,
              Bt + (size_t)(bn + row) * K + k0 + ch * 8);
    }
}

__device__ __forceinline__ void xgemm_compute_tile(
    uint32_t abase, uint32_t bbase, float acc[4][8][4],
    int warpM, int warpN, int lane)
{
    const int lrow = lane & 15;
    const int lhi = lane >> 4;
#pragma unroll
    for (int ki = 0; ki < 4; ki++) {
        uint32_t av[4][4];
        uint32_t bv[4][4];
#pragma unroll
        for (int mi = 0; mi < 4; mi++) {
            int row = warpM + mi * 16 + lrow;
            int ch = (ki * 2 + lhi) ^ (row & 7);
            ldsm_x4(av[mi][0], av[mi][1], av[mi][2], av[mi][3],
                    abase + row * 128 + ch * 16);
        }
#pragma unroll
        for (int nj = 0; nj < 4; nj++) {
            int row = warpN + nj * 16 + lrow;
            int ch = (ki * 2 + lhi) ^ (row & 7);
            ldsm_x4(bv[nj][0], bv[nj][1], bv[nj][2], bv[nj][3],
                    bbase + row * 128 + ch * 16);
        }
#pragma unroll
        for (int mi = 0; mi < 4; mi++)
#pragma unroll
            for (int nt = 0; nt < 8; nt++) {
                uint32_t b[2];
                b[0] = bv[nt >> 1][nt & 1];
                b[1] = bv[nt >> 1][2 + (nt & 1)];
                mma_f16(acc[mi][nt], av[mi], b, acc[mi][nt]);
            }
    }
}

__device__ __forceinline__ void xgemm_mainloop(
    const __half* __restrict__ A, const __half* __restrict__ Bt,
    int K, int bm, int bn, float acc[4][8][4],
    int warpM, int warpN, int tid, int lane)
{
    extern __shared__ __align__(16) char xsm[];
    const uint32_t s0 = (uint32_t)__cvta_generic_to_shared(xsm);
    const uint32_t a0 = s0;
    const uint32_t b0 = s0 + XTILE_B;
    const uint32_t a1 = s0 + XSTAGE_B;
    const uint32_t b1 = s0 + XSTAGE_B + XTILE_B;

#pragma unroll
    for (int mi = 0; mi < 4; mi++)
#pragma unroll
        for (int nt = 0; nt < 8; nt++)
#pragma unroll
            for (int e = 0; e < 4; e++) acc[mi][nt][e] = 0.f;

    const int T = K / 64;

    xgemm_copy_tile(A, Bt, K, bm, bn, 0, a0, b0, tid);
    cp_commit();

    for (int t = 0; t < T - 1; t++) {
        uint32_t na = (t & 1) ? a0 : a1;
        uint32_t nb = (t & 1) ? b0 : b1;
        uint32_t la = (t & 1) ? a1 : a0;
        uint32_t lb = (t & 1) ? b1 : b0;
        xgemm_copy_tile(A, Bt, K, bm, bn, (t + 1) * 64, na, nb, tid);
        cp_commit();
        cp_wait<1>();
        __syncthreads();
        xgemm_compute_tile(la, lb, acc, warpM, warpN, lane);
        __syncthreads();
    }
    cp_wait<0>();
    __syncthreads();
    {
        uint32_t la = ((T - 1) & 1) ? a1 : a0;
        uint32_t lb = ((T - 1) & 1) ? b1 : b0;
        xgemm_compute_tile(la, lb, acc, warpM, warpN, lane);
    }
}

// ---------------------------------------------------------------------------
// Fused QKV projection with RoPE epilogue.
// grid.x: 0-7 Q (bn=bx*128), 8-9 K, 10-11 V; grid.y = M/128.
// RoPE pair (d, d+32) = (acc[mi][nt], acc[mi][nt+4]) for nt<4 — same thread.
// Q/K write roped fp16 in [b,h,s,d] / [b,kv,s,d]; V writes fp16 (b,s,kv,d).
// ---------------------------------------------------------------------------
__global__ __launch_bounds__(128)
void gemm_qkv_kernel(const __half* __restrict__ xh,
                     const __half* __restrict__ Wqt,
                     const __half* __restrict__ Wkt,
                     const __half* __restrict__ Wvt,
                     const float* __restrict__ cosT,
                     const float* __restrict__ sinT,
                     __half* __restrict__ qt,
                     __half* __restrict__ kt,
                     __half* __restrict__ vh)
{
    const int tid = threadIdx.x;
    const int lane = tid & 31;
    const int warp = tid >> 5;
    const int q = lane >> 2;
    const int r = lane & 3;
    const int warpM = (warp >> 1) * 64;
    const int warpN = (warp & 1) * 64;

    const int bx = blockIdx.x;
    const int bm = blockIdx.y * 128;

    const __half* Bt;
    int bn;
    if (bx < 8)       { Bt = Wqt; bn = bx * 128; }
    else if (bx < 10) { Bt = Wkt; bn = (bx - 8) * 128; }
    else              { Bt = Wvt; bn = (bx - 10) * 128; }

    float acc[4][8][4];
    xgemm_mainloop(xh, Bt, DD, bm, bn, acc, warpM, warpN, tid, lane);

    if (bx < 10) {
        // RoPE epilogue (Q or K)
        const bool isQ = (bx < 8);
        const int head = (bn + warpN) >> 6;   // h (Q) or kv (K)
        const float fs = isQ ? FSC : 1.0f;
#pragma unroll
        for (int mi = 0; mi < 4; mi++) {
            int rg0 = bm + warpM + mi * 16 + q;
#pragma unroll
            for (int hv = 0; hv < 2; hv++) {
                int rg = rg0 + hv * 8;
                int bb = rg >> 11;
                int s = rg & 2047;
                const float* crow = cosT + s * HDIM;
                const float* srow = sinT + s * HDIM;
                __half* orow;
                if (isQ)
                    orow = qt + (((size_t)(bb * HH + head) * SS + s) << 6);
                else
                    orow = kt + (((size_t)(bb * KVH + head) * SS + s) << 6);
#pragma unroll
                for (int nt = 0; nt < 4; nt++) {
                    int d = nt * 8 + 2 * r;
                    float2 cl = *(const float2*)(crow + d);
                    float2 sl = *(const float2*)(srow + d);
                    float2 chg = *(const float2*)(crow + d + 32);
                    float2 shg = *(const float2*)(srow + d + 32);
                    float v0 = acc[mi][nt][2 * hv];
                    float v1 = acc[mi][nt][2 * hv + 1];
                    float w0 = acc[mi][nt + 4][2 * hv];
                    float w1 = acc[mi][nt + 4][2 * hv + 1];
                    float lo0 = (v0 * cl.x - w0 * sl.x) * fs;
                    float lo1 = (v1 * cl.y - w1 * sl.y) * fs;
                    float hi0 = (w0 * chg.x + v0 * shg.x) * fs;
                    float hi1 = (w1 * chg.y + v1 * shg.y) * fs;
                    *(__half2*)(orow + d) = __floats2half2_rn(lo0, lo1);
                    *(__half2*)(orow + d + 32) = __floats2half2_rn(hi0, hi1);
                }
            }
        }
    } else {
        // V epilogue: fp16 to (m, col) layout, col = kv*64+d
#pragma unroll
        for (int mi = 0; mi < 4; mi++) {
            int rg0 = bm + warpM + mi * 16 + q;
#pragma unroll
            for (int nt = 0; nt < 8; nt++) {
                int col = bn + warpN + nt * 8 + 2 * r;
                *(__half2*)(vh + (size_t)rg0 * 256 + col) =
                    __floats2half2_rn(acc[mi][nt][0], acc[mi][nt][1]);
                *(__half2*)(vh + (size_t)(rg0 + 8) * 256 + col) =
                    __floats2half2_rn(acc[mi][nt][2], acc[mi][nt][3]);
            }
        }
    }
}

// Output projection (generic fp32 epilogue)
__global__ __launch_bounds__(128)
void gemm_o_kernel(const __half* __restrict__ A, const __half* __restrict__ Bt,
                   float* __restrict__ C)
{
    const int tid = threadIdx.x;
    const int lane = tid & 31;
    const int warp = tid >> 5;
    const int q = lane >> 2;
    const int r = lane & 3;
    const int warpM = (warp >> 1) * 64;
    const int warpN = (warp & 1) * 64;
    const int bm = blockIdx.y * 128;
    const int bn = blockIdx.x * 128;

    float acc[4][8][4];
    xgemm_mainloop(A, Bt, DD, bm, bn, acc, warpM, warpN, tid, lane);

#pragma unroll
    for (int mi = 0; mi < 4; mi++) {
        int row0 = bm + warpM + mi * 16 + q;
#pragma unroll
        for (int nt = 0; nt < 8; nt++) {
            int col = bn + warpN + nt * 8 + 2 * r;
            *(float2*)(C + (size_t)row0 * DD + col) =
                make_float2(acc[mi][nt][0], acc[mi][nt][1]);
            *(float2*)(C + (size_t)(row0 + 8) * DD + col) =
                make_float2(acc[mi][nt][2], acc[mi][nt][3]);
        }
    }
}

// ---------------------------------------------------------------------------
// V transpose: vh (b,s,kv,d) fp16 -> vtT (b,kv,d,s) fp16
// ---------------------------------------------------------------------------
__global__ void vtrans_kernel(const __half* __restrict__ vh,
                              __half* __restrict__ vtT)
{
    __shared__ __half tile[32][33];
    const int s0 = blockIdx.x * 32;
    const int d0 = (blockIdx.y & 1) * 32;
    const int bkv = blockIdx.y >> 1;
    const int b = bkv >> 2;
    const int kv = bkv & 3;
    const int tx = threadIdx.x;
#pragma unroll
    for (int ty = threadIdx.y; ty < 32; ty += 8)
        tile[ty][tx] = vh[(((size_t)(b * SS + s0 + ty)) * KVH + kv) * HDIM + d0 + tx];
    __syncthreads();
#pragma unroll
    for (int ty = threadIdx.y; ty < 32; ty += 8)
        vtT[((size_t)bkv * HDIM + d0 + ty) * SS + s0 + tx] = tile[tx][ty];
}

// ---------------------------------------------------------------------------
// fp16 MMA flash attention (unchanged from R9/R10)
// ---------------------------------------------------------------------------
#define HS 72
#define HSW 36

__global__ __launch_bounds__(128)
void flash_mma_kernel(const __half* __restrict__ Qt, const __half* __restrict__ Kt,
                      const __half* __restrict__ VtT, __half* __restrict__ attn)
{
    __shared__ __align__(16) __half Ks[64 * HS];
    __shared__ __align__(16) __half Vs[64 * HS];
    __shared__ __align__(16) __half Ps[64 * HS];

    const int tid = threadIdx.x;
    const int lane = tid & 31;
    const int w = tid >> 5;
    const int q = lane >> 2;
    const int r = lane & 3;

    const int bx = gridDim.x - 1 - blockIdx.x;
    const int bh = blockIdx.y;
    const int b = bh >> 4;
    const int h = bh & 15;
    const int kvh = h >> 2;

    const __half* qbase = Qt + ((size_t)bh * SS + bx * 64) * HDIM;
    const __half* kbase = Kt + (size_t)(b * KVH + kvh) * SS * HDIM;
    const __half* vbase = VtT + (size_t)(b * KVH + kvh) * HDIM * SS;

#pragma unroll
    for (int it = 0; it < 4; it++) {
        int e = tid + it * 128;
        int row = e >> 3;
        int ch = e & 7;
        *(uint4*)(Ps + row * HS + ch * 8) =
            *(const uint4*)(qbase + row * HDIM + ch * 8);
    }
    __syncthreads();

    uint32_t qf[4][4];
    {
        const uint32_t* Pw = (const uint32_t*)Ps;
#pragma unroll
        for (int ki = 0; ki < 4; ki++) {
            const uint32_t* p = Pw + (w * 16 + q) * HSW + ki * 8 + r;
            qf[ki][0] = p[0];
            qf[ki][1] = p[8 * HSW];
            qf[ki][2] = p[4];
            qf[ki][3] = p[8 * HSW + 4];
        }
    }
    __syncthreads();

    float of[8][4];
#pragma unroll
    for (int nt = 0; nt < 8; nt++)
#pragma unroll
        for (int e = 0; e < 4; e++) of[nt][e] = 0.f;
    float m0 = -INFINITY, m1 = -INFINITY, l0 = 0.f, l1 = 0.f;

    for (int jt = 0; jt <= bx; jt++) {
        __syncthreads();
#pragma unroll
        for (int it = 0; it < 4; it++) {
            int e = tid + it * 128;
            int row = e >> 3;
            int ch = e & 7;
            *(uint4*)(Ks + row * HS + ch * 8) =
                *(const uint4*)(kbase + (size_t)(jt * 64 + row) * HDIM + ch * 8);
            *(uint4*)(Vs + row * HS + ch * 8) =
                *(const uint4*)(vbase + (size_t)row * SS + jt * 64 + ch * 8);
        }
        __syncthreads();

        float sf[8][4];
#pragma unroll
        for (int nt = 0; nt < 8; nt++)
#pragma unroll
            for (int e = 0; e < 4; e++) sf[nt][e] = 0.f;
        {
            const uint32_t* Kw = (const uint32_t*)Ks;
#pragma unroll
            for (int ki = 0; ki < 4; ki++) {
#pragma unroll
                for (int nt = 0; nt < 8; nt++) {
                    uint32_t bfr[2];
                    const uint32_t* kp = Kw + (nt * 8 + q) * HSW + ki * 8 + r;
                    bfr[0] = kp[0];
                    bfr[1] = kp[4];
                    mma_f16(sf[nt], qf[ki], bfr, sf[nt]);
                }
            }
        }

        if (jt == bx) {
            const int rowA = w * 16 + q;
            const int rowB = rowA + 8;
#pragma unroll
            for (int nt = 0; nt < 8; nt++) {
                int col = nt * 8 + 2 * r;
                if (col     > rowA) sf[nt][0] = -1e30f;
                if (col + 1 > rowA) sf[nt][1] = -1e30f;
                if (col     > rowB) sf[nt][2] = -1e30f;
                if (col + 1 > rowB) sf[nt][3] = -1e30f;
            }
        }

        float mxA = -1e30f, mxB = -1e30f;
#pragma unroll
        for (int nt = 0; nt < 8; nt++) {
            mxA = fmaxf(mxA, fmaxf(sf[nt][0], sf[nt][1]));
            mxB = fmaxf(mxB, fmaxf(sf[nt][2], sf[nt][3]));
        }
        mxA = fmaxf(mxA, __shfl_xor_sync(0xffffffffu, mxA, 1));
        mxA = fmaxf(mxA, __shfl_xor_sync(0xffffffffu, mxA, 2));
        mxB = fmaxf(mxB, __shfl_xor_sync(0xffffffffu, mxB, 1));
        mxB = fmaxf(mxB, __shfl_xor_sync(0xffffffffu, mxB, 2));

        float mn0 = fmaxf(m0, mxA);
        float mn1 = fmaxf(m1, mxB);
        float sc0 = ex2(m0 - mn0);
        float sc1 = ex2(m1 - mn1);
        m0 = mn0; m1 = mn1;

        float rs0 = 0.f, rs1 = 0.f;
        __half* prow = Ps + (w * 16 + q) * HS;
#pragma unroll
        for (int nt = 0; nt < 8; nt++) {
            float p00 = ex2(sf[nt][0] - m0);
            float p01 = ex2(sf[nt][1] - m0);
            float p10 = ex2(sf[nt][2] - m1);
            float p11 = ex2(sf[nt][3] - m1);
            rs0 += p00 + p01;
            rs1 += p10 + p11;
            *(__half2*)(prow + nt * 8 + 2 * r) = __floats2half2_rn(p00, p01);
            *(__half2*)(prow + 8 * HS + nt * 8 + 2 * r) = __floats2half2_rn(p10, p11);
        }
        rs0 += __shfl_xor_sync(0xffffffffu, rs0, 1);
        rs0 += __shfl_xor_sync(0xffffffffu, rs0, 2);
        rs1 += __shfl_xor_sync(0xffffffffu, rs1, 1);
        rs1 += __shfl_xor_sync(0xffffffffu, rs1, 2);
        l0 = l0 * sc0 + rs0;
        l1 = l1 * sc1 + rs1;
#pragma unroll
        for (int nt = 0; nt < 8; nt++) {
            of[nt][0] *= sc0; of[nt][1] *= sc0;
            of[nt][2] *= sc1; of[nt][3] *= sc1;
        }
        __syncwarp();

        {
            const uint32_t* prw = (const uint32_t*)Ps + (w * 16 + q) * HSW;
            const uint32_t* Vw = (const uint32_t*)Vs;
#pragma unroll
            for (int kk = 0; kk < 4; kk++) {
                uint32_t af[4];
                af[0] = prw[kk * 8 + r];
                af[1] = prw[8 * HSW + kk * 8 + r];
                af[2] = prw[kk * 8 + 4 + r];
                af[3] = prw[8 * HSW + kk * 8 + 4 + r];
#pragma unroll
                for (int nt = 0; nt < 8; nt++) {
                    uint32_t bfr[2];
                    const uint32_t* vp = Vw + (nt * 8 + q) * HSW + kk * 8 + r;
                    bfr[0] = vp[0];
                    bfr[1] = vp[4];
                    mma_f16(of[nt], af, bfr, of[nt]);
                }
            }
        }
    }

    const float il0 = 1.f / l0;
    const float il1 = 1.f / l1;
    __half* ob = attn + ((size_t)b * SS + bx * 64 + w * 16) * (HH * HDIM) + h * HDIM;
#pragma unroll
    for (int nt = 0; nt < 8; nt++) {
        int col = nt * 8 + 2 * r;
        *(__half2*)(ob + (size_t)q * (HH * HDIM) + col) =
            __floats2half2_rn(of[nt][0] * il0, of[nt][1] * il0);
        *(__half2*)(ob + (size_t)(q + 8) * (HH * HDIM) + col) =
            __floats2half2_rn(of[nt][2] * il1, of[nt][3] * il1);
    }
}

// ---------------------------------------------------------------------------
// Launch
// ---------------------------------------------------------------------------
extern "C" void kernel_launch(void* const* d_in, const int* in_sizes, int n_in,
                              void* d_out, int out_size)
{
    (void)in_sizes; (void)n_in; (void)out_size;
    const float* x    = (const float*)d_in[0];
    const float* cosT = (const float*)d_in[1];
    const float* sinT = (const float*)d_in[2];
    const float* Wq   = (const float*)d_in[3];
    const float* Wk   = (const float*)d_in[4];
    const float* Wv   = (const float*)d_in[5];
    const float* Wo   = (const float*)d_in[6];
    float* out = (float*)d_out;

    static bool attr_set = false;
    if (!attr_set) {
        cudaFuncSetAttribute(gemm_qkv_kernel,
                             cudaFuncAttributeMaxDynamicSharedMemorySize, XGSMEM);
        cudaFuncSetAttribute(gemm_o_kernel,
                             cudaFuncAttributeMaxDynamicSharedMemorySize, XGSMEM);
        attr_set = true;
    }

    __half *qt, *kt, *vh, *vtT, *attn, *xh, *wqt, *wkt, *wvt, *wot;
    cudaGetSymbolAddress((void**)&qt,   g_qt);
    cudaGetSymbolAddress((void**)&kt,   g_kt);
    cudaGetSymbolAddress((void**)&vh,   g_vh);
    cudaGetSymbolAddress((void**)&vtT,  g_vtT);
    cudaGetSymbolAddress((void**)&attn, g_attn);
    cudaGetSymbolAddress((void**)&xh,   g_xh);
    cudaGetSymbolAddress((void**)&wqt,  g_wqt);
    cudaGetSymbolAddress((void**)&wkt,  g_wkt);
    cudaGetSymbolAddress((void**)&wvt,  g_wvt);
    cudaGetSymbolAddress((void**)&wot,  g_wot);

    const int M = BB * SS;   // 4096

    // 0) Prep
    conv_x_kernel<<<(M * DD / 4 + 255) / 256, 256>>>(x, xh, M * DD / 4);
    prep_w_kernel<<<2560, dim3(32, 8)>>>(Wq, Wk, Wv, Wo, wqt, wkt, wvt, wot);

    // 1) Fused QKV projections + RoPE epilogue (fp16 ldmatrix MMA)
    gemm_qkv_kernel<<<dim3(12, M / 128), 128, XGSMEM>>>(
        xh, wqt, wkt, wvt, cosT, sinT, qt, kt, vh);

    // 2) V transpose (fp16 -> fp16 [d][s])
    vtrans_kernel<<<dim3(SS / 32, 2 * BB * KVH), dim3(32, 8)>>>(vh, vtT);

    // 3) Causal GQA attention (fp16 MMA flash)
    flash_mma_kernel<<<dim3(SS / 64, BB * HH), 128>>>(qt, kt, vtT, attn);

    // 4) Output projection (fp16 ldmatrix MMA)
    gemm_o_kernel<<<dim3(DD / 128, M / 128), 128, XGSMEM>>>(attn, wot, out);
}